// round 1
// baseline (speedup 1.0000x reference)
#include <cuda_runtime.h>
#include <math.h>

#define NH    12
#define NTOK  2048
#define BATCH 4
#define CDIM  768
#define HD    64
#define KEEP  1024
#define ROWS  (BATCH*NTOK)   /* 8192 */
#define C3    (3*CDIM)       /* 2304 */

// ---- scratch (static device globals; no runtime allocation) ----
__device__ float g_qkv[(size_t)ROWS * C3];       // [8192][2304]: [.|q:h*64+d | k:768+... | v:1536+...]
__device__ float g_scores[BATCH * NH * NTOK];    // [bh][n] = sum_d q^2
__device__ int   g_keep[BATCH * NH * KEEP];      // selected token indices (set; order irrelevant)
__device__ float g_attnout[(size_t)ROWS * CDIM]; // [8192][768] attention output, [b,n,h*64+d]

// ============================================================================
// Classic SGEMM: C[M,N] = A[M,K] @ B[K,N], 128x128 block, 8x8/thread, BK=8.
// Optional epilogue: +bias[col], clip to [-10,10]. All dims multiples of tile.
// ============================================================================
__global__ __launch_bounds__(256) void sgemm128(
    const float* __restrict__ A, const float* __restrict__ B,
    float* __restrict__ C, int M, int N, int K,
    const float* __restrict__ bias, int do_clip)
{
    constexpr int BK = 8;
    __shared__ float As[BK][128];
    __shared__ float Bs[BK][128];
    const int tid  = threadIdx.x;
    const int tcol = tid & 15, trow = tid >> 4;
    const int brow0 = blockIdx.y * 128, bcol0 = blockIdx.x * 128;
    const int aRow = tid >> 1, aCol = (tid & 1) * 4;
    const int bRow = tid >> 5, bCol = (tid & 31) * 4;
    const float* Ap = A + (size_t)(brow0 + aRow) * K + aCol;
    const float* Bp = B + (size_t)bRow * N + bcol0 + bCol;

    float acc[8][8];
#pragma unroll
    for (int i = 0; i < 8; i++)
#pragma unroll
        for (int j = 0; j < 8; j++) acc[i][j] = 0.f;

    for (int k0 = 0; k0 < K; k0 += BK) {
        float4 av = *(const float4*)Ap; Ap += BK;
        float4 bv = *(const float4*)Bp; Bp += (size_t)BK * N;
        As[aCol + 0][aRow] = av.x; As[aCol + 1][aRow] = av.y;
        As[aCol + 2][aRow] = av.z; As[aCol + 3][aRow] = av.w;
        *(float4*)&Bs[bRow][bCol] = bv;
        __syncthreads();
#pragma unroll
        for (int kk = 0; kk < BK; kk++) {
            float ar[8], br[8];
            *(float4*)&ar[0] = *(const float4*)&As[kk][trow * 8];
            *(float4*)&ar[4] = *(const float4*)&As[kk][trow * 8 + 4];
            *(float4*)&br[0] = *(const float4*)&Bs[kk][tcol * 8];
            *(float4*)&br[4] = *(const float4*)&Bs[kk][tcol * 8 + 4];
#pragma unroll
            for (int i = 0; i < 8; i++)
#pragma unroll
                for (int j = 0; j < 8; j++) acc[i][j] = fmaf(ar[i], br[j], acc[i][j]);
        }
        __syncthreads();
    }

#pragma unroll
    for (int i = 0; i < 8; i++) {
        int r = brow0 + trow * 8 + i;
        float* Crow = C + (size_t)r * N + bcol0 + tcol * 8;
#pragma unroll
        for (int jj = 0; jj < 2; jj++) {
            float4 v;
            float* a4 = &acc[i][jj * 4];
            v.x = a4[0]; v.y = a4[1]; v.z = a4[2]; v.w = a4[3];
            if (bias) {
                const float* bp = bias + bcol0 + tcol * 8 + jj * 4;
                v.x += bp[0]; v.y += bp[1]; v.z += bp[2]; v.w += bp[3];
            }
            if (do_clip) {
                v.x = fminf(fmaxf(v.x, -10.f), 10.f);
                v.y = fminf(fmaxf(v.y, -10.f), 10.f);
                v.z = fminf(fmaxf(v.z, -10.f), 10.f);
                v.w = fminf(fmaxf(v.w, -10.f), 10.f);
            }
            *(float4*)(Crow + jj * 4) = v;
        }
    }
}

// ============================================================================
// scores[bh][n] = sum_d q[b,h,n,d]^2   (monotone with L2 norm -> same top-k)
// ============================================================================
__global__ void scores_kernel(const float* __restrict__ qkv, float* __restrict__ scores)
{
    int idx = blockIdx.x * blockDim.x + threadIdx.x;
    if (idx >= BATCH * NH * NTOK) return;
    int n  = idx & (NTOK - 1);
    int bh = idx >> 11;
    int h = bh % NH, b = bh / NH;
    const float4* q = (const float4*)(qkv + (size_t)(b * NTOK + n) * C3 + h * HD);
    float s = 0.f;
#pragma unroll
    for (int i = 0; i < 16; i++) {
        float4 v = q[i];
        s += v.x * v.x + v.y * v.y + v.z * v.z + v.w * v.w;
    }
    scores[idx] = s;
}

// ============================================================================
// Per-(b,h) top-KEEP selection via bitonic sort of packed u64 keys.
// key = (score_bits << 32) | (NTOK-1-n): scores >= 0 so raw float bits are
// order-preserving; ties break to lower index (matches top_k) — and the
// attention is permutation-invariant over the keep set anyway.
// ============================================================================
__global__ __launch_bounds__(1024) void topk_kernel(
    const float* __restrict__ scores, int* __restrict__ keep)
{
    __shared__ unsigned long long keys[NTOK];
    const int bh = blockIdx.x, t = threadIdx.x;
    for (int i = t; i < NTOK; i += 1024) {
        unsigned sb = __float_as_uint(scores[bh * NTOK + i]);
        keys[i] = ((unsigned long long)sb << 32) | (unsigned)(NTOK - 1 - i);
    }
    for (int k = 2; k <= NTOK; k <<= 1) {
        for (int j = k >> 1; j > 0; j >>= 1) {
            __syncthreads();
            for (int i = t; i < NTOK; i += 1024) {
                int ixj = i ^ j;
                if (ixj > i) {
                    unsigned long long a = keys[i], c = keys[ixj];
                    bool asc = ((i & k) == 0);
                    if ((a > c) == asc) { keys[i] = c; keys[ixj] = a; }
                }
            }
        }
    }
    __syncthreads();
    if (t < KEEP) {
        // ascending sort -> top KEEP live in [NTOK-KEEP, NTOK)
        keep[bh * KEEP + t] = (NTOK - 1) - (int)(keys[NTOK - KEEP + t] & 0xffffffffu);
    }
}

// ============================================================================
// Gathered flash attention. Block = (query tile of 64) x (b,h). 256 threads as
// 16x16, each owns 4x4 of the 64x64 S tile and 4x4 of the 64x64 O tile.
// Online softmax with the reference clip(s*scale, -50, 50) applied pre-softmax.
// smem: QsT[d][i] (16KB) + KPs (K^T then P^T reuse, 16KB) + Vs[j][d] (16KB).
// ============================================================================
__global__ __launch_bounds__(256) void attn_kernel(
    const float* __restrict__ qkv, const int* __restrict__ keep,
    float* __restrict__ out)
{
    __shared__ float QsT[HD][64];  // [d][i]
    __shared__ float KPs[64][64];  // phase A: K^T [d][j];  phase B: P^T [j][i]
    __shared__ float Vs[64][64];   // [j][d]
    const int tid = threadIdx.x;
    const int tx = tid & 15, ty = tid >> 4;
    const int bh = blockIdx.y, b = bh / NH, h = bh % NH;
    const int qbase = blockIdx.x * 64;

    // Load Q tile transposed (conflict-free scalar stores: lane -> distinct j)
    {
        int j = tid & 63, qq = tid >> 6;
        const float* qrow = qkv + (size_t)(b * NTOK + qbase + j) * C3 + h * HD;
#pragma unroll
        for (int s = 0; s < 4; s++) {
            int d0 = qq * 16 + s * 4;
            float4 v = *(const float4*)(qrow + d0);
            QsT[d0 + 0][j] = v.x; QsT[d0 + 1][j] = v.y;
            QsT[d0 + 2][j] = v.z; QsT[d0 + 3][j] = v.w;
        }
    }

    float m[4], l[4], acc[4][4];
#pragma unroll
    for (int i = 0; i < 4; i++) {
        m[i] = -INFINITY; l[i] = 0.f;
#pragma unroll
        for (int d2 = 0; d2 < 4; d2++) acc[i][d2] = 0.f;
    }

    for (int kc = 0; kc < KEEP / 64; kc++) {
        // gather K (transposed) and V (row-major) for this 64-key chunk
        {
            int j = tid & 63, qq = tid >> 6;
            int kidx = keep[bh * KEEP + kc * 64 + j];
            const float* krow = qkv + (size_t)(b * NTOK + kidx) * C3 + CDIM + h * HD;
#pragma unroll
            for (int s = 0; s < 4; s++) {
                int d0 = qq * 16 + s * 4;
                float4 v = *(const float4*)(krow + d0);
                KPs[d0 + 0][j] = v.x; KPs[d0 + 1][j] = v.y;
                KPs[d0 + 2][j] = v.z; KPs[d0 + 3][j] = v.w;
            }
            int j2 = tid >> 2, qq2 = tid & 3;
            int kidx2 = keep[bh * KEEP + kc * 64 + j2];
            const float* vrow = qkv + (size_t)(b * NTOK + kidx2) * C3 + 2 * CDIM + h * HD;
#pragma unroll
            for (int s = 0; s < 4; s++) {
                int d0 = qq2 * 16 + s * 4;
                *(float4*)&Vs[j2][d0] = *(const float4*)(vrow + d0);
            }
        }
        __syncthreads();

        // S = Q @ K^T  (4x4 per thread)
        float S[4][4];
#pragma unroll
        for (int i = 0; i < 4; i++)
#pragma unroll
            for (int j = 0; j < 4; j++) S[i][j] = 0.f;
#pragma unroll 8
        for (int d = 0; d < HD; d++) {
            float4 a  = *(const float4*)&QsT[d][ty * 4];
            float4 bb = *(const float4*)&KPs[d][tx * 4];
            float ar[4] = {a.x, a.y, a.z, a.w};
            float br[4] = {bb.x, bb.y, bb.z, bb.w};
#pragma unroll
            for (int i = 0; i < 4; i++)
#pragma unroll
                for (int j = 0; j < 4; j++) S[i][j] = fmaf(ar[i], br[j], S[i][j]);
        }

        // scale + clip + online softmax (row group = 16 lanes, shfl reduce)
        float p[4][4];
#pragma unroll
        for (int i = 0; i < 4; i++) {
            float rmax = -INFINITY;
#pragma unroll
            for (int j = 0; j < 4; j++) {
                float s = S[i][j] * 0.125f;
                s = fminf(fmaxf(s, -50.f), 50.f);
                S[i][j] = s;
                rmax = fmaxf(rmax, s);
            }
#pragma unroll
            for (int o = 8; o >= 1; o >>= 1)
                rmax = fmaxf(rmax, __shfl_xor_sync(0xffffffffu, rmax, o));
            float mn = fmaxf(m[i], rmax);
            float corr = expf(m[i] - mn);
            float rs = 0.f;
#pragma unroll
            for (int j = 0; j < 4; j++) { float e = expf(S[i][j] - mn); p[i][j] = e; rs += e; }
#pragma unroll
            for (int o = 8; o >= 1; o >>= 1)
                rs += __shfl_xor_sync(0xffffffffu, rs, o);
            l[i] = l[i] * corr + rs;
#pragma unroll
            for (int d2 = 0; d2 < 4; d2++) acc[i][d2] *= corr;
            m[i] = mn;
        }
        __syncthreads();   // all S reads of KPs done -> safe to overwrite with P^T
#pragma unroll
        for (int i = 0; i < 4; i++)
#pragma unroll
            for (int j = 0; j < 4; j++) KPs[tx * 4 + j][ty * 4 + i] = p[i][j];
        __syncthreads();

        // O += P @ V  via  O[i][d] += sum_j P^T[j][i] * Vs[j][d]
#pragma unroll 8
        for (int j2 = 0; j2 < 64; j2++) {
            float4 pa = *(const float4*)&KPs[j2][ty * 4];
            float4 vb = *(const float4*)&Vs[j2][tx * 4];
            float par[4] = {pa.x, pa.y, pa.z, pa.w};
            float vbr[4] = {vb.x, vb.y, vb.z, vb.w};
#pragma unroll
            for (int i = 0; i < 4; i++)
#pragma unroll
                for (int d2 = 0; d2 < 4; d2++) acc[i][d2] = fmaf(par[i], vbr[d2], acc[i][d2]);
        }
        __syncthreads();   // PV reads done before next chunk's gather overwrites
    }

    // finalize + write in [b, n, h*64+d] layout
#pragma unroll
    for (int i = 0; i < 4; i++) {
        float inv = 1.f / l[i];
        int n = qbase + ty * 4 + i;
        float* orow = out + (size_t)(b * NTOK + n) * CDIM + h * HD + tx * 4;
        float4 v;
        v.x = acc[i][0] * inv; v.y = acc[i][1] * inv;
        v.z = acc[i][2] * inv; v.w = acc[i][3] * inv;
        *(float4*)orow = v;
    }
}

// ============================================================================
// launch
// ============================================================================
extern "C" void kernel_launch(void* const* d_in, const int* in_sizes, int n_in,
                              void* d_out, int out_size)
{
    (void)in_sizes; (void)n_in; (void)out_size;
    const float* x      = (const float*)d_in[0];
    const float* w_qkv  = (const float*)d_in[1];
    const float* w_proj = (const float*)d_in[2];
    const float* b_proj = (const float*)d_in[3];
    float* out = (float*)d_out;

    float* qkv_p; float* sc_p; int* keep_p; float* ao_p;
    cudaGetSymbolAddress((void**)&qkv_p,  g_qkv);
    cudaGetSymbolAddress((void**)&sc_p,   g_scores);
    cudaGetSymbolAddress((void**)&keep_p, g_keep);
    cudaGetSymbolAddress((void**)&ao_p,   g_attnout);

    // 1) qkv = x @ w_qkv : [8192,768] @ [768,2304]
    sgemm128<<<dim3(C3 / 128, ROWS / 128), 256>>>(x, w_qkv, qkv_p, ROWS, C3, CDIM, nullptr, 0);
    // 2) query-norm^2 scores
    scores_kernel<<<(BATCH * NH * NTOK + 255) / 256, 256>>>(qkv_p, sc_p);
    // 3) per-(b,h) top-1024 selection
    topk_kernel<<<BATCH * NH, 1024>>>(sc_p, keep_p);
    // 4) gathered flash attention
    attn_kernel<<<dim3(NTOK / 64, BATCH * NH), 256>>>(qkv_p, keep_p, ao_p);
    // 5) out = clip(attn_out @ w_proj + b_proj, -10, 10)
    sgemm128<<<dim3(CDIM / 128, ROWS / 128), 256>>>(ao_p, w_proj, out, ROWS, CDIM, CDIM, b_proj, 1);
}

// round 2
// speedup vs baseline: 1.1686x; 1.1686x over previous
#include <cuda_runtime.h>
#include <math.h>

#define NH    12
#define NTOK  2048
#define BATCH 4
#define CDIM  768
#define HD    64
#define KEEP  1024
#define ROWS  (BATCH*NTOK)   /* 8192 */
#define C3    (3*CDIM)       /* 2304 */
#define NBH   (BATCH*NH)     /* 48 */
#define BQ    128            /* query tile */
#define BKC   128            /* key chunk  */

// ---- scratch (static device globals; no runtime allocation) ----
__device__ float g_qkv[(size_t)ROWS * C3];        // [8192][2304]
__device__ float g_scores[NBH * NTOK];
__device__ int   g_keep[NBH * KEEP];
__device__ float g_kselT[(size_t)NBH * HD * KEEP]; // [bh][d][j]  (K^T, gathered)
__device__ float g_vsel [(size_t)NBH * KEEP * HD]; // [bh][j][d]  (V,   gathered)
__device__ float g_attnout[(size_t)ROWS * CDIM];   // [b,n,h*64+d]

// ============================================================================
// Classic SGEMM: C[M,N] = A[M,K] @ B[K,N], 128x128 block, 8x8/thread, BK=8.
// Optional epilogue: +bias[col], clip to [-10,10].
// ============================================================================
__global__ __launch_bounds__(256) void sgemm128(
    const float* __restrict__ A, const float* __restrict__ B,
    float* __restrict__ C, int M, int N, int K,
    const float* __restrict__ bias, int do_clip)
{
    constexpr int BK = 8;
    __shared__ float As[BK][128];
    __shared__ float Bs[BK][128];
    const int tid  = threadIdx.x;
    const int tcol = tid & 15, trow = tid >> 4;
    const int brow0 = blockIdx.y * 128, bcol0 = blockIdx.x * 128;
    const int aRow = tid >> 1, aCol = (tid & 1) * 4;
    const int bRow = tid >> 5, bCol = (tid & 31) * 4;
    const float* Ap = A + (size_t)(brow0 + aRow) * K + aCol;
    const float* Bp = B + (size_t)bRow * N + bcol0 + bCol;

    float acc[8][8];
#pragma unroll
    for (int i = 0; i < 8; i++)
#pragma unroll
        for (int j = 0; j < 8; j++) acc[i][j] = 0.f;

    for (int k0 = 0; k0 < K; k0 += BK) {
        float4 av = *(const float4*)Ap; Ap += BK;
        float4 bv = *(const float4*)Bp; Bp += (size_t)BK * N;
        As[aCol + 0][aRow] = av.x; As[aCol + 1][aRow] = av.y;
        As[aCol + 2][aRow] = av.z; As[aCol + 3][aRow] = av.w;
        *(float4*)&Bs[bRow][bCol] = bv;
        __syncthreads();
#pragma unroll
        for (int kk = 0; kk < BK; kk++) {
            float ar[8], br[8];
            *(float4*)&ar[0] = *(const float4*)&As[kk][trow * 8];
            *(float4*)&ar[4] = *(const float4*)&As[kk][trow * 8 + 4];
            *(float4*)&br[0] = *(const float4*)&Bs[kk][tcol * 8];
            *(float4*)&br[4] = *(const float4*)&Bs[kk][tcol * 8 + 4];
#pragma unroll
            for (int i = 0; i < 8; i++)
#pragma unroll
                for (int j = 0; j < 8; j++) acc[i][j] = fmaf(ar[i], br[j], acc[i][j]);
        }
        __syncthreads();
    }

#pragma unroll
    for (int i = 0; i < 8; i++) {
        int r = brow0 + trow * 8 + i;
        float* Crow = C + (size_t)r * N + bcol0 + tcol * 8;
#pragma unroll
        for (int jj = 0; jj < 2; jj++) {
            float4 v;
            float* a4 = &acc[i][jj * 4];
            v.x = a4[0]; v.y = a4[1]; v.z = a4[2]; v.w = a4[3];
            if (bias) {
                const float* bp = bias + bcol0 + tcol * 8 + jj * 4;
                v.x += bp[0]; v.y += bp[1]; v.z += bp[2]; v.w += bp[3];
            }
            if (do_clip) {
                v.x = fminf(fmaxf(v.x, -10.f), 10.f);
                v.y = fminf(fmaxf(v.y, -10.f), 10.f);
                v.z = fminf(fmaxf(v.z, -10.f), 10.f);
                v.w = fminf(fmaxf(v.w, -10.f), 10.f);
            }
            *(float4*)(Crow + jj * 4) = v;
        }
    }
}

// ============================================================================
// scores[bh][n] = sum_d q^2   (monotone with L2 norm -> same top-k set)
// ============================================================================
__global__ void scores_kernel(const float* __restrict__ qkv, float* __restrict__ scores)
{
    int idx = blockIdx.x * blockDim.x + threadIdx.x;
    if (idx >= NBH * NTOK) return;
    int n  = idx & (NTOK - 1);
    int bh = idx >> 11;
    int h = bh % NH, b = bh / NH;
    const float4* q = (const float4*)(qkv + (size_t)(b * NTOK + n) * C3 + h * HD);
    float s = 0.f;
#pragma unroll
    for (int i = 0; i < 16; i++) {
        float4 v = q[i];
        s += v.x * v.x + v.y * v.y + v.z * v.z + v.w * v.w;
    }
    scores[idx] = s;
}

// ============================================================================
// Per-(b,h) top-KEEP via bitonic sort of packed u64 keys (set semantics).
// ============================================================================
__global__ __launch_bounds__(1024) void topk_kernel(
    const float* __restrict__ scores, int* __restrict__ keep)
{
    __shared__ unsigned long long keys[NTOK];
    const int bh = blockIdx.x, t = threadIdx.x;
    for (int i = t; i < NTOK; i += 1024) {
        unsigned sb = __float_as_uint(scores[bh * NTOK + i]);
        keys[i] = ((unsigned long long)sb << 32) | (unsigned)(NTOK - 1 - i);
    }
    for (int k = 2; k <= NTOK; k <<= 1) {
        for (int j = k >> 1; j > 0; j >>= 1) {
            __syncthreads();
            for (int i = t; i < NTOK; i += 1024) {
                int ixj = i ^ j;
                if (ixj > i) {
                    unsigned long long a = keys[i], c = keys[ixj];
                    bool asc = ((i & k) == 0);
                    if ((a > c) == asc) { keys[i] = c; keys[ixj] = a; }
                }
            }
        }
    }
    __syncthreads();
    if (t < KEEP) {
        keep[bh * KEEP + t] = (NTOK - 1) - (int)(keys[NTOK - KEEP + t] & 0xffffffffu);
    }
}

// ============================================================================
// Gather selected K (transposed -> [bh][d][j]) and V (row-major -> [bh][j][d])
// into contiguous scratch. grid = (KEEP/64, NBH), 256 threads.
// ============================================================================
__global__ __launch_bounds__(256) void gather_kernel(
    const float* __restrict__ qkv, const int* __restrict__ keep,
    float* __restrict__ kselT, float* __restrict__ vsel)
{
    __shared__ float tile[HD][65];
    const int bh = blockIdx.y, jc = blockIdx.x;
    const int b = bh / NH, h = bh % NH;
    const int t = threadIdx.x;

#pragma unroll
    for (int r = 0; r < 4; r++) {
        int idx = t + r * 256;                // 0..1023
        int row = idx >> 4, f4 = (idx & 15) * 4;
        int kidx = keep[bh * KEEP + jc * 64 + row];
        const float* base = qkv + (size_t)(b * NTOK + kidx) * C3 + h * HD;
        float4 kv = *(const float4*)(base + CDIM + f4);
        tile[f4 + 0][row] = kv.x; tile[f4 + 1][row] = kv.y;
        tile[f4 + 2][row] = kv.z; tile[f4 + 3][row] = kv.w;
        float4 vv = *(const float4*)(base + 2 * CDIM + f4);
        *(float4*)(vsel + (size_t)bh * KEEP * HD + (size_t)(jc * 64 + row) * HD + f4) = vv;
    }
    __syncthreads();
#pragma unroll
    for (int r = 0; r < 4; r++) {
        int idx = t + r * 256;
        int d = idx >> 4, jf = (idx & 15) * 4;
        float4 v;
        v.x = tile[d][jf + 0]; v.y = tile[d][jf + 1];
        v.z = tile[d][jf + 2]; v.w = tile[d][jf + 3];
        *(float4*)(kselT + (size_t)bh * HD * KEEP + (size_t)d * KEEP + jc * 64 + jf) = v;
    }
}

// ============================================================================
// Gathered flash attention v2: 128 (q) x 128 (keys) tile, 256 threads.
// S phase: 16x16 thread grid, 8x8 per thread (1 B LDS / FMA).
// PV phase: O tile 128x64, 8x4 per thread, P via smem.
// smem (dynamic 160KB): QsT[64][128] | KT[64][128] | Vs[128][64] | Ps[128][128]
// ============================================================================
__global__ __launch_bounds__(256, 1) void attn_kernel(
    const float* __restrict__ qkv, const float* __restrict__ kselT,
    const float* __restrict__ vsel, float* __restrict__ out)
{
    extern __shared__ float sm[];
    float* QsT = sm;                         // [64][128] (d-major)
    float* KT  = sm + HD * BQ;               // [64][128] (d-major)
    float* Vs  = sm + 2 * HD * BQ;           // [128][64]
    float* Ps  = sm + 2 * HD * BQ + BKC * HD;// [128][128]

    const int tid = threadIdx.x;
    const int tx = tid & 15, ty = tid >> 4;
    const int ty8 = ty * 8, tx8 = tx * 8, tx4 = tx * 4;
    const int bh = blockIdx.y, b = bh / NH, h = bh % NH;
    const int qbase = blockIdx.x * BQ;

    // load Q tile transposed (scalar stores, conflict-free)
    {
        int j = tid & 127, half = tid >> 7;
        const float* qrow = qkv + (size_t)(b * NTOK + qbase + j) * C3 + h * HD;
#pragma unroll
        for (int s = 0; s < 8; s++) {
            int d0 = half * 32 + s * 4;
            float4 v = *(const float4*)(qrow + d0);
            QsT[(d0 + 0) * BQ + j] = v.x; QsT[(d0 + 1) * BQ + j] = v.y;
            QsT[(d0 + 2) * BQ + j] = v.z; QsT[(d0 + 3) * BQ + j] = v.w;
        }
    }

    float m[8], l[8], acc[8][4];
#pragma unroll
    for (int i = 0; i < 8; i++) {
        m[i] = -INFINITY; l[i] = 0.f;
#pragma unroll
        for (int d2 = 0; d2 < 4; d2++) acc[i][d2] = 0.f;
    }

    const float* kbase = kselT + (size_t)bh * HD * KEEP;
    const float* vbase = vsel  + (size_t)bh * KEEP * HD;

    for (int kc = 0; kc < KEEP / BKC; kc++) {
        // stream K^T chunk [64][128] and V chunk [128][64] (coalesced float4)
#pragma unroll
        for (int r = 0; r < 8; r++) {
            int idx = tid + r * 256;                  // 0..2047
            int d = idx >> 5, f = (idx & 31) * 4;
            *(float4*)(KT + d * BKC + f) =
                *(const float4*)(kbase + (size_t)d * KEEP + kc * BKC + f);
        }
#pragma unroll
        for (int r = 0; r < 8; r++) {
            int idx = tid + r * 256;
            int j = idx >> 4, f = (idx & 15) * 4;
            *(float4*)(Vs + j * HD + f) =
                *(const float4*)(vbase + (size_t)(kc * BKC + j) * HD + f);
        }
        __syncthreads();

        // S = Q @ Ksel^T  (8x8 per thread)
        float S[8][8];
#pragma unroll
        for (int i = 0; i < 8; i++)
#pragma unroll
            for (int j = 0; j < 8; j++) S[i][j] = 0.f;
#pragma unroll 4
        for (int d = 0; d < HD; d++) {
            float4 a0 = *(const float4*)(QsT + d * BQ + ty8);
            float4 a1 = *(const float4*)(QsT + d * BQ + ty8 + 4);
            float4 b0 = *(const float4*)(KT + d * BKC + tx8);
            float4 b1 = *(const float4*)(KT + d * BKC + tx8 + 4);
            float ar[8] = {a0.x, a0.y, a0.z, a0.w, a1.x, a1.y, a1.z, a1.w};
            float br[8] = {b0.x, b0.y, b0.z, b0.w, b1.x, b1.y, b1.z, b1.w};
#pragma unroll
            for (int i = 0; i < 8; i++)
#pragma unroll
                for (int j = 0; j < 8; j++) S[i][j] = fmaf(ar[i], br[j], S[i][j]);
        }

        // scale + clip + online softmax (row spans 16 tx lanes; xor-shfl allreduce)
#pragma unroll
        for (int i = 0; i < 8; i++) {
            float rmax = -INFINITY;
#pragma unroll
            for (int j = 0; j < 8; j++) {
                float s = S[i][j] * 0.125f;
                s = fminf(fmaxf(s, -50.f), 50.f);
                S[i][j] = s;
                rmax = fmaxf(rmax, s);
            }
#pragma unroll
            for (int o = 8; o >= 1; o >>= 1)
                rmax = fmaxf(rmax, __shfl_xor_sync(0xffffffffu, rmax, o));
            float mn = fmaxf(m[i], rmax);
            float corr = __expf(m[i] - mn);
            float rs = 0.f;
#pragma unroll
            for (int j = 0; j < 8; j++) {
                float e = __expf(S[i][j] - mn);
                S[i][j] = e; rs += e;
            }
#pragma unroll
            for (int o = 8; o >= 1; o >>= 1)
                rs += __shfl_xor_sync(0xffffffffu, rs, o);
            l[i] = l[i] * corr + rs;
#pragma unroll
            for (int d2 = 0; d2 < 4; d2++) acc[i][d2] *= corr;
            m[i] = mn;
        }

        // P -> smem (row-major)
#pragma unroll
        for (int i = 0; i < 8; i++) {
            float4 v0, v1;
            v0.x = S[i][0]; v0.y = S[i][1]; v0.z = S[i][2]; v0.w = S[i][3];
            v1.x = S[i][4]; v1.y = S[i][5]; v1.z = S[i][6]; v1.w = S[i][7];
            *(float4*)(Ps + (ty8 + i) * BKC + tx8)     = v0;
            *(float4*)(Ps + (ty8 + i) * BKC + tx8 + 4) = v1;
        }
        __syncthreads();

        // O += P @ V   (8 rows x 4 d-cols per thread)
        const float* PsRow = Ps + ty8 * BKC;
#pragma unroll 2
        for (int j2 = 0; j2 < BKC; j2++) {
            float4 vb = *(const float4*)(Vs + j2 * HD + tx4);
            float p0 = PsRow[0 * BKC + j2];
            float p1 = PsRow[1 * BKC + j2];
            float p2 = PsRow[2 * BKC + j2];
            float p3 = PsRow[3 * BKC + j2];
            float p4 = PsRow[4 * BKC + j2];
            float p5 = PsRow[5 * BKC + j2];
            float p6 = PsRow[6 * BKC + j2];
            float p7 = PsRow[7 * BKC + j2];
            float vr[4] = {vb.x, vb.y, vb.z, vb.w};
            float pr[8] = {p0, p1, p2, p3, p4, p5, p6, p7};
#pragma unroll
            for (int i = 0; i < 8; i++)
#pragma unroll
                for (int d2 = 0; d2 < 4; d2++)
                    acc[i][d2] = fmaf(pr[i], vr[d2], acc[i][d2]);
        }
        __syncthreads();   // protect Vs/KT before next chunk's loads
    }

    // finalize + write [b, n, h*64+d]
#pragma unroll
    for (int i = 0; i < 8; i++) {
        float inv = 1.f / l[i];
        int n = qbase + ty8 + i;
        float4 v;
        v.x = acc[i][0] * inv; v.y = acc[i][1] * inv;
        v.z = acc[i][2] * inv; v.w = acc[i][3] * inv;
        *(float4*)(out + (size_t)(b * NTOK + n) * CDIM + h * HD + tx4) = v;
    }
}

// ============================================================================
// launch
// ============================================================================
extern "C" void kernel_launch(void* const* d_in, const int* in_sizes, int n_in,
                              void* d_out, int out_size)
{
    (void)in_sizes; (void)n_in; (void)out_size;
    const float* x      = (const float*)d_in[0];
    const float* w_qkv  = (const float*)d_in[1];
    const float* w_proj = (const float*)d_in[2];
    const float* b_proj = (const float*)d_in[3];
    float* out = (float*)d_out;

    float* qkv_p; float* sc_p; int* keep_p; float* kT_p; float* vs_p; float* ao_p;
    cudaGetSymbolAddress((void**)&qkv_p,  g_qkv);
    cudaGetSymbolAddress((void**)&sc_p,   g_scores);
    cudaGetSymbolAddress((void**)&keep_p, g_keep);
    cudaGetSymbolAddress((void**)&kT_p,   g_kselT);
    cudaGetSymbolAddress((void**)&vs_p,   g_vsel);
    cudaGetSymbolAddress((void**)&ao_p,   g_attnout);

    const int attn_smem = (2 * HD * BQ + BKC * HD + BKC * BKC) * (int)sizeof(float); // 160KB
    cudaFuncSetAttribute(attn_kernel, cudaFuncAttributeMaxDynamicSharedMemorySize, attn_smem);

    // 1) qkv = x @ w_qkv : [8192,768] @ [768,2304]
    sgemm128<<<dim3(C3 / 128, ROWS / 128), 256>>>(x, w_qkv, qkv_p, ROWS, C3, CDIM, nullptr, 0);
    // 2) query-norm^2 scores
    scores_kernel<<<(NBH * NTOK + 255) / 256, 256>>>(qkv_p, sc_p);
    // 3) per-(b,h) top-1024 selection
    topk_kernel<<<NBH, 1024>>>(sc_p, keep_p);
    // 4) gather K^T / V into contiguous scratch
    gather_kernel<<<dim3(KEEP / 64, NBH), 256>>>(qkv_p, keep_p, kT_p, vs_p);
    // 5) gathered flash attention (128x128 tiles)
    attn_kernel<<<dim3(NTOK / BQ, NBH), 256, attn_smem>>>(qkv_p, kT_p, vs_p, ao_p);
    // 6) out = clip(attn_out @ w_proj + b_proj, -10, 10)
    sgemm128<<<dim3(CDIM / 128, ROWS / 128), 256>>>(ao_p, w_proj, out, ROWS, CDIM, CDIM, b_proj, 1);
}

// round 4
// speedup vs baseline: 1.2767x; 1.0925x over previous
#include <cuda_runtime.h>
#include <math.h>
#include <cstdint>

#define NH    12
#define NTOK  2048
#define BATCH 4
#define CDIM  768
#define HD    64
#define KEEP  1024
#define ROWS  (BATCH*NTOK)   /* 8192 */
#define C3    (3*CDIM)       /* 2304 */
#define NBH   (BATCH*NH)     /* 48 */
#define BQ    128
#define BKC   128
#define SST   36             /* smem row stride (floats) for GEMM tiles */

// ---- scratch (static device globals; no runtime allocation) ----
__device__ float g_qkv[(size_t)ROWS * C3];
__device__ float g_scores[NBH * NTOK];
__device__ int   g_keep[NBH * KEEP];
__device__ float g_kselT[(size_t)NBH * HD * KEEP];
__device__ float g_vsel [(size_t)NBH * KEEP * HD];
__device__ float g_attnout[(size_t)ROWS * CDIM];
__device__ float g_xhi[(size_t)ROWS * CDIM];
__device__ float g_xlo[(size_t)ROWS * CDIM];
__device__ float g_wqT_hi[(size_t)C3 * CDIM];   // w_qkv^T [2304][768]
__device__ float g_wqT_lo[(size_t)C3 * CDIM];
__device__ float g_wpT_hi[(size_t)CDIM * CDIM]; // w_proj^T [768][768]
__device__ float g_wpT_lo[(size_t)CDIM * CDIM];

__device__ __forceinline__ float tf32_rna(float a) {
    float r; asm("cvt.rna.tf32.f32 %0, %1;" : "=f"(r) : "f"(a)); return r;
}

__device__ __forceinline__ void mma_tf32(float& c0, float& c1, float& c2, float& c3,
                                         uint32_t a0, uint32_t a1, uint32_t a2, uint32_t a3,
                                         uint32_t b0, uint32_t b1) {
    asm volatile("mma.sync.aligned.m16n8k8.row.col.f32.tf32.tf32.f32 "
        "{%0,%1,%2,%3}, {%4,%5,%6,%7}, {%8,%9}, {%0,%1,%2,%3};"
        : "+f"(c0), "+f"(c1), "+f"(c2), "+f"(c3)
        : "r"(a0), "r"(a1), "r"(a2), "r"(a3), "r"(b0), "r"(b1));
}

// ============================================================================
// mma.sync tf32 GEMM: C[M,N] = A[M,K] @ BT[N,K]^T.
// CTA tile 128x128, 8 warps (2 m x 4 n), warp tile 64x32, K-chunk 32.
// TERMS=3: D = Ah*Bh + Ah*Bl + Al*Bh (fp32-class); TERMS=2: Ah*Bh + Ah*Bl.
// smem rows padded to stride 36 -> conflict-free scalar fragment loads.
// ============================================================================
template<int TERMS>
__global__ __launch_bounds__(256) void mma_gemm(
    const float* __restrict__ Ahi, const float* __restrict__ Alo,
    const float* __restrict__ Bhi, const float* __restrict__ Blo,
    float* __restrict__ C, int K, int ldc,
    const float* __restrict__ bias, int do_clip)
{
    extern __shared__ float sm[];
    float* Ah = sm;                    // [128][SST]
    float* Bh = sm + 128 * SST;
    float* Bl = sm + 2 * 128 * SST;    // TERMS>=2
    float* Al = sm + 3 * 128 * SST;    // TERMS==3

    const int tid = threadIdx.x, lane = tid & 31, wid = tid >> 5;
    const int g = lane >> 2, ct = lane & 3;
    const int wm = wid & 1, wn = wid >> 1;            // 2 x 4 warp grid
    const int m0 = blockIdx.y * 128, n0 = blockIdx.x * 128;
    const int lrow = tid >> 1, lk0 = (tid & 1) * 16;  // loader: 2 threads/row

    float acc[4][4][4];
#pragma unroll
    for (int mt = 0; mt < 4; mt++)
#pragma unroll
        for (int nt = 0; nt < 4; nt++)
#pragma unroll
            for (int i = 0; i < 4; i++) acc[mt][nt][i] = 0.f;

    const float* Agh = Ahi + (size_t)(m0 + lrow) * K + lk0;
    const float* Bgh = Bhi + (size_t)(n0 + lrow) * K + lk0;
    const float* Bgl = (TERMS >= 2) ? (Blo + (size_t)(n0 + lrow) * K + lk0) : nullptr;
    const float* Agl = (TERMS == 3) ? (Alo + (size_t)(m0 + lrow) * K + lk0) : nullptr;

    const int NC = K / 32;
    for (int c = 0; c < NC; c++) {
        const int k0 = c * 32;
        // ---- load K-chunk into smem (coalesced LDG.128 + conflict-free STS.128)
#pragma unroll
        for (int i = 0; i < 4; i++) {
            int kk = lk0 + i * 4;
            *(float4*)&Ah[lrow * SST + kk] = *(const float4*)(Agh + k0 + i * 4);
            *(float4*)&Bh[lrow * SST + kk] = *(const float4*)(Bgh + k0 + i * 4);
            if (TERMS >= 2)
                *(float4*)&Bl[lrow * SST + kk] = *(const float4*)(Bgl + k0 + i * 4);
            if (TERMS == 3)
                *(float4*)&Al[lrow * SST + kk] = *(const float4*)(Agl + k0 + i * 4);
        }
        __syncthreads();

        // ---- 4 k-steps of m16n8k8
#pragma unroll
        for (int ks = 0; ks < 4; ks++) {
            const int kc = ks * 8 + ct;
            uint32_t afh[4][4], afl[4][4], bfh[4][2], bfl[4][2];
#pragma unroll
            for (int mt = 0; mt < 4; mt++) {
                int r = (wm * 64 + mt * 16 + g) * SST;
                afh[mt][0] = __float_as_uint(Ah[r + kc]);
                afh[mt][1] = __float_as_uint(Ah[r + 8 * SST + kc]);
                afh[mt][2] = __float_as_uint(Ah[r + kc + 4]);
                afh[mt][3] = __float_as_uint(Ah[r + 8 * SST + kc + 4]);
                if (TERMS == 3) {
                    afl[mt][0] = __float_as_uint(Al[r + kc]);
                    afl[mt][1] = __float_as_uint(Al[r + 8 * SST + kc]);
                    afl[mt][2] = __float_as_uint(Al[r + kc + 4]);
                    afl[mt][3] = __float_as_uint(Al[r + 8 * SST + kc + 4]);
                }
            }
#pragma unroll
            for (int nt = 0; nt < 4; nt++) {
                int r = (wn * 32 + nt * 8 + g) * SST;
                bfh[nt][0] = __float_as_uint(Bh[r + kc]);
                bfh[nt][1] = __float_as_uint(Bh[r + kc + 4]);
                if (TERMS >= 2) {
                    bfl[nt][0] = __float_as_uint(Bl[r + kc]);
                    bfl[nt][1] = __float_as_uint(Bl[r + kc + 4]);
                }
            }
#pragma unroll
            for (int mt = 0; mt < 4; mt++)
#pragma unroll
                for (int nt = 0; nt < 4; nt++) {
                    float* a = acc[mt][nt];
                    mma_tf32(a[0], a[1], a[2], a[3],
                             afh[mt][0], afh[mt][1], afh[mt][2], afh[mt][3],
                             bfh[nt][0], bfh[nt][1]);
                    if (TERMS >= 2)
                        mma_tf32(a[0], a[1], a[2], a[3],
                                 afh[mt][0], afh[mt][1], afh[mt][2], afh[mt][3],
                                 bfl[nt][0], bfl[nt][1]);
                    if (TERMS == 3)
                        mma_tf32(a[0], a[1], a[2], a[3],
                                 afl[mt][0], afl[mt][1], afl[mt][2], afl[mt][3],
                                 bfh[nt][0], bfh[nt][1]);
                }
        }
        __syncthreads();
    }

    // ---- epilogue: bias + clip + float2 stores
#pragma unroll
    for (int mt = 0; mt < 4; mt++) {
#pragma unroll
        for (int nt = 0; nt < 4; nt++) {
            int row = m0 + wm * 64 + mt * 16 + g;
            int col = n0 + wn * 32 + nt * 8 + ct * 2;
            float v0 = acc[mt][nt][0], v1 = acc[mt][nt][1];
            float v2 = acc[mt][nt][2], v3 = acc[mt][nt][3];
            if (bias) {
                float b0 = bias[col], b1 = bias[col + 1];
                v0 += b0; v1 += b1; v2 += b0; v3 += b1;
            }
            if (do_clip) {
                v0 = fminf(fmaxf(v0, -10.f), 10.f);
                v1 = fminf(fmaxf(v1, -10.f), 10.f);
                v2 = fminf(fmaxf(v2, -10.f), 10.f);
                v3 = fminf(fmaxf(v3, -10.f), 10.f);
            }
            float2 lo2; lo2.x = v0; lo2.y = v1;
            float2 hi2; hi2.x = v2; hi2.y = v3;
            *(float2*)(C + (size_t)row * ldc + col) = lo2;
            *(float2*)(C + (size_t)(row + 8) * ldc + col) = hi2;
        }
    }
}

// ============================================================================
// x -> (hi, lo) tf32 split, elementwise float4
// ============================================================================
__global__ void xsplit_kernel(const float* __restrict__ x, float* __restrict__ hi,
                              float* __restrict__ lo, int n4)
{
    int i = blockIdx.x * blockDim.x + threadIdx.x;
    if (i >= n4) return;
    float4 v = ((const float4*)x)[i];
    float4 h, l;
    h.x = tf32_rna(v.x); l.x = tf32_rna(v.x - h.x);
    h.y = tf32_rna(v.y); l.y = tf32_rna(v.y - h.y);
    h.z = tf32_rna(v.z); l.z = tf32_rna(v.z - h.z);
    h.w = tf32_rna(v.w); l.w = tf32_rna(v.w - h.w);
    ((float4*)hi)[i] = h;
    ((float4*)lo)[i] = l;
}

// ============================================================================
// weight transpose + tf32 split: in[K,N] -> ohi[N,K] (+olo[N,K])
// ============================================================================
__global__ void wsplit_kernel(const float* __restrict__ in, float* __restrict__ ohi,
                              float* __restrict__ olo, int K, int N)
{
    __shared__ float t[32][33];
    const int n0 = blockIdx.x * 32, k0 = blockIdx.y * 32;
    const int tx = threadIdx.x, ty = threadIdx.y;
#pragma unroll
    for (int i = 0; i < 4; i++)
        t[ty + i * 8][tx] = in[(size_t)(k0 + ty + i * 8) * N + n0 + tx];
    __syncthreads();
#pragma unroll
    for (int i = 0; i < 4; i++) {
        float v = t[tx][ty + i * 8];
        float h = tf32_rna(v);
        ohi[(size_t)(n0 + ty + i * 8) * K + k0 + tx] = h;
        olo[(size_t)(n0 + ty + i * 8) * K + k0 + tx] = tf32_rna(v - h);
    }
}

// ============================================================================
// scores[bh][n] = sum_d q^2
// ============================================================================
__global__ void scores_kernel(const float* __restrict__ qkv, float* __restrict__ scores)
{
    int idx = blockIdx.x * blockDim.x + threadIdx.x;
    if (idx >= NBH * NTOK) return;
    int n  = idx & (NTOK - 1);
    int bh = idx >> 11;
    int h = bh % NH, b = bh / NH;
    const float4* q = (const float4*)(qkv + (size_t)(b * NTOK + n) * C3 + h * HD);
    float s = 0.f;
#pragma unroll
    for (int i = 0; i < 16; i++) {
        float4 v = q[i];
        s += v.x * v.x + v.y * v.y + v.z * v.z + v.w * v.w;
    }
    scores[idx] = s;
}

// ============================================================================
// Per-(b,h) top-KEEP via bitonic sort of packed u64 keys (set semantics).
// ============================================================================
__global__ __launch_bounds__(1024) void topk_kernel(
    const float* __restrict__ scores, int* __restrict__ keep)
{
    __shared__ unsigned long long keys[NTOK];
    const int bh = blockIdx.x, t = threadIdx.x;
    for (int i = t; i < NTOK; i += 1024) {
        unsigned sb = __float_as_uint(scores[bh * NTOK + i]);
        keys[i] = ((unsigned long long)sb << 32) | (unsigned)(NTOK - 1 - i);
    }
    for (int k = 2; k <= NTOK; k <<= 1) {
        for (int j = k >> 1; j > 0; j >>= 1) {
            __syncthreads();
            for (int i = t; i < NTOK; i += 1024) {
                int ixj = i ^ j;
                if (ixj > i) {
                    unsigned long long a = keys[i], c = keys[ixj];
                    bool asc = ((i & k) == 0);
                    if ((a > c) == asc) { keys[i] = c; keys[ixj] = a; }
                }
            }
        }
    }
    __syncthreads();
    if (t < KEEP) {
        keep[bh * KEEP + t] = (NTOK - 1) - (int)(keys[NTOK - KEEP + t] & 0xffffffffu);
    }
}

// ============================================================================
// Gather selected K^T [bh][d][j] and V [bh][j][d] into contiguous scratch.
// ============================================================================
__global__ __launch_bounds__(256) void gather_kernel(
    const float* __restrict__ qkv, const int* __restrict__ keep,
    float* __restrict__ kselT, float* __restrict__ vsel)
{
    __shared__ float tile[HD][65];
    const int bh = blockIdx.y, jc = blockIdx.x;
    const int b = bh / NH, h = bh % NH;
    const int t = threadIdx.x;

#pragma unroll
    for (int r = 0; r < 4; r++) {
        int idx = t + r * 256;
        int row = idx >> 4, f4 = (idx & 15) * 4;
        int kidx = keep[bh * KEEP + jc * 64 + row];
        const float* base = qkv + (size_t)(b * NTOK + kidx) * C3 + h * HD;
        float4 kv = *(const float4*)(base + CDIM + f4);
        tile[f4 + 0][row] = kv.x; tile[f4 + 1][row] = kv.y;
        tile[f4 + 2][row] = kv.z; tile[f4 + 3][row] = kv.w;
        float4 vv = *(const float4*)(base + 2 * CDIM + f4);
        *(float4*)(vsel + (size_t)bh * KEEP * HD + (size_t)(jc * 64 + row) * HD + f4) = vv;
    }
    __syncthreads();
#pragma unroll
    for (int r = 0; r < 4; r++) {
        int idx = t + r * 256;
        int d = idx >> 4, jf = (idx & 15) * 4;
        float4 v;
        v.x = tile[d][jf + 0]; v.y = tile[d][jf + 1];
        v.z = tile[d][jf + 2]; v.w = tile[d][jf + 3];
        *(float4*)(kselT + (size_t)bh * HD * KEEP + (size_t)d * KEEP + jc * 64 + jf) = v;
    }
}

// ============================================================================
// Gathered flash attention: 128x128 tile, 256 threads, 8x8 S / 8x4 O per thread.
// Output tf32-RNA rounded (exact inputs for the tf32 proj GEMM).
// ============================================================================
__global__ __launch_bounds__(256, 1) void attn_kernel(
    const float* __restrict__ qkv, const float* __restrict__ kselT,
    const float* __restrict__ vsel, float* __restrict__ out)
{
    extern __shared__ float smf[];
    float* QsT = smf;
    float* KT  = smf + HD * BQ;
    float* Vs  = smf + 2 * HD * BQ;
    float* Ps  = smf + 2 * HD * BQ + BKC * HD;

    const int tid = threadIdx.x;
    const int tx = tid & 15, ty = tid >> 4;
    const int ty8 = ty * 8, tx8 = tx * 8, tx4 = tx * 4;
    const int bh = blockIdx.y, b = bh / NH, h = bh % NH;
    const int qbase = blockIdx.x * BQ;

    {
        int j = tid & 127, half = tid >> 7;
        const float* qrow = qkv + (size_t)(b * NTOK + qbase + j) * C3 + h * HD;
#pragma unroll
        for (int s = 0; s < 8; s++) {
            int d0 = half * 32 + s * 4;
            float4 v = *(const float4*)(qrow + d0);
            QsT[(d0 + 0) * BQ + j] = v.x; QsT[(d0 + 1) * BQ + j] = v.y;
            QsT[(d0 + 2) * BQ + j] = v.z; QsT[(d0 + 3) * BQ + j] = v.w;
        }
    }

    float m[8], l[8], acc[8][4];
#pragma unroll
    for (int i = 0; i < 8; i++) {
        m[i] = -INFINITY; l[i] = 0.f;
#pragma unroll
        for (int d2 = 0; d2 < 4; d2++) acc[i][d2] = 0.f;
    }

    const float* kbase = kselT + (size_t)bh * HD * KEEP;
    const float* vbase = vsel  + (size_t)bh * KEEP * HD;

    for (int kc = 0; kc < KEEP / BKC; kc++) {
#pragma unroll
        for (int r = 0; r < 8; r++) {
            int idx = tid + r * 256;
            int d = idx >> 5, f = (idx & 31) * 4;
            *(float4*)(KT + d * BKC + f) =
                *(const float4*)(kbase + (size_t)d * KEEP + kc * BKC + f);
        }
#pragma unroll
        for (int r = 0; r < 8; r++) {
            int idx = tid + r * 256;
            int j = idx >> 4, f = (idx & 15) * 4;
            *(float4*)(Vs + j * HD + f) =
                *(const float4*)(vbase + (size_t)(kc * BKC + j) * HD + f);
        }
        __syncthreads();

        float S[8][8];
#pragma unroll
        for (int i = 0; i < 8; i++)
#pragma unroll
            for (int j = 0; j < 8; j++) S[i][j] = 0.f;
#pragma unroll 4
        for (int d = 0; d < HD; d++) {
            float4 a0 = *(const float4*)(QsT + d * BQ + ty8);
            float4 a1 = *(const float4*)(QsT + d * BQ + ty8 + 4);
            float4 b0 = *(const float4*)(KT + d * BKC + tx8);
            float4 b1 = *(const float4*)(KT + d * BKC + tx8 + 4);
            float ar[8] = {a0.x, a0.y, a0.z, a0.w, a1.x, a1.y, a1.z, a1.w};
            float br[8] = {b0.x, b0.y, b0.z, b0.w, b1.x, b1.y, b1.z, b1.w};
#pragma unroll
            for (int i = 0; i < 8; i++)
#pragma unroll
                for (int j = 0; j < 8; j++) S[i][j] = fmaf(ar[i], br[j], S[i][j]);
        }

#pragma unroll
        for (int i = 0; i < 8; i++) {
            float rmax = -INFINITY;
#pragma unroll
            for (int j = 0; j < 8; j++) {
                float s = S[i][j] * 0.125f;
                s = fminf(fmaxf(s, -50.f), 50.f);
                S[i][j] = s;
                rmax = fmaxf(rmax, s);
            }
#pragma unroll
            for (int o = 8; o >= 1; o >>= 1)
                rmax = fmaxf(rmax, __shfl_xor_sync(0xffffffffu, rmax, o));
            float mn = fmaxf(m[i], rmax);
            float corr = __expf(m[i] - mn);
            float rs = 0.f;
#pragma unroll
            for (int j = 0; j < 8; j++) {
                float e = __expf(S[i][j] - mn);
                S[i][j] = e; rs += e;
            }
#pragma unroll
            for (int o = 8; o >= 1; o >>= 1)
                rs += __shfl_xor_sync(0xffffffffu, rs, o);
            l[i] = l[i] * corr + rs;
#pragma unroll
            for (int d2 = 0; d2 < 4; d2++) acc[i][d2] *= corr;
            m[i] = mn;
        }

#pragma unroll
        for (int i = 0; i < 8; i++) {
            float4 v0, v1;
            v0.x = S[i][0]; v0.y = S[i][1]; v0.z = S[i][2]; v0.w = S[i][3];
            v1.x = S[i][4]; v1.y = S[i][5]; v1.z = S[i][6]; v1.w = S[i][7];
            *(float4*)(Ps + (ty8 + i) * BKC + tx8)     = v0;
            *(float4*)(Ps + (ty8 + i) * BKC + tx8 + 4) = v1;
        }
        __syncthreads();

        const float* PsRow = Ps + ty8 * BKC;
#pragma unroll 2
        for (int j2 = 0; j2 < BKC; j2++) {
            float4 vb = *(const float4*)(Vs + j2 * HD + tx4);
            float pr[8];
#pragma unroll
            for (int i = 0; i < 8; i++) pr[i] = PsRow[i * BKC + j2];
            float vr[4] = {vb.x, vb.y, vb.z, vb.w};
#pragma unroll
            for (int i = 0; i < 8; i++)
#pragma unroll
                for (int d2 = 0; d2 < 4; d2++)
                    acc[i][d2] = fmaf(pr[i], vr[d2], acc[i][d2]);
        }
        __syncthreads();
    }

#pragma unroll
    for (int i = 0; i < 8; i++) {
        float inv = 1.f / l[i];
        int n = qbase + ty8 + i;
        float4 v;
        v.x = tf32_rna(acc[i][0] * inv); v.y = tf32_rna(acc[i][1] * inv);
        v.z = tf32_rna(acc[i][2] * inv); v.w = tf32_rna(acc[i][3] * inv);
        *(float4*)(out + (size_t)(b * NTOK + n) * CDIM + h * HD + tx4) = v;
    }
}

// ============================================================================
// launch
// ============================================================================
extern "C" void kernel_launch(void* const* d_in, const int* in_sizes, int n_in,
                              void* d_out, int out_size)
{
    (void)in_sizes; (void)n_in; (void)out_size;
    const float* x      = (const float*)d_in[0];
    const float* w_qkv  = (const float*)d_in[1];
    const float* w_proj = (const float*)d_in[2];
    const float* b_proj = (const float*)d_in[3];
    float* out = (float*)d_out;

    float *qkv_p, *sc_p, *kT_p, *vs_p, *ao_p, *xhi_p, *xlo_p;
    float *wqh_p, *wql_p, *wph_p, *wpl_p;
    int* keep_p;
    cudaGetSymbolAddress((void**)&qkv_p,  g_qkv);
    cudaGetSymbolAddress((void**)&sc_p,   g_scores);
    cudaGetSymbolAddress((void**)&keep_p, g_keep);
    cudaGetSymbolAddress((void**)&kT_p,   g_kselT);
    cudaGetSymbolAddress((void**)&vs_p,   g_vsel);
    cudaGetSymbolAddress((void**)&ao_p,   g_attnout);
    cudaGetSymbolAddress((void**)&xhi_p,  g_xhi);
    cudaGetSymbolAddress((void**)&xlo_p,  g_xlo);
    cudaGetSymbolAddress((void**)&wqh_p,  g_wqT_hi);
    cudaGetSymbolAddress((void**)&wql_p,  g_wqT_lo);
    cudaGetSymbolAddress((void**)&wph_p,  g_wpT_hi);
    cudaGetSymbolAddress((void**)&wpl_p,  g_wpT_lo);

    const int smem3 = 4 * 128 * SST * (int)sizeof(float);  // 73728
    const int smem2 = 3 * 128 * SST * (int)sizeof(float);  // 55296
    cudaFuncSetAttribute(mma_gemm<3>, cudaFuncAttributeMaxDynamicSharedMemorySize, smem3);
    cudaFuncSetAttribute(mma_gemm<2>, cudaFuncAttributeMaxDynamicSharedMemorySize, smem2);
    const int attn_smem = (2 * HD * BQ + BKC * HD + BKC * BKC) * (int)sizeof(float);
    cudaFuncSetAttribute(attn_kernel, cudaFuncAttributeMaxDynamicSharedMemorySize, attn_smem);

    // 0) tf32 splits
    xsplit_kernel<<<(ROWS * CDIM / 4 + 255) / 256, 256>>>(x, xhi_p, xlo_p, ROWS * CDIM / 4);
    wsplit_kernel<<<dim3(C3 / 32, CDIM / 32), dim3(32, 8)>>>(w_qkv, wqh_p, wql_p, CDIM, C3);
    wsplit_kernel<<<dim3(CDIM / 32, CDIM / 32), dim3(32, 8)>>>(w_proj, wph_p, wpl_p, CDIM, CDIM);

    // 1) qkv = x @ w_qkv  (3-term tf32 -> fp32-class, top-k safe)
    mma_gemm<3><<<dim3(C3 / 128, ROWS / 128), 256, smem3>>>(
        xhi_p, xlo_p, wqh_p, wql_p, qkv_p, CDIM, C3, nullptr, 0);

    // 2) scores, 3) top-k, 4) gather, 5) attention
    scores_kernel<<<(NBH * NTOK + 255) / 256, 256>>>(qkv_p, sc_p);
    topk_kernel<<<NBH, 1024>>>(sc_p, keep_p);
    gather_kernel<<<dim3(KEEP / 64, NBH), 256>>>(qkv_p, keep_p, kT_p, vs_p);
    attn_kernel<<<dim3(NTOK / BQ, NBH), 256, attn_smem>>>(qkv_p, kT_p, vs_p, ao_p);

    // 6) out = clip(attnout @ w_proj + b_proj, -10, 10)  (2-term tf32)
    mma_gemm<2><<<dim3(CDIM / 128, ROWS / 128), 256, smem2>>>(
        ao_p, nullptr, wph_p, wpl_p, out, CDIM, CDIM, b_proj, 1);
}

// round 5
// speedup vs baseline: 1.8991x; 1.4875x over previous
#include <cuda_runtime.h>
#include <math.h>
#include <cstdint>

#define NH    12
#define NTOK  2048
#define BATCH 4
#define CDIM  768
#define HD    64
#define KEEP  1024
#define ROWS  (BATCH*NTOK)   /* 8192 */
#define C3    (3*CDIM)       /* 2304 */
#define NBH   (BATCH*NH)     /* 48 */
#define SST   36             /* smem row stride (floats) for GEMM tiles */
#define CLIPV 72.134689f     /* 50 * log2(e) */

// ---- scratch (static device globals; no runtime allocation) ----
__device__ float g_qkv[(size_t)ROWS * C3];
__device__ float g_scores[NBH * NTOK];
__device__ int   g_keep[NBH * KEEP];
__device__ float g_ksel [(size_t)NBH * KEEP * HD];  // [bh][j][d] row-major, tf32
__device__ float g_vselT[(size_t)NBH * HD * KEEP];  // [bh][d][j] transposed, tf32
__device__ float g_attnout[(size_t)ROWS * CDIM];
__device__ float g_xhi[(size_t)ROWS * CDIM];
__device__ float g_xlo[(size_t)ROWS * CDIM];
__device__ float g_wqT_hi[(size_t)C3 * CDIM];   // w_qkv^T [2304][768]
__device__ float g_wqT_lo[(size_t)C3 * CDIM];
__device__ float g_wpT_hi[(size_t)CDIM * CDIM]; // w_proj^T [768][768]
__device__ float g_wpT_lo[(size_t)CDIM * CDIM];

__device__ __forceinline__ float tf32_rna(float a) {
    float r; asm("cvt.rna.tf32.f32 %0, %1;" : "=f"(r) : "f"(a)); return r;
}
__device__ __forceinline__ float pexp(float s) {
    s = fminf(fmaxf(s, -CLIPV), CLIPV);
    float r; asm("ex2.approx.ftz.f32 %0, %1;" : "=f"(r) : "f"(s)); return r;
}
__device__ __forceinline__ void mma_tf32(float& c0, float& c1, float& c2, float& c3,
                                         uint32_t a0, uint32_t a1, uint32_t a2, uint32_t a3,
                                         uint32_t b0, uint32_t b1) {
    asm volatile("mma.sync.aligned.m16n8k8.row.col.f32.tf32.tf32.f32 "
        "{%0,%1,%2,%3}, {%4,%5,%6,%7}, {%8,%9}, {%0,%1,%2,%3};"
        : "+f"(c0), "+f"(c1), "+f"(c2), "+f"(c3)
        : "r"(a0), "r"(a1), "r"(a2), "r"(a3), "r"(b0), "r"(b1));
}

// ============================================================================
// mma.sync tf32 GEMM: C[M,N] = A[M,K] @ BT[N,K]^T.
// CTA tile 128x128, 8 warps (2m x 4n), warp tile 64x32, K-chunk 32.
// TERMS=3: Ah*Bh + Ah*Bl + Al*Bh; TERMS=2: Ah*(Bh+Bl); TERMS=1: Ah*Bh.
// ============================================================================
template<int TERMS>
__global__ __launch_bounds__(256) void mma_gemm(
    const float* __restrict__ Ahi, const float* __restrict__ Alo,
    const float* __restrict__ Bhi, const float* __restrict__ Blo,
    float* __restrict__ C, int K, int ldc,
    const float* __restrict__ bias, int do_clip)
{
    extern __shared__ float sm[];
    float* Ah = sm;                    // [128][SST]
    float* Bh = sm + 128 * SST;
    float* Bl = sm + 2 * 128 * SST;    // TERMS>=2
    float* Al = sm + 3 * 128 * SST;    // TERMS==3

    const int tid = threadIdx.x, lane = tid & 31, wid = tid >> 5;
    const int g = lane >> 2, ct = lane & 3;
    const int wm = wid & 1, wn = wid >> 1;
    const int m0 = blockIdx.y * 128, n0 = blockIdx.x * 128;
    const int lrow = tid >> 1, lk0 = (tid & 1) * 16;

    float acc[4][4][4];
#pragma unroll
    for (int mt = 0; mt < 4; mt++)
#pragma unroll
        for (int nt = 0; nt < 4; nt++)
#pragma unroll
            for (int i = 0; i < 4; i++) acc[mt][nt][i] = 0.f;

    const float* Agh = Ahi + (size_t)(m0 + lrow) * K + lk0;
    const float* Bgh = Bhi + (size_t)(n0 + lrow) * K + lk0;
    const float* Bgl = (TERMS >= 2) ? (Blo + (size_t)(n0 + lrow) * K + lk0) : nullptr;
    const float* Agl = (TERMS == 3) ? (Alo + (size_t)(m0 + lrow) * K + lk0) : nullptr;

    const int NC = K / 32;
    for (int c = 0; c < NC; c++) {
        const int k0 = c * 32;
#pragma unroll
        for (int i = 0; i < 4; i++) {
            int kk = lk0 + i * 4;
            *(float4*)&Ah[lrow * SST + kk] = *(const float4*)(Agh + k0 + i * 4);
            *(float4*)&Bh[lrow * SST + kk] = *(const float4*)(Bgh + k0 + i * 4);
            if (TERMS >= 2)
                *(float4*)&Bl[lrow * SST + kk] = *(const float4*)(Bgl + k0 + i * 4);
            if (TERMS == 3)
                *(float4*)&Al[lrow * SST + kk] = *(const float4*)(Agl + k0 + i * 4);
        }
        __syncthreads();

#pragma unroll
        for (int ks = 0; ks < 4; ks++) {
            const int kc = ks * 8 + ct;
            uint32_t afh[4][4], afl[4][4], bfh[4][2], bfl[4][2];
#pragma unroll
            for (int mt = 0; mt < 4; mt++) {
                int r = (wm * 64 + mt * 16 + g) * SST;
                afh[mt][0] = __float_as_uint(Ah[r + kc]);
                afh[mt][1] = __float_as_uint(Ah[r + 8 * SST + kc]);
                afh[mt][2] = __float_as_uint(Ah[r + kc + 4]);
                afh[mt][3] = __float_as_uint(Ah[r + 8 * SST + kc + 4]);
                if (TERMS == 3) {
                    afl[mt][0] = __float_as_uint(Al[r + kc]);
                    afl[mt][1] = __float_as_uint(Al[r + 8 * SST + kc]);
                    afl[mt][2] = __float_as_uint(Al[r + kc + 4]);
                    afl[mt][3] = __float_as_uint(Al[r + 8 * SST + kc + 4]);
                }
            }
#pragma unroll
            for (int nt = 0; nt < 4; nt++) {
                int r = (wn * 32 + nt * 8 + g) * SST;
                bfh[nt][0] = __float_as_uint(Bh[r + kc]);
                bfh[nt][1] = __float_as_uint(Bh[r + kc + 4]);
                if (TERMS >= 2) {
                    bfl[nt][0] = __float_as_uint(Bl[r + kc]);
                    bfl[nt][1] = __float_as_uint(Bl[r + kc + 4]);
                }
            }
#pragma unroll
            for (int mt = 0; mt < 4; mt++)
#pragma unroll
                for (int nt = 0; nt < 4; nt++) {
                    float* a = acc[mt][nt];
                    mma_tf32(a[0], a[1], a[2], a[3],
                             afh[mt][0], afh[mt][1], afh[mt][2], afh[mt][3],
                             bfh[nt][0], bfh[nt][1]);
                    if (TERMS >= 2)
                        mma_tf32(a[0], a[1], a[2], a[3],
                                 afh[mt][0], afh[mt][1], afh[mt][2], afh[mt][3],
                                 bfl[nt][0], bfl[nt][1]);
                    if (TERMS == 3)
                        mma_tf32(a[0], a[1], a[2], a[3],
                                 afl[mt][0], afl[mt][1], afl[mt][2], afl[mt][3],
                                 bfh[nt][0], bfh[nt][1]);
                }
        }
        __syncthreads();
    }

#pragma unroll
    for (int mt = 0; mt < 4; mt++) {
#pragma unroll
        for (int nt = 0; nt < 4; nt++) {
            int row = m0 + wm * 64 + mt * 16 + g;
            int col = n0 + wn * 32 + nt * 8 + ct * 2;
            float v0 = acc[mt][nt][0], v1 = acc[mt][nt][1];
            float v2 = acc[mt][nt][2], v3 = acc[mt][nt][3];
            if (bias) {
                float b0 = bias[col], b1 = bias[col + 1];
                v0 += b0; v1 += b1; v2 += b0; v3 += b1;
            }
            if (do_clip) {
                v0 = fminf(fmaxf(v0, -10.f), 10.f);
                v1 = fminf(fmaxf(v1, -10.f), 10.f);
                v2 = fminf(fmaxf(v2, -10.f), 10.f);
                v3 = fminf(fmaxf(v3, -10.f), 10.f);
            }
            float2 lo2; lo2.x = v0; lo2.y = v1;
            float2 hi2; hi2.x = v2; hi2.y = v3;
            *(float2*)(C + (size_t)row * ldc + col) = lo2;
            *(float2*)(C + (size_t)(row + 8) * ldc + col) = hi2;
        }
    }
}

// ============================================================================
// x -> (hi, lo) tf32 split
// ============================================================================
__global__ void xsplit_kernel(const float* __restrict__ x, float* __restrict__ hi,
                              float* __restrict__ lo, int n4)
{
    int i = blockIdx.x * blockDim.x + threadIdx.x;
    if (i >= n4) return;
    float4 v = ((const float4*)x)[i];
    float4 h, l;
    h.x = tf32_rna(v.x); l.x = tf32_rna(v.x - h.x);
    h.y = tf32_rna(v.y); l.y = tf32_rna(v.y - h.y);
    h.z = tf32_rna(v.z); l.z = tf32_rna(v.z - h.z);
    h.w = tf32_rna(v.w); l.w = tf32_rna(v.w - h.w);
    ((float4*)hi)[i] = h;
    ((float4*)lo)[i] = l;
}

// ============================================================================
// weight transpose + tf32 split: in[K,N] -> ohi[N,K] + olo[N,K]
// ============================================================================
__global__ void wsplit_kernel(const float* __restrict__ in, float* __restrict__ ohi,
                              float* __restrict__ olo, int K, int N)
{
    __shared__ float t[32][33];
    const int n0 = blockIdx.x * 32, k0 = blockIdx.y * 32;
    const int tx = threadIdx.x, ty = threadIdx.y;
#pragma unroll
    for (int i = 0; i < 4; i++)
        t[ty + i * 8][tx] = in[(size_t)(k0 + ty + i * 8) * N + n0 + tx];
    __syncthreads();
#pragma unroll
    for (int i = 0; i < 4; i++) {
        float v = t[tx][ty + i * 8];
        float h = tf32_rna(v);
        ohi[(size_t)(n0 + ty + i * 8) * K + k0 + tx] = h;
        olo[(size_t)(n0 + ty + i * 8) * K + k0 + tx] = tf32_rna(v - h);
    }
}

// ============================================================================
// scores[bh][n] = sum_d q^2
// ============================================================================
__global__ void scores_kernel(const float* __restrict__ qkv, float* __restrict__ scores)
{
    int idx = blockIdx.x * blockDim.x + threadIdx.x;
    if (idx >= NBH * NTOK) return;
    int n  = idx & (NTOK - 1);
    int bh = idx >> 11;
    int h = bh % NH, b = bh / NH;
    const float4* q = (const float4*)(qkv + (size_t)(b * NTOK + n) * C3 + h * HD);
    float s = 0.f;
#pragma unroll
    for (int i = 0; i < 16; i++) {
        float4 v = q[i];
        s += v.x * v.x + v.y * v.y + v.z * v.z + v.w * v.w;
    }
    scores[idx] = s;
}

// ============================================================================
// Per-(b,h) top-KEEP via bitonic sort of packed u64 keys (set semantics).
// ============================================================================
__global__ __launch_bounds__(1024) void topk_kernel(
    const float* __restrict__ scores, int* __restrict__ keep)
{
    __shared__ unsigned long long keys[NTOK];
    const int bh = blockIdx.x, t = threadIdx.x;
    for (int i = t; i < NTOK; i += 1024) {
        unsigned sb = __float_as_uint(scores[bh * NTOK + i]);
        keys[i] = ((unsigned long long)sb << 32) | (unsigned)(NTOK - 1 - i);
    }
    for (int k = 2; k <= NTOK; k <<= 1) {
        for (int j = k >> 1; j > 0; j >>= 1) {
            __syncthreads();
            for (int i = t; i < NTOK; i += 1024) {
                int ixj = i ^ j;
                if (ixj > i) {
                    unsigned long long a = keys[i], c = keys[ixj];
                    bool asc = ((i & k) == 0);
                    if ((a > c) == asc) { keys[i] = c; keys[ixj] = a; }
                }
            }
        }
    }
    __syncthreads();
    if (t < KEEP) {
        keep[bh * KEEP + t] = (NTOK - 1) - (int)(keys[NTOK - KEEP + t] & 0xffffffffu);
    }
}

// ============================================================================
// Gather: K row-major [bh][j][d] (tf32-rounded), V transposed [bh][d][j]
// (tf32-rounded). grid = (KEEP/64, NBH), 256 threads.
// ============================================================================
__global__ __launch_bounds__(256) void gather_kernel(
    const float* __restrict__ qkv, const int* __restrict__ keep,
    float* __restrict__ ksel, float* __restrict__ vselT)
{
    __shared__ float tile[HD][65];
    const int bh = blockIdx.y, jc = blockIdx.x;
    const int b = bh / NH, h = bh % NH;
    const int t = threadIdx.x;

#pragma unroll
    for (int r = 0; r < 4; r++) {
        int idx = t + r * 256;
        int row = idx >> 4, f4 = (idx & 15) * 4;
        int kidx = keep[bh * KEEP + jc * 64 + row];
        const float* base = qkv + (size_t)(b * NTOK + kidx) * C3 + h * HD;
        float4 kv = *(const float4*)(base + CDIM + f4);
        kv.x = tf32_rna(kv.x); kv.y = tf32_rna(kv.y);
        kv.z = tf32_rna(kv.z); kv.w = tf32_rna(kv.w);
        *(float4*)(ksel + ((size_t)bh * KEEP + jc * 64 + row) * HD + f4) = kv;
        float4 vv = *(const float4*)(base + 2 * CDIM + f4);
        tile[f4 + 0][row] = tf32_rna(vv.x); tile[f4 + 1][row] = tf32_rna(vv.y);
        tile[f4 + 2][row] = tf32_rna(vv.z); tile[f4 + 3][row] = tf32_rna(vv.w);
    }
    __syncthreads();
#pragma unroll
    for (int r = 0; r < 4; r++) {
        int idx = t + r * 256;
        int d = idx >> 4, jf = (idx & 15) * 4;
        float4 v;
        v.x = tile[d][jf + 0]; v.y = tile[d][jf + 1];
        v.z = tile[d][jf + 2]; v.w = tile[d][jf + 3];
        *(float4*)(vselT + ((size_t)bh * HD + d) * KEEP + jc * 64 + jf) = v;
    }
}

// ============================================================================
// mma.sync attention: BQ=128 x key-chunks of 128. 8 warps (2m x 4n).
// No online max (|S|<=clip; exp sums can't overflow fp32): O = sum(pV), l = sum(p),
// normalize once at the end. S and PV both m16n8k8 tf32; P through swizzled smem.
// smem: Qs[128][64] | Ks[128][64] | Vs[64][128] | Pp[128][128] | Lr[4][128]
// ============================================================================
__global__ __launch_bounds__(256, 1) void attn_mma(
    const float* __restrict__ qkv, const float* __restrict__ ksel,
    const float* __restrict__ vselT, float* __restrict__ out)
{
    extern __shared__ float sm[];
    float* Qs = sm;            // [128][64] xor-swizzled
    float* Ks = sm + 8192;     // [128][64] xor-swizzled
    float* Vs = sm + 16384;    // [64][128] xor-swizzled
    float* Pp = sm + 24576;    // [128][128] xor-swizzled
    float* Lr = sm + 40960;    // [4][128]

    const int tid = threadIdx.x, lane = tid & 31, wid = tid >> 5;
    const int g = lane >> 2, ct = lane & 3, g4 = g << 2;
    const int wm = wid & 1, wn = wid >> 1;
    const int bh = blockIdx.y, b = bh / NH, h = bh % NH;
    const int qbase = blockIdx.x * 128;

    // load Q scaled by 0.125*log2(e), tf32-rounded, swizzled
    {
        int j = tid & 127, half = tid >> 7;
        const float* qrow = qkv + (size_t)(b * NTOK + qbase + j) * C3 + h * HD + half * 32;
        const float QSC = 0.125f * 1.44269504f;
#pragma unroll
        for (int i = 0; i < 8; i++) {
            float4 v = *(const float4*)(qrow + i * 4);
            v.x = tf32_rna(v.x * QSC); v.y = tf32_rna(v.y * QSC);
            v.z = tf32_rna(v.z * QSC); v.w = tf32_rna(v.w * QSC);
            int c = half * 32 + i * 4;
            *(float4*)&Qs[j * 64 + (c ^ ((j & 7) << 2))] = v;
        }
    }

    float Oacc[4][2][4];
    float lp[4][2];
#pragma unroll
    for (int mt = 0; mt < 4; mt++) {
        lp[mt][0] = 0.f; lp[mt][1] = 0.f;
#pragma unroll
        for (int nt = 0; nt < 2; nt++)
#pragma unroll
            for (int i = 0; i < 4; i++) Oacc[mt][nt][i] = 0.f;
    }

    const float* kbase = ksel  + (size_t)bh * KEEP * HD;
    const float* vbase = vselT + (size_t)bh * HD * KEEP;

    for (int kc = 0; kc < KEEP / 128; kc++) {
        // load K chunk [128][64] and V chunk [64][128]
        {
            int j = tid & 127, half = tid >> 7;
            const float* kr = kbase + (size_t)(kc * 128 + j) * HD + half * 32;
#pragma unroll
            for (int i = 0; i < 8; i++) {
                float4 v = *(const float4*)(kr + i * 4);
                int c = half * 32 + i * 4;
                *(float4*)&Ks[j * 64 + (c ^ ((j & 7) << 2))] = v;
            }
            int d = tid & 63, part = tid >> 6;
            const float* vr = vbase + (size_t)d * KEEP + kc * 128 + part * 32;
#pragma unroll
            for (int i = 0; i < 8; i++) {
                float4 v = *(const float4*)(vr + i * 4);
                int c = part * 32 + i * 4;
                *(float4*)&Vs[d * 128 + (c ^ ((d & 7) << 2))] = v;
            }
        }
        __syncthreads();

        // ---- S = (Q*scale) @ K^T  (pre-scaled, log2 domain)
        float P[4][4][4];
#pragma unroll
        for (int mt = 0; mt < 4; mt++)
#pragma unroll
            for (int nt = 0; nt < 4; nt++)
#pragma unroll
                for (int i = 0; i < 4; i++) P[mt][nt][i] = 0.f;

#pragma unroll
        for (int ks = 0; ks < 8; ks++) {
            const int k0 = ks * 8 + ct, k1 = k0 + 4;
            uint32_t qa[4][4], kb[4][2];
#pragma unroll
            for (int mt = 0; mt < 4; mt++) {
                int r0 = (wm * 64 + mt * 16 + g) * 64, r1 = r0 + 8 * 64;
                qa[mt][0] = __float_as_uint(Qs[r0 + (k0 ^ g4)]);
                qa[mt][1] = __float_as_uint(Qs[r1 + (k0 ^ g4)]);
                qa[mt][2] = __float_as_uint(Qs[r0 + (k1 ^ g4)]);
                qa[mt][3] = __float_as_uint(Qs[r1 + (k1 ^ g4)]);
            }
#pragma unroll
            for (int nt = 0; nt < 4; nt++) {
                int n0 = (wn * 32 + nt * 8 + g) * 64;
                kb[nt][0] = __float_as_uint(Ks[n0 + (k0 ^ g4)]);
                kb[nt][1] = __float_as_uint(Ks[n0 + (k1 ^ g4)]);
            }
#pragma unroll
            for (int mt = 0; mt < 4; mt++)
#pragma unroll
                for (int nt = 0; nt < 4; nt++)
                    mma_tf32(P[mt][nt][0], P[mt][nt][1], P[mt][nt][2], P[mt][nt][3],
                             qa[mt][0], qa[mt][1], qa[mt][2], qa[mt][3],
                             kb[nt][0], kb[nt][1]);
        }

        // ---- p = exp2(clip(s)), accumulate row sums, store P to smem
#pragma unroll
        for (int mt = 0; mt < 4; mt++) {
            int r0 = wm * 64 + mt * 16 + g;
#pragma unroll
            for (int nt = 0; nt < 4; nt++) {
                int c0 = wn * 32 + nt * 8 + 2 * ct;
                float p0 = pexp(P[mt][nt][0]);
                float p1 = pexp(P[mt][nt][1]);
                float p2 = pexp(P[mt][nt][2]);
                float p3 = pexp(P[mt][nt][3]);
                lp[mt][0] += p0 + p1;
                lp[mt][1] += p2 + p3;
                Pp[r0 * 128 + (c0 ^ g4)]           = p0;
                Pp[r0 * 128 + ((c0 + 1) ^ g4)]     = p1;
                Pp[(r0 + 8) * 128 + (c0 ^ g4)]       = p2;
                Pp[(r0 + 8) * 128 + ((c0 + 1) ^ g4)] = p3;
            }
        }
        __syncthreads();

        // ---- O += P @ V
#pragma unroll
        for (int ks = 0; ks < 16; ks++) {
            const int k0 = ks * 8 + ct, k1 = k0 + 4;
            uint32_t pa[4][4], vb[2][2];
#pragma unroll
            for (int mt = 0; mt < 4; mt++) {
                int r0 = (wm * 64 + mt * 16 + g) * 128, r1 = r0 + 8 * 128;
                pa[mt][0] = __float_as_uint(Pp[r0 + (k0 ^ g4)]);
                pa[mt][1] = __float_as_uint(Pp[r1 + (k0 ^ g4)]);
                pa[mt][2] = __float_as_uint(Pp[r0 + (k1 ^ g4)]);
                pa[mt][3] = __float_as_uint(Pp[r1 + (k1 ^ g4)]);
            }
#pragma unroll
            for (int nt = 0; nt < 2; nt++) {
                int d0 = (wn * 16 + nt * 8 + g) * 128;
                vb[nt][0] = __float_as_uint(Vs[d0 + (k0 ^ g4)]);
                vb[nt][1] = __float_as_uint(Vs[d0 + (k1 ^ g4)]);
            }
#pragma unroll
            for (int mt = 0; mt < 4; mt++)
#pragma unroll
                for (int nt = 0; nt < 2; nt++)
                    mma_tf32(Oacc[mt][nt][0], Oacc[mt][nt][1], Oacc[mt][nt][2], Oacc[mt][nt][3],
                             pa[mt][0], pa[mt][1], pa[mt][2], pa[mt][3],
                             vb[nt][0], vb[nt][1]);
        }
        __syncthreads();
    }

    // ---- l reduction: intra-quad shfl, then cross-warp via smem
#pragma unroll
    for (int mt = 0; mt < 4; mt++)
#pragma unroll
        for (int hf = 0; hf < 2; hf++) {
            float v = lp[mt][hf];
            v += __shfl_xor_sync(0xffffffffu, v, 1);
            v += __shfl_xor_sync(0xffffffffu, v, 2);
            lp[mt][hf] = v;
        }
    if (ct == 0) {
#pragma unroll
        for (int mt = 0; mt < 4; mt++) {
            int r0 = wm * 64 + mt * 16 + g;
            Lr[wn * 128 + r0]     = lp[mt][0];
            Lr[wn * 128 + r0 + 8] = lp[mt][1];
        }
    }
    __syncthreads();
    float linv[4][2];
#pragma unroll
    for (int mt = 0; mt < 4; mt++)
#pragma unroll
        for (int hf = 0; hf < 2; hf++) {
            int r = wm * 64 + mt * 16 + g + hf * 8;
            linv[mt][hf] = 1.f / (Lr[r] + Lr[128 + r] + Lr[256 + r] + Lr[384 + r]);
        }

    // ---- write O (tf32-rounded for the proj GEMM)
#pragma unroll
    for (int mt = 0; mt < 4; mt++) {
        int r0 = wm * 64 + mt * 16 + g;
#pragma unroll
        for (int nt = 0; nt < 2; nt++) {
            int d0 = wn * 16 + nt * 8 + 2 * ct;
            float2 a;
            a.x = tf32_rna(Oacc[mt][nt][0] * linv[mt][0]);
            a.y = tf32_rna(Oacc[mt][nt][1] * linv[mt][0]);
            *(float2*)&out[(size_t)(b * NTOK + qbase + r0) * CDIM + h * HD + d0] = a;
            float2 c;
            c.x = tf32_rna(Oacc[mt][nt][2] * linv[mt][1]);
            c.y = tf32_rna(Oacc[mt][nt][3] * linv[mt][1]);
            *(float2*)&out[(size_t)(b * NTOK + qbase + r0 + 8) * CDIM + h * HD + d0] = c;
        }
    }
}

// ============================================================================
// launch
// ============================================================================
extern "C" void kernel_launch(void* const* d_in, const int* in_sizes, int n_in,
                              void* d_out, int out_size)
{
    (void)in_sizes; (void)n_in; (void)out_size;
    const float* x      = (const float*)d_in[0];
    const float* w_qkv  = (const float*)d_in[1];
    const float* w_proj = (const float*)d_in[2];
    const float* b_proj = (const float*)d_in[3];
    float* out = (float*)d_out;

    float *qkv_p, *sc_p, *ks_p, *vT_p, *ao_p, *xhi_p, *xlo_p;
    float *wqh_p, *wql_p, *wph_p, *wpl_p;
    int* keep_p;
    cudaGetSymbolAddress((void**)&qkv_p,  g_qkv);
    cudaGetSymbolAddress((void**)&sc_p,   g_scores);
    cudaGetSymbolAddress((void**)&keep_p, g_keep);
    cudaGetSymbolAddress((void**)&ks_p,   g_ksel);
    cudaGetSymbolAddress((void**)&vT_p,   g_vselT);
    cudaGetSymbolAddress((void**)&ao_p,   g_attnout);
    cudaGetSymbolAddress((void**)&xhi_p,  g_xhi);
    cudaGetSymbolAddress((void**)&xlo_p,  g_xlo);
    cudaGetSymbolAddress((void**)&wqh_p,  g_wqT_hi);
    cudaGetSymbolAddress((void**)&wql_p,  g_wqT_lo);
    cudaGetSymbolAddress((void**)&wph_p,  g_wpT_hi);
    cudaGetSymbolAddress((void**)&wpl_p,  g_wpT_lo);

    const int smem3 = 4 * 128 * SST * (int)sizeof(float);  // 73728
    const int smem2 = 3 * 128 * SST * (int)sizeof(float);  // 55296
    const int smem1 = 2 * 128 * SST * (int)sizeof(float);  // 36864
    cudaFuncSetAttribute(mma_gemm<3>, cudaFuncAttributeMaxDynamicSharedMemorySize, smem3);
    cudaFuncSetAttribute(mma_gemm<2>, cudaFuncAttributeMaxDynamicSharedMemorySize, smem2);
    cudaFuncSetAttribute(mma_gemm<1>, cudaFuncAttributeMaxDynamicSharedMemorySize, smem1);
    const int attn_smem = (4 * 8192 + 8192 + 512) * (int)sizeof(float); // 165888
    cudaFuncSetAttribute(attn_mma, cudaFuncAttributeMaxDynamicSharedMemorySize, attn_smem);

    // 0) tf32 splits
    xsplit_kernel<<<(ROWS * CDIM / 4 + 255) / 256, 256>>>(x, xhi_p, xlo_p, ROWS * CDIM / 4);
    wsplit_kernel<<<dim3(C3 / 32, CDIM / 32), dim3(32, 8)>>>(w_qkv, wqh_p, wql_p, CDIM, C3);
    wsplit_kernel<<<dim3(CDIM / 32, CDIM / 32), dim3(32, 8)>>>(w_proj, wph_p, wpl_p, CDIM, CDIM);

    // 1a) q = x @ w_q  (3-term tf32, fp32-class -> top-k safe)
    mma_gemm<3><<<dim3(CDIM / 128, ROWS / 128), 256, smem3>>>(
        xhi_p, xlo_p, wqh_p, wql_p, qkv_p, CDIM, C3, nullptr, 0);
    // 1b) k,v = x @ w_kv  (1-term tf32)
    mma_gemm<1><<<dim3(2 * CDIM / 128, ROWS / 128), 256, smem1>>>(
        xhi_p, nullptr, wqh_p + (size_t)CDIM * CDIM, nullptr,
        qkv_p + CDIM, CDIM, C3, nullptr, 0);

    // 2) scores, 3) top-k, 4) gather
    scores_kernel<<<(NBH * NTOK + 255) / 256, 256>>>(qkv_p, sc_p);
    topk_kernel<<<NBH, 1024>>>(sc_p, keep_p);
    gather_kernel<<<dim3(KEEP / 64, NBH), 256>>>(qkv_p, keep_p, ks_p, vT_p);

    // 5) attention on tensor cores
    attn_mma<<<dim3(NTOK / 128, NBH), 256, attn_smem>>>(qkv_p, ks_p, vT_p, ao_p);

    // 6) out = clip(attnout @ w_proj + b_proj, -10, 10)  (2-term tf32, exact on tf32 inputs)
    mma_gemm<2><<<dim3(CDIM / 128, ROWS / 128), 256, smem2>>>(
        ao_p, nullptr, wph_p, wpl_p, out, CDIM, CDIM, b_proj, 1);
}

// round 6
// speedup vs baseline: 2.0748x; 1.0925x over previous
#include <cuda_runtime.h>
#include <math.h>
#include <cstdint>

#define NH    12
#define NTOK  2048
#define BATCH 4
#define CDIM  768
#define HD    64
#define KEEP  1024
#define ROWS  (BATCH*NTOK)   /* 8192 */
#define C3    (3*CDIM)       /* 2304 */
#define NBH   (BATCH*NH)     /* 48 */
#define CLIPV 72.134689f     /* 50 * log2(e) */

// ---- scratch (static device globals; no runtime allocation) ----
__device__ float g_qkv[(size_t)ROWS * C3];
__device__ float g_scores[NBH * NTOK];
__device__ int   g_keep[NBH * KEEP];
__device__ float g_ksel [(size_t)NBH * KEEP * HD];  // [bh][j][d] row-major, tf32
__device__ float g_vselT[(size_t)NBH * HD * KEEP];  // [bh][d][j] transposed, tf32
__device__ float g_attnout[(size_t)ROWS * CDIM];
__device__ float g_xhi[(size_t)ROWS * CDIM];
__device__ float g_xlo[(size_t)ROWS * CDIM];
__device__ float g_wqT_hi[(size_t)C3 * CDIM];   // w_qkv^T [2304][768]
__device__ float g_wqT_lo[(size_t)C3 * CDIM];
__device__ float g_wpT_hi[(size_t)CDIM * CDIM]; // w_proj^T [768][768]
__device__ float g_wpT_lo[(size_t)CDIM * CDIM];

__device__ __forceinline__ float tf32_rna(float a) {
    float r; asm("cvt.rna.tf32.f32 %0, %1;" : "=f"(r) : "f"(a)); return r;
}
__device__ __forceinline__ float pexp(float s) {
    s = fminf(fmaxf(s, -CLIPV), CLIPV);
    float r; asm("ex2.approx.ftz.f32 %0, %1;" : "=f"(r) : "f"(s)); return r;
}
__device__ __forceinline__ uint32_t smem_u32(const void* p) {
    uint32_t a;
    asm("{ .reg .u64 t; cvta.to.shared.u64 t, %1; cvt.u32.u64 %0, t; }" : "=r"(a) : "l"(p));
    return a;
}
__device__ __forceinline__ void cp16(uint32_t dst, const float* src) {
    size_t ga = __cvta_generic_to_global(src);
    asm volatile("cp.async.cg.shared.global [%0], [%1], 16;" :: "r"(dst), "l"(ga));
}
__device__ __forceinline__ void mma_tf32(float& c0, float& c1, float& c2, float& c3,
                                         uint32_t a0, uint32_t a1, uint32_t a2, uint32_t a3,
                                         uint32_t b0, uint32_t b1) {
    asm volatile("mma.sync.aligned.m16n8k8.row.col.f32.tf32.tf32.f32 "
        "{%0,%1,%2,%3}, {%4,%5,%6,%7}, {%8,%9}, {%0,%1,%2,%3};"
        : "+f"(c0), "+f"(c1), "+f"(c2), "+f"(c3)
        : "r"(a0), "r"(a1), "r"(a2), "r"(a3), "r"(b0), "r"(b1));
}

// ============================================================================
// cp.async double-buffered mma.sync tf32 GEMM body.
// C[M,N] = A[M,K] @ BT[N,K]^T, CTA tile 128x128, 8 warps (2m x 4n).
// TERMS=3: Ah*Bh + Ah*Bl + Al*Bh;  TERMS=2: Ah*(Bh+Bl);  TERMS=1: Ah*Bh.
// CH = K-chunk (16 for TERMS=3, else 32); smem row stride CH+4 (conflict-free).
// ============================================================================
template<int TERMS, int CH>
__device__ __forceinline__ void gemm_body(
    const float* __restrict__ Ahi, const float* __restrict__ Alo,
    const float* __restrict__ Bhi, const float* __restrict__ Blo,
    float* __restrict__ C, int K, int ldc,
    const float* __restrict__ bias, int do_clip, float* sm)
{
    constexpr int RS = CH + 4;
    constexpr int T  = 128 * RS;                       // floats per tile
    constexpr int NT = (TERMS == 3) ? 4 : (TERMS + 1); // tiles per stage
    constexpr int SS = NT * T;                         // floats per stage

    const int tid = threadIdx.x, lane = tid & 31, wid = tid >> 5;
    const int g = lane >> 2, ct = lane & 3;
    const int wm = wid & 1, wn = wid >> 1;
    const int m0 = blockIdx.y * 128, n0 = blockIdx.x * 128;
    const int lrow = tid >> 1, lk0 = (tid & 1) * (CH / 2);

    float acc[4][4][4];
#pragma unroll
    for (int mt = 0; mt < 4; mt++)
#pragma unroll
        for (int nt = 0; nt < 4; nt++)
#pragma unroll
            for (int i = 0; i < 4; i++) acc[mt][nt][i] = 0.f;

    const float* agh = Ahi + (size_t)(m0 + lrow) * K + lk0;
    const float* bgh = Bhi + (size_t)(n0 + lrow) * K + lk0;
    const float* bgl = (TERMS >= 2) ? (Blo + (size_t)(n0 + lrow) * K + lk0) : nullptr;
    const float* agl = (TERMS == 3) ? (Alo + (size_t)(m0 + lrow) * K + lk0) : nullptr;

    const uint32_t sb0 = smem_u32(sm) + (uint32_t)((lrow * RS + lk0) * 4);
    const int NC = K / CH;

    auto issue = [&](int c) {
        const uint32_t sb = sb0 + (uint32_t)((c & 1) * SS * 4);
        const int k0 = c * CH;
#pragma unroll
        for (int i = 0; i < CH / 8; i++) {
            cp16(sb + i * 16,                    agh + k0 + i * 4);
            cp16(sb + (uint32_t)T * 4 + i * 16,  bgh + k0 + i * 4);
            if (TERMS >= 2) cp16(sb + 2u * T * 4 + i * 16, bgl + k0 + i * 4);
            if (TERMS == 3) cp16(sb + 3u * T * 4 + i * 16, agl + k0 + i * 4);
        }
        asm volatile("cp.async.commit_group;" ::: "memory");
    };

    issue(0);
    for (int c = 0; c < NC; c++) {
        if (c + 1 < NC) {
            issue(c + 1);
            asm volatile("cp.async.wait_group 1;" ::: "memory");
        } else {
            asm volatile("cp.async.wait_group 0;" ::: "memory");
        }
        __syncthreads();

        float* Ah = sm + (c & 1) * SS;
        float* Bh = Ah + T;
        float* Bl = Ah + 2 * T;
        float* Al = Ah + 3 * T;

#pragma unroll
        for (int ks = 0; ks < CH / 8; ks++) {
            const int kc = ks * 8 + ct;
            uint32_t afh[4][4], afl[4][4], bfh[4][2], bfl[4][2];
#pragma unroll
            for (int mt = 0; mt < 4; mt++) {
                int r = (wm * 64 + mt * 16 + g) * RS;
                afh[mt][0] = __float_as_uint(Ah[r + kc]);
                afh[mt][1] = __float_as_uint(Ah[r + 8 * RS + kc]);
                afh[mt][2] = __float_as_uint(Ah[r + kc + 4]);
                afh[mt][3] = __float_as_uint(Ah[r + 8 * RS + kc + 4]);
                if (TERMS == 3) {
                    afl[mt][0] = __float_as_uint(Al[r + kc]);
                    afl[mt][1] = __float_as_uint(Al[r + 8 * RS + kc]);
                    afl[mt][2] = __float_as_uint(Al[r + kc + 4]);
                    afl[mt][3] = __float_as_uint(Al[r + 8 * RS + kc + 4]);
                }
            }
#pragma unroll
            for (int nt = 0; nt < 4; nt++) {
                int r = (wn * 32 + nt * 8 + g) * RS;
                bfh[nt][0] = __float_as_uint(Bh[r + kc]);
                bfh[nt][1] = __float_as_uint(Bh[r + kc + 4]);
                if (TERMS >= 2) {
                    bfl[nt][0] = __float_as_uint(Bl[r + kc]);
                    bfl[nt][1] = __float_as_uint(Bl[r + kc + 4]);
                }
            }
#pragma unroll
            for (int mt = 0; mt < 4; mt++)
#pragma unroll
                for (int nt = 0; nt < 4; nt++) {
                    float* a = acc[mt][nt];
                    mma_tf32(a[0], a[1], a[2], a[3],
                             afh[mt][0], afh[mt][1], afh[mt][2], afh[mt][3],
                             bfh[nt][0], bfh[nt][1]);
                    if (TERMS >= 2)
                        mma_tf32(a[0], a[1], a[2], a[3],
                                 afh[mt][0], afh[mt][1], afh[mt][2], afh[mt][3],
                                 bfl[nt][0], bfl[nt][1]);
                    if (TERMS == 3)
                        mma_tf32(a[0], a[1], a[2], a[3],
                                 afl[mt][0], afl[mt][1], afl[mt][2], afl[mt][3],
                                 bfh[nt][0], bfh[nt][1]);
                }
        }
        __syncthreads();
    }

#pragma unroll
    for (int mt = 0; mt < 4; mt++) {
#pragma unroll
        for (int nt = 0; nt < 4; nt++) {
            int row = m0 + wm * 64 + mt * 16 + g;
            int col = n0 + wn * 32 + nt * 8 + ct * 2;
            float v0 = acc[mt][nt][0], v1 = acc[mt][nt][1];
            float v2 = acc[mt][nt][2], v3 = acc[mt][nt][3];
            if (bias) {
                float b0 = bias[col], b1 = bias[col + 1];
                v0 += b0; v1 += b1; v2 += b0; v3 += b1;
            }
            if (do_clip) {
                v0 = fminf(fmaxf(v0, -10.f), 10.f);
                v1 = fminf(fmaxf(v1, -10.f), 10.f);
                v2 = fminf(fmaxf(v2, -10.f), 10.f);
                v3 = fminf(fmaxf(v3, -10.f), 10.f);
            }
            float2 lo2; lo2.x = v0; lo2.y = v1;
            float2 hi2; hi2.x = v2; hi2.y = v3;
            *(float2*)(C + (size_t)row * ldc + col) = lo2;
            *(float2*)(C + (size_t)(row + 8) * ldc + col) = hi2;
        }
    }
}

// qkv in one launch: first 6 column-blocks (q) 3-term, rest (k,v) 1-term
__global__ __launch_bounds__(256) void qkv_gemm(
    const float* __restrict__ xhi, const float* __restrict__ xlo,
    const float* __restrict__ wTh, const float* __restrict__ wTl,
    float* __restrict__ C)
{
    extern __shared__ float sm[];
    if (blockIdx.x * 128 < CDIM)
        gemm_body<3, 16>(xhi, xlo, wTh, wTl, C, CDIM, C3, nullptr, 0, sm);
    else
        gemm_body<1, 32>(xhi, nullptr, wTh, nullptr, C, CDIM, C3, nullptr, 0, sm);
}

__global__ __launch_bounds__(256) void proj_gemm(
    const float* __restrict__ A, const float* __restrict__ Bh,
    const float* __restrict__ Bl, const float* __restrict__ bias,
    float* __restrict__ C)
{
    extern __shared__ float sm[];
    gemm_body<2, 32>(A, nullptr, Bh, Bl, C, CDIM, CDIM, bias, 1, sm);
}

// ============================================================================
// x -> (hi, lo) tf32 split
// ============================================================================
__global__ void xsplit_kernel(const float* __restrict__ x, float* __restrict__ hi,
                              float* __restrict__ lo, int n4)
{
    int i = blockIdx.x * blockDim.x + threadIdx.x;
    if (i >= n4) return;
    float4 v = ((const float4*)x)[i];
    float4 h, l;
    h.x = tf32_rna(v.x); l.x = tf32_rna(v.x - h.x);
    h.y = tf32_rna(v.y); l.y = tf32_rna(v.y - h.y);
    h.z = tf32_rna(v.z); l.z = tf32_rna(v.z - h.z);
    h.w = tf32_rna(v.w); l.w = tf32_rna(v.w - h.w);
    ((float4*)hi)[i] = h;
    ((float4*)lo)[i] = l;
}

// ============================================================================
// weight transpose + tf32 split: in[K,N] -> ohi[N,K] + olo[N,K]
// ============================================================================
__global__ void wsplit_kernel(const float* __restrict__ in, float* __restrict__ ohi,
                              float* __restrict__ olo, int K, int N)
{
    __shared__ float t[32][33];
    const int n0 = blockIdx.x * 32, k0 = blockIdx.y * 32;
    const int tx = threadIdx.x, ty = threadIdx.y;
#pragma unroll
    for (int i = 0; i < 4; i++)
        t[ty + i * 8][tx] = in[(size_t)(k0 + ty + i * 8) * N + n0 + tx];
    __syncthreads();
#pragma unroll
    for (int i = 0; i < 4; i++) {
        float v = t[tx][ty + i * 8];
        float h = tf32_rna(v);
        ohi[(size_t)(n0 + ty + i * 8) * K + k0 + tx] = h;
        olo[(size_t)(n0 + ty + i * 8) * K + k0 + tx] = tf32_rna(v - h);
    }
}

// ============================================================================
// scores[bh][n] = sum_d q^2
// ============================================================================
__global__ void scores_kernel(const float* __restrict__ qkv, float* __restrict__ scores)
{
    int idx = blockIdx.x * blockDim.x + threadIdx.x;
    if (idx >= NBH * NTOK) return;
    int n  = idx & (NTOK - 1);
    int bh = idx >> 11;
    int h = bh % NH, b = bh / NH;
    const float4* q = (const float4*)(qkv + (size_t)(b * NTOK + n) * C3 + h * HD);
    float s = 0.f;
#pragma unroll
    for (int i = 0; i < 16; i++) {
        float4 v = q[i];
        s += v.x * v.x + v.y * v.y + v.z * v.z + v.w * v.w;
    }
    scores[idx] = s;
}

// ============================================================================
// Per-(b,h) top-KEEP via bitonic sort of packed u64 keys (set semantics).
// ============================================================================
__global__ __launch_bounds__(1024) void topk_kernel(
    const float* __restrict__ scores, int* __restrict__ keep)
{
    __shared__ unsigned long long keys[NTOK];
    const int bh = blockIdx.x, t = threadIdx.x;
    for (int i = t; i < NTOK; i += 1024) {
        unsigned sb = __float_as_uint(scores[bh * NTOK + i]);
        keys[i] = ((unsigned long long)sb << 32) | (unsigned)(NTOK - 1 - i);
    }
    for (int k = 2; k <= NTOK; k <<= 1) {
        for (int j = k >> 1; j > 0; j >>= 1) {
            __syncthreads();
            for (int i = t; i < NTOK; i += 1024) {
                int ixj = i ^ j;
                if (ixj > i) {
                    unsigned long long a = keys[i], c = keys[ixj];
                    bool asc = ((i & k) == 0);
                    if ((a > c) == asc) { keys[i] = c; keys[ixj] = a; }
                }
            }
        }
    }
    __syncthreads();
    if (t < KEEP) {
        keep[bh * KEEP + t] = (NTOK - 1) - (int)(keys[NTOK - KEEP + t] & 0xffffffffu);
    }
}

// ============================================================================
// Gather: K row-major [bh][j][d] (tf32-rounded), V transposed [bh][d][j]
// ============================================================================
__global__ __launch_bounds__(256) void gather_kernel(
    const float* __restrict__ qkv, const int* __restrict__ keep,
    float* __restrict__ ksel, float* __restrict__ vselT)
{
    __shared__ float tile[HD][65];
    const int bh = blockIdx.y, jc = blockIdx.x;
    const int b = bh / NH, h = bh % NH;
    const int t = threadIdx.x;

#pragma unroll
    for (int r = 0; r < 4; r++) {
        int idx = t + r * 256;
        int row = idx >> 4, f4 = (idx & 15) * 4;
        int kidx = keep[bh * KEEP + jc * 64 + row];
        const float* base = qkv + (size_t)(b * NTOK + kidx) * C3 + h * HD;
        float4 kv = *(const float4*)(base + CDIM + f4);
        kv.x = tf32_rna(kv.x); kv.y = tf32_rna(kv.y);
        kv.z = tf32_rna(kv.z); kv.w = tf32_rna(kv.w);
        *(float4*)(ksel + ((size_t)bh * KEEP + jc * 64 + row) * HD + f4) = kv;
        float4 vv = *(const float4*)(base + 2 * CDIM + f4);
        tile[f4 + 0][row] = tf32_rna(vv.x); tile[f4 + 1][row] = tf32_rna(vv.y);
        tile[f4 + 2][row] = tf32_rna(vv.z); tile[f4 + 3][row] = tf32_rna(vv.w);
    }
    __syncthreads();
#pragma unroll
    for (int r = 0; r < 4; r++) {
        int idx = t + r * 256;
        int d = idx >> 4, jf = (idx & 15) * 4;
        float4 v;
        v.x = tile[d][jf + 0]; v.y = tile[d][jf + 1];
        v.z = tile[d][jf + 2]; v.w = tile[d][jf + 3];
        *(float4*)(vselT + ((size_t)bh * HD + d) * KEEP + jc * 64 + jf) = v;
    }
}

// ============================================================================
// mma.sync attention: BQ=128 x key-chunks of 128. 8 warps (2m x 4n).
// No online max (|S|<=clip bound; sums can't overflow fp32).
// ============================================================================
__global__ __launch_bounds__(256, 1) void attn_mma(
    const float* __restrict__ qkv, const float* __restrict__ ksel,
    const float* __restrict__ vselT, float* __restrict__ out)
{
    extern __shared__ float sm[];
    float* Qs = sm;            // [128][64] xor-swizzled
    float* Ks = sm + 8192;     // [128][64] xor-swizzled
    float* Vs = sm + 16384;    // [64][128] xor-swizzled
    float* Pp = sm + 24576;    // [128][128] xor-swizzled
    float* Lr = sm + 40960;    // [4][128]

    const int tid = threadIdx.x, lane = tid & 31, wid = tid >> 5;
    const int g = lane >> 2, ct = lane & 3, g4 = g << 2;
    const int wm = wid & 1, wn = wid >> 1;
    const int bh = blockIdx.y, b = bh / NH, h = bh % NH;
    const int qbase = blockIdx.x * 128;

    {
        int j = tid & 127, half = tid >> 7;
        const float* qrow = qkv + (size_t)(b * NTOK + qbase + j) * C3 + h * HD + half * 32;
        const float QSC = 0.125f * 1.44269504f;
#pragma unroll
        for (int i = 0; i < 8; i++) {
            float4 v = *(const float4*)(qrow + i * 4);
            v.x = tf32_rna(v.x * QSC); v.y = tf32_rna(v.y * QSC);
            v.z = tf32_rna(v.z * QSC); v.w = tf32_rna(v.w * QSC);
            int c = half * 32 + i * 4;
            *(float4*)&Qs[j * 64 + (c ^ ((j & 7) << 2))] = v;
        }
    }

    float Oacc[4][2][4];
    float lp[4][2];
#pragma unroll
    for (int mt = 0; mt < 4; mt++) {
        lp[mt][0] = 0.f; lp[mt][1] = 0.f;
#pragma unroll
        for (int nt = 0; nt < 2; nt++)
#pragma unroll
            for (int i = 0; i < 4; i++) Oacc[mt][nt][i] = 0.f;
    }

    const float* kbase = ksel  + (size_t)bh * KEEP * HD;
    const float* vbase = vselT + (size_t)bh * HD * KEEP;

    for (int kc = 0; kc < KEEP / 128; kc++) {
        {
            int j = tid & 127, half = tid >> 7;
            const float* kr = kbase + (size_t)(kc * 128 + j) * HD + half * 32;
#pragma unroll
            for (int i = 0; i < 8; i++) {
                float4 v = *(const float4*)(kr + i * 4);
                int c = half * 32 + i * 4;
                *(float4*)&Ks[j * 64 + (c ^ ((j & 7) << 2))] = v;
            }
            int d = tid & 63, part = tid >> 6;
            const float* vr = vbase + (size_t)d * KEEP + kc * 128 + part * 32;
#pragma unroll
            for (int i = 0; i < 8; i++) {
                float4 v = *(const float4*)(vr + i * 4);
                int c = part * 32 + i * 4;
                *(float4*)&Vs[d * 128 + (c ^ ((d & 7) << 2))] = v;
            }
        }
        __syncthreads();

        float P[4][4][4];
#pragma unroll
        for (int mt = 0; mt < 4; mt++)
#pragma unroll
            for (int nt = 0; nt < 4; nt++)
#pragma unroll
                for (int i = 0; i < 4; i++) P[mt][nt][i] = 0.f;

#pragma unroll
        for (int ks = 0; ks < 8; ks++) {
            const int k0 = ks * 8 + ct, k1 = k0 + 4;
            uint32_t qa[4][4], kb[4][2];
#pragma unroll
            for (int mt = 0; mt < 4; mt++) {
                int r0 = (wm * 64 + mt * 16 + g) * 64, r1 = r0 + 8 * 64;
                qa[mt][0] = __float_as_uint(Qs[r0 + (k0 ^ g4)]);
                qa[mt][1] = __float_as_uint(Qs[r1 + (k0 ^ g4)]);
                qa[mt][2] = __float_as_uint(Qs[r0 + (k1 ^ g4)]);
                qa[mt][3] = __float_as_uint(Qs[r1 + (k1 ^ g4)]);
            }
#pragma unroll
            for (int nt = 0; nt < 4; nt++) {
                int n0 = (wn * 32 + nt * 8 + g) * 64;
                kb[nt][0] = __float_as_uint(Ks[n0 + (k0 ^ g4)]);
                kb[nt][1] = __float_as_uint(Ks[n0 + (k1 ^ g4)]);
            }
#pragma unroll
            for (int mt = 0; mt < 4; mt++)
#pragma unroll
                for (int nt = 0; nt < 4; nt++)
                    mma_tf32(P[mt][nt][0], P[mt][nt][1], P[mt][nt][2], P[mt][nt][3],
                             qa[mt][0], qa[mt][1], qa[mt][2], qa[mt][3],
                             kb[nt][0], kb[nt][1]);
        }

#pragma unroll
        for (int mt = 0; mt < 4; mt++) {
            int r0 = wm * 64 + mt * 16 + g;
#pragma unroll
            for (int nt = 0; nt < 4; nt++) {
                int c0 = wn * 32 + nt * 8 + 2 * ct;
                float p0 = pexp(P[mt][nt][0]);
                float p1 = pexp(P[mt][nt][1]);
                float p2 = pexp(P[mt][nt][2]);
                float p3 = pexp(P[mt][nt][3]);
                lp[mt][0] += p0 + p1;
                lp[mt][1] += p2 + p3;
                Pp[r0 * 128 + (c0 ^ g4)]           = p0;
                Pp[r0 * 128 + ((c0 + 1) ^ g4)]     = p1;
                Pp[(r0 + 8) * 128 + (c0 ^ g4)]       = p2;
                Pp[(r0 + 8) * 128 + ((c0 + 1) ^ g4)] = p3;
            }
        }
        __syncthreads();

#pragma unroll
        for (int ks = 0; ks < 16; ks++) {
            const int k0 = ks * 8 + ct, k1 = k0 + 4;
            uint32_t pa[4][4], vb[2][2];
#pragma unroll
            for (int mt = 0; mt < 4; mt++) {
                int r0 = (wm * 64 + mt * 16 + g) * 128, r1 = r0 + 8 * 128;
                pa[mt][0] = __float_as_uint(Pp[r0 + (k0 ^ g4)]);
                pa[mt][1] = __float_as_uint(Pp[r1 + (k0 ^ g4)]);
                pa[mt][2] = __float_as_uint(Pp[r0 + (k1 ^ g4)]);
                pa[mt][3] = __float_as_uint(Pp[r1 + (k1 ^ g4)]);
            }
#pragma unroll
            for (int nt = 0; nt < 2; nt++) {
                int d0 = (wn * 16 + nt * 8 + g) * 128;
                vb[nt][0] = __float_as_uint(Vs[d0 + (k0 ^ g4)]);
                vb[nt][1] = __float_as_uint(Vs[d0 + (k1 ^ g4)]);
            }
#pragma unroll
            for (int mt = 0; mt < 4; mt++)
#pragma unroll
                for (int nt = 0; nt < 2; nt++)
                    mma_tf32(Oacc[mt][nt][0], Oacc[mt][nt][1], Oacc[mt][nt][2], Oacc[mt][nt][3],
                             pa[mt][0], pa[mt][1], pa[mt][2], pa[mt][3],
                             vb[nt][0], vb[nt][1]);
        }
        __syncthreads();
    }

#pragma unroll
    for (int mt = 0; mt < 4; mt++)
#pragma unroll
        for (int hf = 0; hf < 2; hf++) {
            float v = lp[mt][hf];
            v += __shfl_xor_sync(0xffffffffu, v, 1);
            v += __shfl_xor_sync(0xffffffffu, v, 2);
            lp[mt][hf] = v;
        }
    if (ct == 0) {
#pragma unroll
        for (int mt = 0; mt < 4; mt++) {
            int r0 = wm * 64 + mt * 16 + g;
            Lr[wn * 128 + r0]     = lp[mt][0];
            Lr[wn * 128 + r0 + 8] = lp[mt][1];
        }
    }
    __syncthreads();
    float linv[4][2];
#pragma unroll
    for (int mt = 0; mt < 4; mt++)
#pragma unroll
        for (int hf = 0; hf < 2; hf++) {
            int r = wm * 64 + mt * 16 + g + hf * 8;
            linv[mt][hf] = 1.f / (Lr[r] + Lr[128 + r] + Lr[256 + r] + Lr[384 + r]);
        }

#pragma unroll
    for (int mt = 0; mt < 4; mt++) {
        int r0 = wm * 64 + mt * 16 + g;
#pragma unroll
        for (int nt = 0; nt < 2; nt++) {
            int d0 = wn * 16 + nt * 8 + 2 * ct;
            float2 a;
            a.x = tf32_rna(Oacc[mt][nt][0] * linv[mt][0]);
            a.y = tf32_rna(Oacc[mt][nt][1] * linv[mt][0]);
            *(float2*)&out[(size_t)(b * NTOK + qbase + r0) * CDIM + h * HD + d0] = a;
            float2 c;
            c.x = tf32_rna(Oacc[mt][nt][2] * linv[mt][1]);
            c.y = tf32_rna(Oacc[mt][nt][3] * linv[mt][1]);
            *(float2*)&out[(size_t)(b * NTOK + qbase + r0 + 8) * CDIM + h * HD + d0] = c;
        }
    }
}

// ============================================================================
// launch
// ============================================================================
extern "C" void kernel_launch(void* const* d_in, const int* in_sizes, int n_in,
                              void* d_out, int out_size)
{
    (void)in_sizes; (void)n_in; (void)out_size;
    const float* x      = (const float*)d_in[0];
    const float* w_qkv  = (const float*)d_in[1];
    const float* w_proj = (const float*)d_in[2];
    const float* b_proj = (const float*)d_in[3];
    float* out = (float*)d_out;

    float *qkv_p, *sc_p, *ks_p, *vT_p, *ao_p, *xhi_p, *xlo_p;
    float *wqh_p, *wql_p, *wph_p, *wpl_p;
    int* keep_p;
    cudaGetSymbolAddress((void**)&qkv_p,  g_qkv);
    cudaGetSymbolAddress((void**)&sc_p,   g_scores);
    cudaGetSymbolAddress((void**)&keep_p, g_keep);
    cudaGetSymbolAddress((void**)&ks_p,   g_ksel);
    cudaGetSymbolAddress((void**)&vT_p,   g_vselT);
    cudaGetSymbolAddress((void**)&ao_p,   g_attnout);
    cudaGetSymbolAddress((void**)&xhi_p,  g_xhi);
    cudaGetSymbolAddress((void**)&xlo_p,  g_xlo);
    cudaGetSymbolAddress((void**)&wqh_p,  g_wqT_hi);
    cudaGetSymbolAddress((void**)&wql_p,  g_wqT_lo);
    cudaGetSymbolAddress((void**)&wph_p,  g_wpT_hi);
    cudaGetSymbolAddress((void**)&wpl_p,  g_wpT_lo);

    // smem: qkv = 2 stages * 4 tiles * 128*20 floats = 81920 B
    //       proj = 2 stages * 3 tiles * 128*36 floats = 110592 B
    const int smem_qkv  = 2 * 4 * 128 * 20 * (int)sizeof(float);
    const int smem_proj = 2 * 3 * 128 * 36 * (int)sizeof(float);
    cudaFuncSetAttribute(qkv_gemm,  cudaFuncAttributeMaxDynamicSharedMemorySize, smem_qkv);
    cudaFuncSetAttribute(proj_gemm, cudaFuncAttributeMaxDynamicSharedMemorySize, smem_proj);
    const int attn_smem = (4 * 8192 + 8192 + 512) * (int)sizeof(float);
    cudaFuncSetAttribute(attn_mma, cudaFuncAttributeMaxDynamicSharedMemorySize, attn_smem);

    // 0) tf32 splits
    xsplit_kernel<<<(ROWS * CDIM / 4 + 255) / 256, 256>>>(x, xhi_p, xlo_p, ROWS * CDIM / 4);
    wsplit_kernel<<<dim3(C3 / 32, CDIM / 32), dim3(32, 8)>>>(w_qkv, wqh_p, wql_p, CDIM, C3);
    wsplit_kernel<<<dim3(CDIM / 32, CDIM / 32), dim3(32, 8)>>>(w_proj, wph_p, wpl_p, CDIM, CDIM);

    // 1) qkv = x @ w_qkv  (q 3-term, k/v 1-term, single launch, cp.async pipelined)
    qkv_gemm<<<dim3(C3 / 128, ROWS / 128), 256, smem_qkv>>>(
        xhi_p, xlo_p, wqh_p, wql_p, qkv_p);

    // 2) scores, 3) top-k, 4) gather
    scores_kernel<<<(NBH * NTOK + 255) / 256, 256>>>(qkv_p, sc_p);
    topk_kernel<<<NBH, 1024>>>(sc_p, keep_p);
    gather_kernel<<<dim3(KEEP / 64, NBH), 256>>>(qkv_p, keep_p, ks_p, vT_p);

    // 5) attention on tensor cores
    attn_mma<<<dim3(NTOK / 128, NBH), 256, attn_smem>>>(qkv_p, ks_p, vT_p, ao_p);

    // 6) out = clip(attnout @ w_proj + b_proj, -10, 10)  (2-term tf32, pipelined)
    proj_gemm<<<dim3(CDIM / 128, ROWS / 128), 256, smem_proj>>>(
        ao_p, wph_p, wpl_p, b_proj, out);
}

// round 7
// speedup vs baseline: 2.2115x; 1.0659x over previous
#include <cuda_runtime.h>
#include <math.h>
#include <cstdint>

#define NH    12
#define NTOK  2048
#define BATCH 4
#define CDIM  768
#define HD    64
#define KEEP  1024
#define ROWS  (BATCH*NTOK)   /* 8192 */
#define C3    (3*CDIM)       /* 2304 */
#define NBH   (BATCH*NH)     /* 48 */
#define CLIPV 72.134689f     /* 50 * log2(e) */

// ---- scratch (static device globals; no runtime allocation) ----
__device__ float g_qkv[(size_t)ROWS * C3];
__device__ float g_scores[NBH * NTOK];
__device__ int   g_keep[NBH * KEEP];
__device__ float g_ksel [(size_t)NBH * KEEP * HD];  // [bh][j][d] row-major, tf32
__device__ float g_vselT[(size_t)NBH * HD * KEEP];  // [bh][d][slot] transposed+slot-permuted
__device__ float g_attnout[(size_t)ROWS * CDIM];
__device__ float g_xhi[(size_t)ROWS * CDIM];
__device__ float g_xlo[(size_t)ROWS * CDIM];
__device__ float g_wqT_hi[(size_t)C3 * CDIM];   // w_qkv^T [2304][768]
__device__ float g_wqT_lo[(size_t)C3 * CDIM];
__device__ float g_wpT_hi[(size_t)CDIM * CDIM]; // w_proj^T [768][768]
__device__ float g_wpT_lo[(size_t)CDIM * CDIM];

__device__ __forceinline__ float tf32_rna(float a) {
    float r; asm("cvt.rna.tf32.f32 %0, %1;" : "=f"(r) : "f"(a)); return r;
}
__device__ __forceinline__ float pexp(float s) {
    s = fminf(fmaxf(s, -CLIPV), CLIPV);
    float r; asm("ex2.approx.ftz.f32 %0, %1;" : "=f"(r) : "f"(s)); return r;
}
__device__ __forceinline__ uint32_t smem_u32(const void* p) {
    uint32_t a;
    asm("{ .reg .u64 t; cvta.to.shared.u64 t, %1; cvt.u32.u64 %0, t; }" : "=r"(a) : "l"(p));
    return a;
}
__device__ __forceinline__ void cp16(uint32_t dst, const float* src) {
    size_t ga = __cvta_generic_to_global(src);
    asm volatile("cp.async.cg.shared.global [%0], [%1], 16;" :: "r"(dst), "l"(ga));
}
__device__ __forceinline__ void mma_tf32(float& c0, float& c1, float& c2, float& c3,
                                         uint32_t a0, uint32_t a1, uint32_t a2, uint32_t a3,
                                         uint32_t b0, uint32_t b1) {
    asm volatile("mma.sync.aligned.m16n8k8.row.col.f32.tf32.tf32.f32 "
        "{%0,%1,%2,%3}, {%4,%5,%6,%7}, {%8,%9}, {%0,%1,%2,%3};"
        : "+f"(c0), "+f"(c1), "+f"(c2), "+f"(c3)
        : "r"(a0), "r"(a1), "r"(a2), "r"(a3), "r"(b0), "r"(b1));
}

// ============================================================================
// cp.async double-buffered mma.sync tf32 GEMM body.
// C[M,N] = A[M,K] @ BT[N,K]^T, CTA tile 128x128, 8 warps (2m x 4n).
// TERMS=3: Ah*Bh + Ah*Bl + Al*Bh;  TERMS=2: Ah*(Bh+Bl);  TERMS=1: Ah*Bh.
// CH = K-chunk; smem row stride CH+4 (conflict-free fragment LDS).
// ============================================================================
template<int TERMS, int CH>
__device__ __forceinline__ void gemm_body(
    const float* __restrict__ Ahi, const float* __restrict__ Alo,
    const float* __restrict__ Bhi, const float* __restrict__ Blo,
    float* __restrict__ C, int K, int ldc,
    const float* __restrict__ bias, int do_clip, float* sm)
{
    constexpr int RS = CH + 4;
    constexpr int T  = 128 * RS;
    constexpr int NT = (TERMS == 3) ? 4 : (TERMS + 1);
    constexpr int SS = NT * T;

    const int tid = threadIdx.x, lane = tid & 31, wid = tid >> 5;
    const int g = lane >> 2, ct = lane & 3;
    const int wm = wid & 1, wn = wid >> 1;
    const int m0 = blockIdx.y * 128, n0 = blockIdx.x * 128;
    const int lrow = tid >> 1, lk0 = (tid & 1) * (CH / 2);

    float acc[4][4][4];
#pragma unroll
    for (int mt = 0; mt < 4; mt++)
#pragma unroll
        for (int nt = 0; nt < 4; nt++)
#pragma unroll
            for (int i = 0; i < 4; i++) acc[mt][nt][i] = 0.f;

    const float* agh = Ahi + (size_t)(m0 + lrow) * K + lk0;
    const float* bgh = Bhi + (size_t)(n0 + lrow) * K + lk0;
    const float* bgl = (TERMS >= 2) ? (Blo + (size_t)(n0 + lrow) * K + lk0) : nullptr;
    const float* agl = (TERMS == 3) ? (Alo + (size_t)(m0 + lrow) * K + lk0) : nullptr;

    const uint32_t sb0 = smem_u32(sm) + (uint32_t)((lrow * RS + lk0) * 4);
    const int NC = K / CH;

    auto issue = [&](int c) {
        const uint32_t sb = sb0 + (uint32_t)((c & 1) * SS * 4);
        const int k0 = c * CH;
#pragma unroll
        for (int i = 0; i < CH / 8; i++) {
            cp16(sb + i * 16,                    agh + k0 + i * 4);
            cp16(sb + (uint32_t)T * 4 + i * 16,  bgh + k0 + i * 4);
            if (TERMS >= 2) cp16(sb + 2u * T * 4 + i * 16, bgl + k0 + i * 4);
            if (TERMS == 3) cp16(sb + 3u * T * 4 + i * 16, agl + k0 + i * 4);
        }
        asm volatile("cp.async.commit_group;" ::: "memory");
    };

    issue(0);
    for (int c = 0; c < NC; c++) {
        if (c + 1 < NC) {
            issue(c + 1);
            asm volatile("cp.async.wait_group 1;" ::: "memory");
        } else {
            asm volatile("cp.async.wait_group 0;" ::: "memory");
        }
        __syncthreads();

        float* Ah = sm + (c & 1) * SS;
        float* Bh = Ah + T;
        float* Bl = Ah + 2 * T;
        float* Al = Ah + 3 * T;

#pragma unroll
        for (int ks = 0; ks < CH / 8; ks++) {
            const int kc = ks * 8 + ct;
            uint32_t afh[4][4], afl[4][4], bfh[4][2], bfl[4][2];
#pragma unroll
            for (int mt = 0; mt < 4; mt++) {
                int r = (wm * 64 + mt * 16 + g) * RS;
                afh[mt][0] = __float_as_uint(Ah[r + kc]);
                afh[mt][1] = __float_as_uint(Ah[r + 8 * RS + kc]);
                afh[mt][2] = __float_as_uint(Ah[r + kc + 4]);
                afh[mt][3] = __float_as_uint(Ah[r + 8 * RS + kc + 4]);
                if (TERMS == 3) {
                    afl[mt][0] = __float_as_uint(Al[r + kc]);
                    afl[mt][1] = __float_as_uint(Al[r + 8 * RS + kc]);
                    afl[mt][2] = __float_as_uint(Al[r + kc + 4]);
                    afl[mt][3] = __float_as_uint(Al[r + 8 * RS + kc + 4]);
                }
            }
#pragma unroll
            for (int nt = 0; nt < 4; nt++) {
                int r = (wn * 32 + nt * 8 + g) * RS;
                bfh[nt][0] = __float_as_uint(Bh[r + kc]);
                bfh[nt][1] = __float_as_uint(Bh[r + kc + 4]);
                if (TERMS >= 2) {
                    bfl[nt][0] = __float_as_uint(Bl[r + kc]);
                    bfl[nt][1] = __float_as_uint(Bl[r + kc + 4]);
                }
            }
#pragma unroll
            for (int mt = 0; mt < 4; mt++)
#pragma unroll
                for (int nt = 0; nt < 4; nt++) {
                    float* a = acc[mt][nt];
                    mma_tf32(a[0], a[1], a[2], a[3],
                             afh[mt][0], afh[mt][1], afh[mt][2], afh[mt][3],
                             bfh[nt][0], bfh[nt][1]);
                    if (TERMS >= 2)
                        mma_tf32(a[0], a[1], a[2], a[3],
                                 afh[mt][0], afh[mt][1], afh[mt][2], afh[mt][3],
                                 bfl[nt][0], bfl[nt][1]);
                    if (TERMS == 3)
                        mma_tf32(a[0], a[1], a[2], a[3],
                                 afl[mt][0], afl[mt][1], afl[mt][2], afl[mt][3],
                                 bfh[nt][0], bfh[nt][1]);
                }
        }
        __syncthreads();
    }

#pragma unroll
    for (int mt = 0; mt < 4; mt++) {
#pragma unroll
        for (int nt = 0; nt < 4; nt++) {
            int row = m0 + wm * 64 + mt * 16 + g;
            int col = n0 + wn * 32 + nt * 8 + ct * 2;
            float v0 = acc[mt][nt][0], v1 = acc[mt][nt][1];
            float v2 = acc[mt][nt][2], v3 = acc[mt][nt][3];
            if (bias) {
                float b0 = bias[col], b1 = bias[col + 1];
                v0 += b0; v1 += b1; v2 += b0; v3 += b1;
            }
            if (do_clip) {
                v0 = fminf(fmaxf(v0, -10.f), 10.f);
                v1 = fminf(fmaxf(v1, -10.f), 10.f);
                v2 = fminf(fmaxf(v2, -10.f), 10.f);
                v3 = fminf(fmaxf(v3, -10.f), 10.f);
            }
            float2 lo2; lo2.x = v0; lo2.y = v1;
            float2 hi2; hi2.x = v2; hi2.y = v3;
            *(float2*)(C + (size_t)row * ldc + col) = lo2;
            *(float2*)(C + (size_t)(row + 8) * ldc + col) = hi2;
        }
    }
}

// qkv in one launch: first 6 column-blocks (q) 3-term, rest (k,v) 1-term
__global__ __launch_bounds__(256, 2) void qkv_gemm(
    const float* __restrict__ xhi, const float* __restrict__ xlo,
    const float* __restrict__ wTh, const float* __restrict__ wTl,
    float* __restrict__ C)
{
    extern __shared__ float sm[];
    if (blockIdx.x * 128 < CDIM)
        gemm_body<3, 16>(xhi, xlo, wTh, wTl, C, CDIM, C3, nullptr, 0, sm);
    else
        gemm_body<1, 32>(xhi, nullptr, wTh, nullptr, C, CDIM, C3, nullptr, 0, sm);
}

__global__ __launch_bounds__(256, 2) void proj_gemm(
    const float* __restrict__ A, const float* __restrict__ Bh,
    const float* __restrict__ Bl, const float* __restrict__ bias,
    float* __restrict__ C)
{
    extern __shared__ float sm[];
    gemm_body<2, 16>(A, nullptr, Bh, Bl, C, CDIM, CDIM, bias, 1, sm);
}

// ============================================================================
// x -> (hi, lo) tf32 split
// ============================================================================
__global__ void xsplit_kernel(const float* __restrict__ x, float* __restrict__ hi,
                              float* __restrict__ lo, int n4)
{
    int i = blockIdx.x * blockDim.x + threadIdx.x;
    if (i >= n4) return;
    float4 v = ((const float4*)x)[i];
    float4 h, l;
    h.x = tf32_rna(v.x); l.x = tf32_rna(v.x - h.x);
    h.y = tf32_rna(v.y); l.y = tf32_rna(v.y - h.y);
    h.z = tf32_rna(v.z); l.z = tf32_rna(v.z - h.z);
    h.w = tf32_rna(v.w); l.w = tf32_rna(v.w - h.w);
    ((float4*)hi)[i] = h;
    ((float4*)lo)[i] = l;
}

// ============================================================================
// weight transpose + tf32 split: in[K,N] -> ohi[N,K] + olo[N,K]
// ============================================================================
__global__ void wsplit_kernel(const float* __restrict__ in, float* __restrict__ ohi,
                              float* __restrict__ olo, int K, int N)
{
    __shared__ float t[32][33];
    const int n0 = blockIdx.x * 32, k0 = blockIdx.y * 32;
    const int tx = threadIdx.x, ty = threadIdx.y;
#pragma unroll
    for (int i = 0; i < 4; i++)
        t[ty + i * 8][tx] = in[(size_t)(k0 + ty + i * 8) * N + n0 + tx];
    __syncthreads();
#pragma unroll
    for (int i = 0; i < 4; i++) {
        float v = t[tx][ty + i * 8];
        float h = tf32_rna(v);
        ohi[(size_t)(n0 + ty + i * 8) * K + k0 + tx] = h;
        olo[(size_t)(n0 + ty + i * 8) * K + k0 + tx] = tf32_rna(v - h);
    }
}

// ============================================================================
// scores[bh][n] = sum_d q^2
// ============================================================================
__global__ void scores_kernel(const float* __restrict__ qkv, float* __restrict__ scores)
{
    int idx = blockIdx.x * blockDim.x + threadIdx.x;
    if (idx >= NBH * NTOK) return;
    int n  = idx & (NTOK - 1);
    int bh = idx >> 11;
    int h = bh % NH, b = bh / NH;
    const float4* q = (const float4*)(qkv + (size_t)(b * NTOK + n) * C3 + h * HD);
    float s = 0.f;
#pragma unroll
    for (int i = 0; i < 16; i++) {
        float4 v = q[i];
        s += v.x * v.x + v.y * v.y + v.z * v.z + v.w * v.w;
    }
    scores[idx] = s;
}

// ============================================================================
// Per-(b,h) top-KEEP via bitonic sort of packed u64 keys (set semantics).
// ============================================================================
__global__ __launch_bounds__(1024) void topk_kernel(
    const float* __restrict__ scores, int* __restrict__ keep)
{
    __shared__ unsigned long long keys[NTOK];
    const int bh = blockIdx.x, t = threadIdx.x;
    for (int i = t; i < NTOK; i += 1024) {
        unsigned sb = __float_as_uint(scores[bh * NTOK + i]);
        keys[i] = ((unsigned long long)sb << 32) | (unsigned)(NTOK - 1 - i);
    }
    for (int k = 2; k <= NTOK; k <<= 1) {
        for (int j = k >> 1; j > 0; j >>= 1) {
            __syncthreads();
            for (int i = t; i < NTOK; i += 1024) {
                int ixj = i ^ j;
                if (ixj > i) {
                    unsigned long long a = keys[i], c = keys[ixj];
                    bool asc = ((i & k) == 0);
                    if ((a > c) == asc) { keys[i] = c; keys[ixj] = a; }
                }
            }
        }
    }
    __syncthreads();
    if (t < KEEP) {
        keep[bh * KEEP + t] = (NTOK - 1) - (int)(keys[NTOK - KEEP + t] & 0xffffffffu);
    }
}

// ============================================================================
// Gather: K row-major [bh][j][d] (tf32-rounded).
// V transposed [bh][d][slot], slot order per 8-group = [0,2,4,6,1,3,5,7] so
// that the S-mma C fragment (cols 2ct,2ct+1) can be fed directly as the
// PV-mma A operand (k-slots ct, ct+4) without cross-lane movement.
// ============================================================================
__global__ __launch_bounds__(256) void gather_kernel(
    const float* __restrict__ qkv, const int* __restrict__ keep,
    float* __restrict__ ksel, float* __restrict__ vselT)
{
    __shared__ float tile[HD][65];
    const int bh = blockIdx.y, jc = blockIdx.x;
    const int b = bh / NH, h = bh % NH;
    const int t = threadIdx.x;

#pragma unroll
    for (int r = 0; r < 4; r++) {
        int idx = t + r * 256;
        int row = idx >> 4, f4 = (idx & 15) * 4;
        int kidx = keep[bh * KEEP + jc * 64 + row];
        const float* base = qkv + (size_t)(b * NTOK + kidx) * C3 + h * HD;
        float4 kv = *(const float4*)(base + CDIM + f4);
        kv.x = tf32_rna(kv.x); kv.y = tf32_rna(kv.y);
        kv.z = tf32_rna(kv.z); kv.w = tf32_rna(kv.w);
        *(float4*)(ksel + ((size_t)bh * KEEP + jc * 64 + row) * HD + f4) = kv;
        float4 vv = *(const float4*)(base + 2 * CDIM + f4);
        tile[f4 + 0][row] = tf32_rna(vv.x); tile[f4 + 1][row] = tf32_rna(vv.y);
        tile[f4 + 2][row] = tf32_rna(vv.z); tile[f4 + 3][row] = tf32_rna(vv.w);
    }
    __syncthreads();
#pragma unroll
    for (int r = 0; r < 4; r++) {
        int idx = t + r * 256;
        int d = idx >> 4, jf = (idx & 15) * 4;   // slots jf..jf+3 (jf % 4 == 0)
        int jgrp = jf & ~7;
        int o = (jf & 4) ? 1 : 0;                // slot s -> key jgrp + 2*(s&3) + o
        float4 v;
        v.x = tile[d][jgrp + 0 + o]; v.y = tile[d][jgrp + 2 + o];
        v.z = tile[d][jgrp + 4 + o]; v.w = tile[d][jgrp + 6 + o];
        *(float4*)(vselT + ((size_t)bh * HD + d) * KEEP + jc * 64 + jf) = v;
    }
}

// ============================================================================
// mma.sync attention, warp-row-split: 8 warps x 16 query rows; each warp owns
// all 128 key-columns of its rows, so P stays in registers and feeds the PV
// mma directly (V pre-permuted per 8-group). No P smem, no cross-warp reduce.
// smem 96KB: Qs[128][64] | Ks[128][64] | Vs[64][128], all xor-swizzled.
// ============================================================================
__global__ __launch_bounds__(256, 2) void attn_mma(
    const float* __restrict__ qkv, const float* __restrict__ ksel,
    const float* __restrict__ vselT, float* __restrict__ out)
{
    extern __shared__ float sm[];
    float* Qs = sm;            // [128][64]
    float* Ks = sm + 8192;     // [128][64]
    float* Vs = sm + 16384;    // [64][128]

    const int tid = threadIdx.x, lane = tid & 31, wid = tid >> 5;
    const int g = lane >> 2, ct = lane & 3, g4 = g << 2;
    const int bh = blockIdx.y, b = bh / NH, h = bh % NH;
    const int qbase = blockIdx.x * 128;

    // load Q scaled by 0.125*log2(e), tf32-rounded, swizzled
    {
        int j = tid & 127, half = tid >> 7;
        const float* qrow = qkv + (size_t)(b * NTOK + qbase + j) * C3 + h * HD + half * 32;
        const float QSC = 0.125f * 1.44269504f;
#pragma unroll
        for (int i = 0; i < 8; i++) {
            float4 v = *(const float4*)(qrow + i * 4);
            v.x = tf32_rna(v.x * QSC); v.y = tf32_rna(v.y * QSC);
            v.z = tf32_rna(v.z * QSC); v.w = tf32_rna(v.w * QSC);
            int c = half * 32 + i * 4;
            *(float4*)&Qs[j * 64 + (c ^ ((j & 7) << 2))] = v;
        }
    }

    float P[16][4];
    float O[8][4];
    float lp0 = 0.f, lp1 = 0.f;
#pragma unroll
    for (int dt = 0; dt < 8; dt++)
#pragma unroll
        for (int i = 0; i < 4; i++) O[dt][i] = 0.f;

    const float* kbase = ksel  + (size_t)bh * KEEP * HD;
    const float* vbase = vselT + (size_t)bh * HD * KEEP;
    const int rq0 = (wid * 16 + g) * 64, rq1 = rq0 + 8 * 64;

    for (int kc = 0; kc < KEEP / 128; kc++) {
        // load K chunk [128][64] and V chunk [64][128] (pre-permuted slots)
        {
            int j = tid & 127, half = tid >> 7;
            const float* kr = kbase + (size_t)(kc * 128 + j) * HD + half * 32;
#pragma unroll
            for (int i = 0; i < 8; i++) {
                float4 v = *(const float4*)(kr + i * 4);
                int c = half * 32 + i * 4;
                *(float4*)&Ks[j * 64 + (c ^ ((j & 7) << 2))] = v;
            }
            int d = tid & 63, part = tid >> 6;
            const float* vr = vbase + (size_t)d * KEEP + kc * 128 + part * 32;
#pragma unroll
            for (int i = 0; i < 8; i++) {
                float4 v = *(const float4*)(vr + i * 4);
                int c = part * 32 + i * 4;
                *(float4*)&Vs[d * 128 + (c ^ ((d & 7) << 2))] = v;
            }
        }
        __syncthreads();

        // ---- S = (Q*scale) @ K^T : warp rows x 128 keys
#pragma unroll
        for (int nt = 0; nt < 16; nt++)
#pragma unroll
            for (int i = 0; i < 4; i++) P[nt][i] = 0.f;

#pragma unroll
        for (int ks = 0; ks < 8; ks++) {
            const int k0 = ks * 8 + ct, k1 = k0 + 4;
            uint32_t qa0 = __float_as_uint(Qs[rq0 + (k0 ^ g4)]);
            uint32_t qa1 = __float_as_uint(Qs[rq1 + (k0 ^ g4)]);
            uint32_t qa2 = __float_as_uint(Qs[rq0 + (k1 ^ g4)]);
            uint32_t qa3 = __float_as_uint(Qs[rq1 + (k1 ^ g4)]);
#pragma unroll
            for (int nt = 0; nt < 16; nt++) {
                int r = (nt * 8 + g) * 64;
                uint32_t kb0 = __float_as_uint(Ks[r + (k0 ^ g4)]);
                uint32_t kb1 = __float_as_uint(Ks[r + (k1 ^ g4)]);
                mma_tf32(P[nt][0], P[nt][1], P[nt][2], P[nt][3],
                         qa0, qa1, qa2, qa3, kb0, kb1);
            }
        }

        // ---- p = exp2(clip(s)); accumulate row sums (rows g and g+8)
#pragma unroll
        for (int nt = 0; nt < 16; nt++) {
            float p0 = pexp(P[nt][0]);
            float p1 = pexp(P[nt][1]);
            float p2 = pexp(P[nt][2]);
            float p3 = pexp(P[nt][3]);
            lp0 += p0 + p1;
            lp1 += p2 + p3;
            P[nt][0] = p0; P[nt][1] = p1; P[nt][2] = p2; P[nt][3] = p3;
        }

        // ---- O += P @ V  (P as A operand; V slot-permuted to match C layout)
#pragma unroll
        for (int ks = 0; ks < 16; ks++) {
            const int k0 = ks * 8 + ct, k1 = k0 + 4;
            uint32_t a0 = __float_as_uint(P[ks][0]);
            uint32_t a1 = __float_as_uint(P[ks][2]);
            uint32_t a2 = __float_as_uint(P[ks][1]);
            uint32_t a3 = __float_as_uint(P[ks][3]);
#pragma unroll
            for (int dt = 0; dt < 8; dt++) {
                int r = (dt * 8 + g) * 128;
                uint32_t vb0 = __float_as_uint(Vs[r + (k0 ^ g4)]);
                uint32_t vb1 = __float_as_uint(Vs[r + (k1 ^ g4)]);
                mma_tf32(O[dt][0], O[dt][1], O[dt][2], O[dt][3],
                         a0, a1, a2, a3, vb0, vb1);
            }
        }
        __syncthreads();   // protect Ks/Vs before next chunk's loads
    }

    // ---- row sums: quad allreduce (lanes sharing a row differ in bits 0,1)
    lp0 += __shfl_xor_sync(0xffffffffu, lp0, 1);
    lp0 += __shfl_xor_sync(0xffffffffu, lp0, 2);
    lp1 += __shfl_xor_sync(0xffffffffu, lp1, 1);
    lp1 += __shfl_xor_sync(0xffffffffu, lp1, 2);
    const float li0 = 1.f / lp0, li1 = 1.f / lp1;

    // ---- write O (tf32-rounded for the proj GEMM)
    const int row0 = qbase + wid * 16 + g;
#pragma unroll
    for (int dt = 0; dt < 8; dt++) {
        int d0 = dt * 8 + 2 * ct;
        float2 a;
        a.x = tf32_rna(O[dt][0] * li0);
        a.y = tf32_rna(O[dt][1] * li0);
        *(float2*)&out[(size_t)(b * NTOK + row0) * CDIM + h * HD + d0] = a;
        float2 c;
        c.x = tf32_rna(O[dt][2] * li1);
        c.y = tf32_rna(O[dt][3] * li1);
        *(float2*)&out[(size_t)(b * NTOK + row0 + 8) * CDIM + h * HD + d0] = c;
    }
}

// ============================================================================
// launch
// ============================================================================
extern "C" void kernel_launch(void* const* d_in, const int* in_sizes, int n_in,
                              void* d_out, int out_size)
{
    (void)in_sizes; (void)n_in; (void)out_size;
    const float* x      = (const float*)d_in[0];
    const float* w_qkv  = (const float*)d_in[1];
    const float* w_proj = (const float*)d_in[2];
    const float* b_proj = (const float*)d_in[3];
    float* out = (float*)d_out;

    float *qkv_p, *sc_p, *ks_p, *vT_p, *ao_p, *xhi_p, *xlo_p;
    float *wqh_p, *wql_p, *wph_p, *wpl_p;
    int* keep_p;
    cudaGetSymbolAddress((void**)&qkv_p,  g_qkv);
    cudaGetSymbolAddress((void**)&sc_p,   g_scores);
    cudaGetSymbolAddress((void**)&keep_p, g_keep);
    cudaGetSymbolAddress((void**)&ks_p,   g_ksel);
    cudaGetSymbolAddress((void**)&vT_p,   g_vselT);
    cudaGetSymbolAddress((void**)&ao_p,   g_attnout);
    cudaGetSymbolAddress((void**)&xhi_p,  g_xhi);
    cudaGetSymbolAddress((void**)&xlo_p,  g_xlo);
    cudaGetSymbolAddress((void**)&wqh_p,  g_wqT_hi);
    cudaGetSymbolAddress((void**)&wql_p,  g_wqT_lo);
    cudaGetSymbolAddress((void**)&wph_p,  g_wpT_hi);
    cudaGetSymbolAddress((void**)&wpl_p,  g_wpT_lo);

    // qkv: max(3-term CH16: 2*4*128*20, 1-term CH32: 2*2*128*36) floats
    const int smem_qkv  = 2 * 4 * 128 * 20 * (int)sizeof(float);  // 81920
    const int smem_proj = 2 * 3 * 128 * 20 * (int)sizeof(float);  // 61440
    cudaFuncSetAttribute(qkv_gemm,  cudaFuncAttributeMaxDynamicSharedMemorySize, smem_qkv);
    cudaFuncSetAttribute(proj_gemm, cudaFuncAttributeMaxDynamicSharedMemorySize, smem_proj);
    const int attn_smem = 3 * 8192 * (int)sizeof(float);          // 98304
    cudaFuncSetAttribute(attn_mma, cudaFuncAttributeMaxDynamicSharedMemorySize, attn_smem);

    // 0) tf32 splits
    xsplit_kernel<<<(ROWS * CDIM / 4 + 255) / 256, 256>>>(x, xhi_p, xlo_p, ROWS * CDIM / 4);
    wsplit_kernel<<<dim3(C3 / 32, CDIM / 32), dim3(32, 8)>>>(w_qkv, wqh_p, wql_p, CDIM, C3);
    wsplit_kernel<<<dim3(CDIM / 32, CDIM / 32), dim3(32, 8)>>>(w_proj, wph_p, wpl_p, CDIM, CDIM);

    // 1) qkv = x @ w_qkv  (q 3-term, k/v 1-term, cp.async pipelined, 2 CTA/SM)
    qkv_gemm<<<dim3(C3 / 128, ROWS / 128), 256, smem_qkv>>>(
        xhi_p, xlo_p, wqh_p, wql_p, qkv_p);

    // 2) scores, 3) top-k, 4) gather (V slot-permuted)
    scores_kernel<<<(NBH * NTOK + 255) / 256, 256>>>(qkv_p, sc_p);
    topk_kernel<<<NBH, 1024>>>(sc_p, keep_p);
    gather_kernel<<<dim3(KEEP / 64, NBH), 256>>>(qkv_p, keep_p, ks_p, vT_p);

    // 5) attention on tensor cores (P in registers, 2 CTA/SM)
    attn_mma<<<dim3(NTOK / 128, NBH), 256, attn_smem>>>(qkv_p, ks_p, vT_p, ao_p);

    // 6) out = clip(attnout @ w_proj + b_proj, -10, 10)  (2-term tf32)
    proj_gemm<<<dim3(CDIM / 128, ROWS / 128), 256, smem_proj>>>(
        ao_p, wph_p, wpl_p, b_proj, out);
}

// round 8
// speedup vs baseline: 2.3015x; 1.0407x over previous
#include <cuda_runtime.h>
#include <math.h>
#include <cstdint>

#define NH    12
#define NTOK  2048
#define BATCH 4
#define CDIM  768
#define HD    64
#define KEEP  1024
#define ROWS  (BATCH*NTOK)   /* 8192 */
#define C3    (3*CDIM)       /* 2304 */
#define NBH   (BATCH*NH)     /* 48 */
#define CLIPV 72.134689f     /* 50 * log2(e) */

// ---- scratch (static device globals; no runtime allocation) ----
__device__ float g_qkv[(size_t)ROWS * C3];
__device__ float g_scores[NBH * NTOK];
__device__ int   g_keep[NBH * KEEP];
__device__ float g_ksel [(size_t)NBH * KEEP * HD];  // [bh][j][d] row-major, tf32
__device__ float g_vselT[(size_t)NBH * HD * KEEP];  // [bh][d][slot] transposed+slot-permuted
__device__ float g_attnout[(size_t)ROWS * CDIM];
__device__ float g_xhi[(size_t)ROWS * CDIM];
__device__ float g_xlo[(size_t)ROWS * CDIM];
__device__ float g_wqT_hi[(size_t)C3 * CDIM];   // w_qkv^T [2304][768]
__device__ float g_wqT_lo[(size_t)C3 * CDIM];
__device__ float g_wpT_hi[(size_t)CDIM * CDIM]; // w_proj^T [768][768]
__device__ float g_wpT_lo[(size_t)CDIM * CDIM];

__device__ __forceinline__ float tf32_rna(float a) {
    float r; asm("cvt.rna.tf32.f32 %0, %1;" : "=f"(r) : "f"(a)); return r;
}
__device__ __forceinline__ float pexp(float s) {
    s = fminf(fmaxf(s, -CLIPV), CLIPV);
    float r; asm("ex2.approx.ftz.f32 %0, %1;" : "=f"(r) : "f"(s)); return r;
}
__device__ __forceinline__ uint32_t smem_u32(const void* p) {
    uint32_t a;
    asm("{ .reg .u64 t; cvta.to.shared.u64 t, %1; cvt.u32.u64 %0, t; }" : "=r"(a) : "l"(p));
    return a;
}
__device__ __forceinline__ void cp16(uint32_t dst, const float* src) {
    size_t ga = __cvta_generic_to_global(src);
    asm volatile("cp.async.cg.shared.global [%0], [%1], 16;" :: "r"(dst), "l"(ga));
}
__device__ __forceinline__ void mma_tf32(float& c0, float& c1, float& c2, float& c3,
                                         uint32_t a0, uint32_t a1, uint32_t a2, uint32_t a3,
                                         uint32_t b0, uint32_t b1) {
    asm volatile("mma.sync.aligned.m16n8k8.row.col.f32.tf32.tf32.f32 "
        "{%0,%1,%2,%3}, {%4,%5,%6,%7}, {%8,%9}, {%0,%1,%2,%3};"
        : "+f"(c0), "+f"(c1), "+f"(c2), "+f"(c3)
        : "r"(a0), "r"(a1), "r"(a2), "r"(a3), "r"(b0), "r"(b1));
}

// ============================================================================
// 3-stage cp.async mma.sync tf32 GEMM body, xor-swizzled smem (no padding).
// C[M,N] = A[M,K] @ BT[N,K]^T, CTA tile 128x128, 8 warps (2m x 4n).
// TERMS=3: Ah*Bh + Ah*Bl + Al*Bh;  TERMS=2: Ah*(Bh+Bl);  TERMS=1: Ah*Bh.
// Swizzle: col-group gg ^= (row>>1)&3 (CH16) or row&7 (CH32); verified
// conflict-free for both cp.async stores and fragment LDS.
// Mainloop order: wait_group(1) -> bar -> issue(c+2) -> compute(c): one
// barrier per chunk, ~2 compute phases of latency cover.
// ============================================================================
template<int TERMS, int CH>
__device__ __forceinline__ void gemm_body(
    const float* __restrict__ Ahi, const float* __restrict__ Alo,
    const float* __restrict__ Bhi, const float* __restrict__ Blo,
    float* __restrict__ C, int K, int ldc,
    const float* __restrict__ bias, int do_clip, float* sm)
{
    constexpr int STAGES = 3;
    constexpr int T  = 128 * CH;                       // floats per tile
    constexpr int NT = (TERMS == 3) ? 4 : (TERMS + 1); // tiles per stage
    constexpr int SS = NT * T;
    constexpr int GPR = CH / 4;                        // 4-float groups per row
    constexpr int GPT = 128 * GPR / 256;               // groups per thread per tile

    const int tid = threadIdx.x, lane = tid & 31, wid = tid >> 5;
    const int g = lane >> 2, ct = lane & 3;
    const int wm = wid & 1, wn = wid >> 1;
    const int m0 = blockIdx.y * 128, n0 = blockIdx.x * 128;

    auto sidx = [](int row, int kc) {
        int swz = (CH == 16) ? ((row >> 1) & 3) : (row & 7);
        return row * CH + ((((kc >> 2) ^ swz) << 2) | (kc & 3));
    };

    float acc[4][4][4];
#pragma unroll
    for (int mt = 0; mt < 4; mt++)
#pragma unroll
        for (int nt = 0; nt < 4; nt++)
#pragma unroll
            for (int i = 0; i < 4; i++) acc[mt][nt][i] = 0.f;

    const uint32_t smb = smem_u32(sm);
    const int NC = K / CH;

    auto issue = [&](int c) {
        const uint32_t sb = smb + (uint32_t)((c % STAGES) * SS * 4);
        const int k0 = c * CH;
#pragma unroll
        for (int j = 0; j < GPT; j++) {
            int gidx = tid + j * 256;
            int row = gidx / GPR, gg = gidx & (GPR - 1);
            int swz = (CH == 16) ? ((row >> 1) & 3) : (row & 7);
            uint32_t off = (uint32_t)((row * CH + ((gg ^ swz) << 2)) * 4);
            int gk = k0 + gg * 4;
            cp16(sb + off,              Ahi + (size_t)(m0 + row) * K + gk);
            cp16(sb + (uint32_t)T * 4 + off, Bhi + (size_t)(n0 + row) * K + gk);
            if (TERMS >= 2)
                cp16(sb + 2u * T * 4 + off, Blo + (size_t)(n0 + row) * K + gk);
            if (TERMS == 3)
                cp16(sb + 3u * T * 4 + off, Alo + (size_t)(m0 + row) * K + gk);
        }
        asm volatile("cp.async.commit_group;" ::: "memory");
    };

    issue(0);
    issue(1);

    for (int c = 0; c < NC; c++) {
        asm volatile("cp.async.wait_group %0;" :: "n"(STAGES - 2));
        __syncthreads();
        if (c + STAGES - 1 < NC) issue(c + STAGES - 1);

        float* Ah = sm + (c % STAGES) * SS;
        float* Bh = Ah + T;
        float* Bl = Ah + 2 * T;
        float* Al = Ah + 3 * T;

#pragma unroll
        for (int ks = 0; ks < CH / 8; ks++) {
            const int kc = ks * 8 + ct;
            uint32_t afh[4][4], afl[4][4], bfh[4][2], bfl[4][2];
#pragma unroll
            for (int mt = 0; mt < 4; mt++) {
                int r0 = wm * 64 + mt * 16 + g;
                afh[mt][0] = __float_as_uint(Ah[sidx(r0,     kc)]);
                afh[mt][1] = __float_as_uint(Ah[sidx(r0 + 8, kc)]);
                afh[mt][2] = __float_as_uint(Ah[sidx(r0,     kc + 4)]);
                afh[mt][3] = __float_as_uint(Ah[sidx(r0 + 8, kc + 4)]);
                if (TERMS == 3) {
                    afl[mt][0] = __float_as_uint(Al[sidx(r0,     kc)]);
                    afl[mt][1] = __float_as_uint(Al[sidx(r0 + 8, kc)]);
                    afl[mt][2] = __float_as_uint(Al[sidx(r0,     kc + 4)]);
                    afl[mt][3] = __float_as_uint(Al[sidx(r0 + 8, kc + 4)]);
                }
            }
#pragma unroll
            for (int nt = 0; nt < 4; nt++) {
                int r = wn * 32 + nt * 8 + g;
                bfh[nt][0] = __float_as_uint(Bh[sidx(r, kc)]);
                bfh[nt][1] = __float_as_uint(Bh[sidx(r, kc + 4)]);
                if (TERMS >= 2) {
                    bfl[nt][0] = __float_as_uint(Bl[sidx(r, kc)]);
                    bfl[nt][1] = __float_as_uint(Bl[sidx(r, kc + 4)]);
                }
            }
#pragma unroll
            for (int mt = 0; mt < 4; mt++)
#pragma unroll
                for (int nt = 0; nt < 4; nt++) {
                    float* a = acc[mt][nt];
                    mma_tf32(a[0], a[1], a[2], a[3],
                             afh[mt][0], afh[mt][1], afh[mt][2], afh[mt][3],
                             bfh[nt][0], bfh[nt][1]);
                    if (TERMS >= 2)
                        mma_tf32(a[0], a[1], a[2], a[3],
                                 afh[mt][0], afh[mt][1], afh[mt][2], afh[mt][3],
                                 bfl[nt][0], bfl[nt][1]);
                    if (TERMS == 3)
                        mma_tf32(a[0], a[1], a[2], a[3],
                                 afl[mt][0], afl[mt][1], afl[mt][2], afl[mt][3],
                                 bfh[nt][0], bfh[nt][1]);
                }
        }
    }

#pragma unroll
    for (int mt = 0; mt < 4; mt++) {
#pragma unroll
        for (int nt = 0; nt < 4; nt++) {
            int row = m0 + wm * 64 + mt * 16 + g;
            int col = n0 + wn * 32 + nt * 8 + ct * 2;
            float v0 = acc[mt][nt][0], v1 = acc[mt][nt][1];
            float v2 = acc[mt][nt][2], v3 = acc[mt][nt][3];
            if (bias) {
                float b0 = bias[col], b1 = bias[col + 1];
                v0 += b0; v1 += b1; v2 += b0; v3 += b1;
            }
            if (do_clip) {
                v0 = fminf(fmaxf(v0, -10.f), 10.f);
                v1 = fminf(fmaxf(v1, -10.f), 10.f);
                v2 = fminf(fmaxf(v2, -10.f), 10.f);
                v3 = fminf(fmaxf(v3, -10.f), 10.f);
            }
            float2 lo2; lo2.x = v0; lo2.y = v1;
            float2 hi2; hi2.x = v2; hi2.y = v3;
            *(float2*)(C + (size_t)row * ldc + col) = lo2;
            *(float2*)(C + (size_t)(row + 8) * ldc + col) = hi2;
        }
    }
}

// qkv in one launch: first 6 column-blocks (q) 3-term, rest (k,v) 1-term
__global__ __launch_bounds__(256, 2) void qkv_gemm(
    const float* __restrict__ xhi, const float* __restrict__ xlo,
    const float* __restrict__ wTh, const float* __restrict__ wTl,
    float* __restrict__ C)
{
    extern __shared__ float sm[];
    if (blockIdx.x * 128 < CDIM)
        gemm_body<3, 16>(xhi, xlo, wTh, wTl, C, CDIM, C3, nullptr, 0, sm);
    else
        gemm_body<1, 32>(xhi, nullptr, wTh, nullptr, C, CDIM, C3, nullptr, 0, sm);
}

__global__ __launch_bounds__(256, 2) void proj_gemm(
    const float* __restrict__ A, const float* __restrict__ Bh,
    const float* __restrict__ Bl, const float* __restrict__ bias,
    float* __restrict__ C)
{
    extern __shared__ float sm[];
    gemm_body<2, 16>(A, nullptr, Bh, Bl, C, CDIM, CDIM, bias, 1, sm);
}

// ============================================================================
// x -> (hi, lo) tf32 split
// ============================================================================
__global__ void xsplit_kernel(const float* __restrict__ x, float* __restrict__ hi,
                              float* __restrict__ lo, int n4)
{
    int i = blockIdx.x * blockDim.x + threadIdx.x;
    if (i >= n4) return;
    float4 v = ((const float4*)x)[i];
    float4 h, l;
    h.x = tf32_rna(v.x); l.x = tf32_rna(v.x - h.x);
    h.y = tf32_rna(v.y); l.y = tf32_rna(v.y - h.y);
    h.z = tf32_rna(v.z); l.z = tf32_rna(v.z - h.z);
    h.w = tf32_rna(v.w); l.w = tf32_rna(v.w - h.w);
    ((float4*)hi)[i] = h;
    ((float4*)lo)[i] = l;
}

// ============================================================================
// weight transpose + tf32 split: in[K,N] -> ohi[N,K] + olo[N,K]
// ============================================================================
__global__ void wsplit_kernel(const float* __restrict__ in, float* __restrict__ ohi,
                              float* __restrict__ olo, int K, int N)
{
    __shared__ float t[32][33];
    const int n0 = blockIdx.x * 32, k0 = blockIdx.y * 32;
    const int tx = threadIdx.x, ty = threadIdx.y;
#pragma unroll
    for (int i = 0; i < 4; i++)
        t[ty + i * 8][tx] = in[(size_t)(k0 + ty + i * 8) * N + n0 + tx];
    __syncthreads();
#pragma unroll
    for (int i = 0; i < 4; i++) {
        float v = t[tx][ty + i * 8];
        float h = tf32_rna(v);
        ohi[(size_t)(n0 + ty + i * 8) * K + k0 + tx] = h;
        olo[(size_t)(n0 + ty + i * 8) * K + k0 + tx] = tf32_rna(v - h);
    }
}

// ============================================================================
// scores[bh][n] = sum_d q^2
// ============================================================================
__global__ void scores_kernel(const float* __restrict__ qkv, float* __restrict__ scores)
{
    int idx = blockIdx.x * blockDim.x + threadIdx.x;
    if (idx >= NBH * NTOK) return;
    int n  = idx & (NTOK - 1);
    int bh = idx >> 11;
    int h = bh % NH, b = bh / NH;
    const float4* q = (const float4*)(qkv + (size_t)(b * NTOK + n) * C3 + h * HD);
    float s = 0.f;
#pragma unroll
    for (int i = 0; i < 16; i++) {
        float4 v = q[i];
        s += v.x * v.x + v.y * v.y + v.z * v.z + v.w * v.w;
    }
    scores[idx] = s;
}

// ============================================================================
// Per-(b,h) top-KEEP via bitonic sort of packed u64 keys (set semantics).
// ============================================================================
__global__ __launch_bounds__(1024) void topk_kernel(
    const float* __restrict__ scores, int* __restrict__ keep)
{
    __shared__ unsigned long long keys[NTOK];
    const int bh = blockIdx.x, t = threadIdx.x;
    for (int i = t; i < NTOK; i += 1024) {
        unsigned sb = __float_as_uint(scores[bh * NTOK + i]);
        keys[i] = ((unsigned long long)sb << 32) | (unsigned)(NTOK - 1 - i);
    }
    for (int k = 2; k <= NTOK; k <<= 1) {
        for (int j = k >> 1; j > 0; j >>= 1) {
            __syncthreads();
            for (int i = t; i < NTOK; i += 1024) {
                int ixj = i ^ j;
                if (ixj > i) {
                    unsigned long long a = keys[i], c = keys[ixj];
                    bool asc = ((i & k) == 0);
                    if ((a > c) == asc) { keys[i] = c; keys[ixj] = a; }
                }
            }
        }
    }
    __syncthreads();
    if (t < KEEP) {
        keep[bh * KEEP + t] = (NTOK - 1) - (int)(keys[NTOK - KEEP + t] & 0xffffffffu);
    }
}

// ============================================================================
// Gather: K row-major [bh][j][d] (tf32-rounded).
// V transposed [bh][d][slot], slot order per 8-group = [0,2,4,6,1,3,5,7] so
// the S-mma C fragment feeds the PV-mma A operand directly.
// ============================================================================
__global__ __launch_bounds__(256) void gather_kernel(
    const float* __restrict__ qkv, const int* __restrict__ keep,
    float* __restrict__ ksel, float* __restrict__ vselT)
{
    __shared__ float tile[HD][65];
    const int bh = blockIdx.y, jc = blockIdx.x;
    const int b = bh / NH, h = bh % NH;
    const int t = threadIdx.x;

#pragma unroll
    for (int r = 0; r < 4; r++) {
        int idx = t + r * 256;
        int row = idx >> 4, f4 = (idx & 15) * 4;
        int kidx = keep[bh * KEEP + jc * 64 + row];
        const float* base = qkv + (size_t)(b * NTOK + kidx) * C3 + h * HD;
        float4 kv = *(const float4*)(base + CDIM + f4);
        kv.x = tf32_rna(kv.x); kv.y = tf32_rna(kv.y);
        kv.z = tf32_rna(kv.z); kv.w = tf32_rna(kv.w);
        *(float4*)(ksel + ((size_t)bh * KEEP + jc * 64 + row) * HD + f4) = kv;
        float4 vv = *(const float4*)(base + 2 * CDIM + f4);
        tile[f4 + 0][row] = tf32_rna(vv.x); tile[f4 + 1][row] = tf32_rna(vv.y);
        tile[f4 + 2][row] = tf32_rna(vv.z); tile[f4 + 3][row] = tf32_rna(vv.w);
    }
    __syncthreads();
#pragma unroll
    for (int r = 0; r < 4; r++) {
        int idx = t + r * 256;
        int d = idx >> 4, jf = (idx & 15) * 4;
        int jgrp = jf & ~7;
        int o = (jf & 4) ? 1 : 0;
        float4 v;
        v.x = tile[d][jgrp + 0 + o]; v.y = tile[d][jgrp + 2 + o];
        v.z = tile[d][jgrp + 4 + o]; v.w = tile[d][jgrp + 6 + o];
        *(float4*)(vselT + ((size_t)bh * HD + d) * KEEP + jc * 64 + jf) = v;
    }
}

// ============================================================================
// mma.sync attention, warp-row-split: 8 warps x 16 query rows; P stays in
// registers and feeds the PV mma directly (V pre-permuted per 8-group).
// smem 96KB: Qs[128][64] | Ks[128][64] | Vs[64][128], all xor-swizzled.
// ============================================================================
__global__ __launch_bounds__(256, 2) void attn_mma(
    const float* __restrict__ qkv, const float* __restrict__ ksel,
    const float* __restrict__ vselT, float* __restrict__ out)
{
    extern __shared__ float sm[];
    float* Qs = sm;            // [128][64]
    float* Ks = sm + 8192;     // [128][64]
    float* Vs = sm + 16384;    // [64][128]

    const int tid = threadIdx.x, lane = tid & 31, wid = tid >> 5;
    const int g = lane >> 2, ct = lane & 3, g4 = g << 2;
    const int bh = blockIdx.y, b = bh / NH, h = bh % NH;
    const int qbase = blockIdx.x * 128;

    {
        int j = tid & 127, half = tid >> 7;
        const float* qrow = qkv + (size_t)(b * NTOK + qbase + j) * C3 + h * HD + half * 32;
        const float QSC = 0.125f * 1.44269504f;
#pragma unroll
        for (int i = 0; i < 8; i++) {
            float4 v = *(const float4*)(qrow + i * 4);
            v.x = tf32_rna(v.x * QSC); v.y = tf32_rna(v.y * QSC);
            v.z = tf32_rna(v.z * QSC); v.w = tf32_rna(v.w * QSC);
            int c = half * 32 + i * 4;
            *(float4*)&Qs[j * 64 + (c ^ ((j & 7) << 2))] = v;
        }
    }

    float P[16][4];
    float O[8][4];
    float lp0 = 0.f, lp1 = 0.f;
#pragma unroll
    for (int dt = 0; dt < 8; dt++)
#pragma unroll
        for (int i = 0; i < 4; i++) O[dt][i] = 0.f;

    const float* kbase = ksel  + (size_t)bh * KEEP * HD;
    const float* vbase = vselT + (size_t)bh * HD * KEEP;
    const int rq0 = (wid * 16 + g) * 64, rq1 = rq0 + 8 * 64;

    for (int kc = 0; kc < KEEP / 128; kc++) {
        {
            int j = tid & 127, half = tid >> 7;
            const float* kr = kbase + (size_t)(kc * 128 + j) * HD + half * 32;
#pragma unroll
            for (int i = 0; i < 8; i++) {
                float4 v = *(const float4*)(kr + i * 4);
                int c = half * 32 + i * 4;
                *(float4*)&Ks[j * 64 + (c ^ ((j & 7) << 2))] = v;
            }
            int d = tid & 63, part = tid >> 6;
            const float* vr = vbase + (size_t)d * KEEP + kc * 128 + part * 32;
#pragma unroll
            for (int i = 0; i < 8; i++) {
                float4 v = *(const float4*)(vr + i * 4);
                int c = part * 32 + i * 4;
                *(float4*)&Vs[d * 128 + (c ^ ((d & 7) << 2))] = v;
            }
        }
        __syncthreads();

#pragma unroll
        for (int nt = 0; nt < 16; nt++)
#pragma unroll
            for (int i = 0; i < 4; i++) P[nt][i] = 0.f;

#pragma unroll
        for (int ks = 0; ks < 8; ks++) {
            const int k0 = ks * 8 + ct, k1 = k0 + 4;
            uint32_t qa0 = __float_as_uint(Qs[rq0 + (k0 ^ g4)]);
            uint32_t qa1 = __float_as_uint(Qs[rq1 + (k0 ^ g4)]);
            uint32_t qa2 = __float_as_uint(Qs[rq0 + (k1 ^ g4)]);
            uint32_t qa3 = __float_as_uint(Qs[rq1 + (k1 ^ g4)]);
#pragma unroll
            for (int nt = 0; nt < 16; nt++) {
                int r = (nt * 8 + g) * 64;
                uint32_t kb0 = __float_as_uint(Ks[r + (k0 ^ g4)]);
                uint32_t kb1 = __float_as_uint(Ks[r + (k1 ^ g4)]);
                mma_tf32(P[nt][0], P[nt][1], P[nt][2], P[nt][3],
                         qa0, qa1, qa2, qa3, kb0, kb1);
            }
        }

#pragma unroll
        for (int nt = 0; nt < 16; nt++) {
            float p0 = pexp(P[nt][0]);
            float p1 = pexp(P[nt][1]);
            float p2 = pexp(P[nt][2]);
            float p3 = pexp(P[nt][3]);
            lp0 += p0 + p1;
            lp1 += p2 + p3;
            P[nt][0] = p0; P[nt][1] = p1; P[nt][2] = p2; P[nt][3] = p3;
        }

#pragma unroll
        for (int ks = 0; ks < 16; ks++) {
            const int k0 = ks * 8 + ct, k1 = k0 + 4;
            uint32_t a0 = __float_as_uint(P[ks][0]);
            uint32_t a1 = __float_as_uint(P[ks][2]);
            uint32_t a2 = __float_as_uint(P[ks][1]);
            uint32_t a3 = __float_as_uint(P[ks][3]);
#pragma unroll
            for (int dt = 0; dt < 8; dt++) {
                int r = (dt * 8 + g) * 128;
                uint32_t vb0 = __float_as_uint(Vs[r + (k0 ^ g4)]);
                uint32_t vb1 = __float_as_uint(Vs[r + (k1 ^ g4)]);
                mma_tf32(O[dt][0], O[dt][1], O[dt][2], O[dt][3],
                         a0, a1, a2, a3, vb0, vb1);
            }
        }
        __syncthreads();
    }

    lp0 += __shfl_xor_sync(0xffffffffu, lp0, 1);
    lp0 += __shfl_xor_sync(0xffffffffu, lp0, 2);
    lp1 += __shfl_xor_sync(0xffffffffu, lp1, 1);
    lp1 += __shfl_xor_sync(0xffffffffu, lp1, 2);
    const float li0 = 1.f / lp0, li1 = 1.f / lp1;

    const int row0 = qbase + wid * 16 + g;
#pragma unroll
    for (int dt = 0; dt < 8; dt++) {
        int d0 = dt * 8 + 2 * ct;
        float2 a;
        a.x = tf32_rna(O[dt][0] * li0);
        a.y = tf32_rna(O[dt][1] * li0);
        *(float2*)&out[(size_t)(b * NTOK + row0) * CDIM + h * HD + d0] = a;
        float2 c;
        c.x = tf32_rna(O[dt][2] * li1);
        c.y = tf32_rna(O[dt][3] * li1);
        *(float2*)&out[(size_t)(b * NTOK + row0 + 8) * CDIM + h * HD + d0] = c;
    }
}

// ============================================================================
// launch
// ============================================================================
extern "C" void kernel_launch(void* const* d_in, const int* in_sizes, int n_in,
                              void* d_out, int out_size)
{
    (void)in_sizes; (void)n_in; (void)out_size;
    const float* x      = (const float*)d_in[0];
    const float* w_qkv  = (const float*)d_in[1];
    const float* w_proj = (const float*)d_in[2];
    const float* b_proj = (const float*)d_in[3];
    float* out = (float*)d_out;

    float *qkv_p, *sc_p, *ks_p, *vT_p, *ao_p, *xhi_p, *xlo_p;
    float *wqh_p, *wql_p, *wph_p, *wpl_p;
    int* keep_p;
    cudaGetSymbolAddress((void**)&qkv_p,  g_qkv);
    cudaGetSymbolAddress((void**)&sc_p,   g_scores);
    cudaGetSymbolAddress((void**)&keep_p, g_keep);
    cudaGetSymbolAddress((void**)&ks_p,   g_ksel);
    cudaGetSymbolAddress((void**)&vT_p,   g_vselT);
    cudaGetSymbolAddress((void**)&ao_p,   g_attnout);
    cudaGetSymbolAddress((void**)&xhi_p,  g_xhi);
    cudaGetSymbolAddress((void**)&xlo_p,  g_xlo);
    cudaGetSymbolAddress((void**)&wqh_p,  g_wqT_hi);
    cudaGetSymbolAddress((void**)&wql_p,  g_wqT_lo);
    cudaGetSymbolAddress((void**)&wph_p,  g_wpT_hi);
    cudaGetSymbolAddress((void**)&wpl_p,  g_wpT_lo);

    // 3 stages, swizzled (no pad):
    //   qkv  : max(3-term CH16: 4*128*16, 1-term CH32: 2*128*32) = 8192 fl/stage
    //   proj : 2-term CH16: 3*128*16 = 6144 fl/stage
    const int smem_qkv  = 3 * 8192 * (int)sizeof(float);   // 98304
    const int smem_proj = 3 * 6144 * (int)sizeof(float);   // 73728
    cudaFuncSetAttribute(qkv_gemm,  cudaFuncAttributeMaxDynamicSharedMemorySize, smem_qkv);
    cudaFuncSetAttribute(proj_gemm, cudaFuncAttributeMaxDynamicSharedMemorySize, smem_proj);
    const int attn_smem = 3 * 8192 * (int)sizeof(float);   // 98304
    cudaFuncSetAttribute(attn_mma, cudaFuncAttributeMaxDynamicSharedMemorySize, attn_smem);

    // 0) tf32 splits
    xsplit_kernel<<<(ROWS * CDIM / 4 + 255) / 256, 256>>>(x, xhi_p, xlo_p, ROWS * CDIM / 4);
    wsplit_kernel<<<dim3(C3 / 32, CDIM / 32), dim3(32, 8)>>>(w_qkv, wqh_p, wql_p, CDIM, C3);
    wsplit_kernel<<<dim3(CDIM / 32, CDIM / 32), dim3(32, 8)>>>(w_proj, wph_p, wpl_p, CDIM, CDIM);

    // 1) qkv = x @ w_qkv  (q 3-term, k/v 1-term, 3-stage cp.async, 2 CTA/SM)
    qkv_gemm<<<dim3(C3 / 128, ROWS / 128), 256, smem_qkv>>>(
        xhi_p, xlo_p, wqh_p, wql_p, qkv_p);

    // 2) scores, 3) top-k, 4) gather (V slot-permuted)
    scores_kernel<<<(NBH * NTOK + 255) / 256, 256>>>(qkv_p, sc_p);
    topk_kernel<<<NBH, 1024>>>(sc_p, keep_p);
    gather_kernel<<<dim3(KEEP / 64, NBH), 256>>>(qkv_p, keep_p, ks_p, vT_p);

    // 5) attention on tensor cores (P in registers, 2 CTA/SM)
    attn_mma<<<dim3(NTOK / 128, NBH), 256, attn_smem>>>(qkv_p, ks_p, vT_p, ao_p);

    // 6) out = clip(attnout @ w_proj + b_proj, -10, 10)  (2-term tf32, 3-stage)
    proj_gemm<<<dim3(CDIM / 128, ROWS / 128), 256, smem_proj>>>(
        ao_p, wph_p, wpl_p, b_proj, out);
}

// round 9
// speedup vs baseline: 2.8149x; 1.2230x over previous
#include <cuda_runtime.h>
#include <math.h>
#include <cstdint>

#define NH    12
#define NTOK  2048
#define BATCH 4
#define CDIM  768
#define HD    64
#define KEEP  1024
#define ROWS  (BATCH*NTOK)   /* 8192 */
#define C3    (3*CDIM)       /* 2304 */
#define NBH   (BATCH*NH)     /* 48 */
#define CLIPV 72.134689f     /* 50 * log2(e) */

// ---- scratch (static device globals; no runtime allocation) ----
__device__ float g_qkv[(size_t)ROWS * C3];
__device__ float g_scores[NBH * NTOK];
__device__ int   g_keep[NBH * KEEP];
__device__ float g_ksel [(size_t)NBH * KEEP * HD];  // [bh][j][d] row-major, tf32
__device__ float g_vselT[(size_t)NBH * HD * KEEP];  // [bh][d][slot] transposed+slot-permuted
__device__ float g_attnout[(size_t)ROWS * CDIM];
__device__ float g_xhi[(size_t)ROWS * CDIM];
__device__ float g_xlo[(size_t)ROWS * CDIM];
__device__ float g_wqT_hi[(size_t)C3 * CDIM];   // w_qkv^T [2304][768]
__device__ float g_wqT_lo[(size_t)C3 * CDIM];
__device__ float g_wpT_hi[(size_t)CDIM * CDIM]; // w_proj^T [768][768]
__device__ float g_wpT_lo[(size_t)CDIM * CDIM];

__device__ __forceinline__ float tf32_rna(float a) {
    float r; asm("cvt.rna.tf32.f32 %0, %1;" : "=f"(r) : "f"(a)); return r;
}
__device__ __forceinline__ float pexp(float s) {
    s = fminf(fmaxf(s, -CLIPV), CLIPV);
    float r; asm("ex2.approx.ftz.f32 %0, %1;" : "=f"(r) : "f"(s)); return r;
}
__device__ __forceinline__ uint32_t smem_u32(const void* p) {
    uint32_t a;
    asm("{ .reg .u64 t; cvta.to.shared.u64 t, %1; cvt.u32.u64 %0, t; }" : "=r"(a) : "l"(p));
    return a;
}
__device__ __forceinline__ void cp16(uint32_t dst, const float* src) {
    size_t ga = __cvta_generic_to_global(src);
    asm volatile("cp.async.cg.shared.global [%0], [%1], 16;" :: "r"(dst), "l"(ga));
}
__device__ __forceinline__ void mma_tf32(float& c0, float& c1, float& c2, float& c3,
                                         uint32_t a0, uint32_t a1, uint32_t a2, uint32_t a3,
                                         uint32_t b0, uint32_t b1) {
    asm volatile("mma.sync.aligned.m16n8k8.row.col.f32.tf32.tf32.f32 "
        "{%0,%1,%2,%3}, {%4,%5,%6,%7}, {%8,%9}, {%0,%1,%2,%3};"
        : "+f"(c0), "+f"(c1), "+f"(c2), "+f"(c3)
        : "r"(a0), "r"(a1), "r"(a2), "r"(a3), "r"(b0), "r"(b1));
}
// ldmatrix x4 on 16B rows of fp32 data (b16 view): lane l <- elem l%4 of row l/4
#define LDSM4(r0_, r1_, r2_, r3_, addr_) \
    asm volatile("ldmatrix.sync.aligned.m8n8.x4.shared.b16 {%0,%1,%2,%3}, [%4];" \
        : "=r"(r0_), "=r"(r1_), "=r"(r2_), "=r"(r3_) : "r"(addr_))

// ============================================================================
// 3-stage cp.async mma.sync tf32 GEMM body, xor-swizzled smem, ldmatrix feeds.
// C[M,N] = A[M,K] @ BT[N,K]^T, CTA tile 128x128, 8 warps (2m x 4n).
// TERMS=3: Ah*Bh + Ah*Bl + Al*Bh;  TERMS=2: Ah*(Bh+Bl);  TERMS=1: Ah*Bh.
// ============================================================================
template<int TERMS, int CH>
__device__ __forceinline__ void gemm_body(
    const float* __restrict__ Ahi, const float* __restrict__ Alo,
    const float* __restrict__ Bhi, const float* __restrict__ Blo,
    float* __restrict__ C, int K, int ldc,
    const float* __restrict__ bias, int do_clip, float* sm)
{
    constexpr int STAGES = 3;
    constexpr int T  = 128 * CH;                       // floats per tile
    constexpr int NT = (TERMS == 3) ? 4 : (TERMS + 1); // tiles per stage
    constexpr int SS = NT * T;
    constexpr int GPR = CH / 4;
    constexpr int GPT = 128 * GPR / 256;

    const int tid = threadIdx.x, lane = tid & 31, wid = tid >> 5;
    const int g = lane >> 2, ct = lane & 3;
    const int wm = wid & 1, wn = wid >> 1;
    const int m0 = blockIdx.y * 128, n0 = blockIdx.x * 128;

    // ldmatrix lane geometry (A-frag: blocks {r,+8} x {klo,khi}; B: {nt,nt+1} x {klo,khi})
    const int ao = ((lane >> 3) & 1) * 8 + (lane & 7);
    const int ak = lane >> 4;
    const int bo = (lane >> 4) * 8 + (lane & 7);
    const int bk = (lane >> 3) & 1;
    const int swzA = (CH == 16) ? ((ao >> 1) & 3) : (ao & 7);
    const int swzB = (CH == 16) ? ((bo >> 1) & 3) : (bo & 7);

    float acc[4][4][4];
#pragma unroll
    for (int mt = 0; mt < 4; mt++)
#pragma unroll
        for (int nt = 0; nt < 4; nt++)
#pragma unroll
            for (int i = 0; i < 4; i++) acc[mt][nt][i] = 0.f;

    const uint32_t smb = smem_u32(sm);
    const int NC = K / CH;

    auto issue = [&](int c) {
        const uint32_t sb = smb + (uint32_t)((c % STAGES) * SS * 4);
        const int k0 = c * CH;
#pragma unroll
        for (int j = 0; j < GPT; j++) {
            int gidx = tid + j * 256;
            int row = gidx / GPR, gg = gidx & (GPR - 1);
            int swz = (CH == 16) ? ((row >> 1) & 3) : (row & 7);
            uint32_t off = (uint32_t)((row * CH + ((gg ^ swz) << 2)) * 4);
            int gk = k0 + gg * 4;
            cp16(sb + off,                   Ahi + (size_t)(m0 + row) * K + gk);
            cp16(sb + (uint32_t)T * 4 + off, Bhi + (size_t)(n0 + row) * K + gk);
            if (TERMS >= 2)
                cp16(sb + 2u * T * 4 + off, Blo + (size_t)(n0 + row) * K + gk);
            if (TERMS == 3)
                cp16(sb + 3u * T * 4 + off, Alo + (size_t)(m0 + row) * K + gk);
        }
        asm volatile("cp.async.commit_group;" ::: "memory");
    };

    issue(0);
    issue(1);

    for (int c = 0; c < NC; c++) {
        asm volatile("cp.async.wait_group %0;" :: "n"(STAGES - 2));
        __syncthreads();
        if (c + STAGES - 1 < NC) issue(c + STAGES - 1);

        const uint32_t stb = smb + (uint32_t)((c % STAGES) * SS * 4);
        uint32_t aAh[4], aAl[4], aBh[2], aBl[2];
#pragma unroll
        for (int mt = 0; mt < 4; mt++) {
            int row = wm * 64 + mt * 16 + ao;
            aAh[mt] = stb + (uint32_t)(row * CH * 4);
            if (TERMS == 3) aAl[mt] = aAh[mt] + 3u * T * 4;
        }
#pragma unroll
        for (int ntp = 0; ntp < 2; ntp++) {
            int row = wn * 32 + ntp * 16 + bo;
            aBh[ntp] = stb + (uint32_t)(T * 4 + row * CH * 4);
            if (TERMS >= 2) aBl[ntp] = aBh[ntp] + (uint32_t)(T * 4);
        }

#pragma unroll
        for (int ks = 0; ks < CH / 8; ks++) {
            const uint32_t offA = (uint32_t)(((2 * ks + ak) ^ swzA) << 4);
            const uint32_t offB = (uint32_t)(((2 * ks + bk) ^ swzB) << 4);
            uint32_t afh[4][4], afl[4][4], bfh[4][2], bfl[4][2];
#pragma unroll
            for (int mt = 0; mt < 4; mt++) {
                LDSM4(afh[mt][0], afh[mt][1], afh[mt][2], afh[mt][3], aAh[mt] + offA);
                if (TERMS == 3)
                    LDSM4(afl[mt][0], afl[mt][1], afl[mt][2], afl[mt][3], aAl[mt] + offA);
            }
            LDSM4(bfh[0][0], bfh[0][1], bfh[1][0], bfh[1][1], aBh[0] + offB);
            LDSM4(bfh[2][0], bfh[2][1], bfh[3][0], bfh[3][1], aBh[1] + offB);
            if (TERMS >= 2) {
                LDSM4(bfl[0][0], bfl[0][1], bfl[1][0], bfl[1][1], aBl[0] + offB);
                LDSM4(bfl[2][0], bfl[2][1], bfl[3][0], bfl[3][1], aBl[1] + offB);
            }
#pragma unroll
            for (int mt = 0; mt < 4; mt++)
#pragma unroll
                for (int nt = 0; nt < 4; nt++) {
                    float* a = acc[mt][nt];
                    mma_tf32(a[0], a[1], a[2], a[3],
                             afh[mt][0], afh[mt][1], afh[mt][2], afh[mt][3],
                             bfh[nt][0], bfh[nt][1]);
                    if (TERMS >= 2)
                        mma_tf32(a[0], a[1], a[2], a[3],
                                 afh[mt][0], afh[mt][1], afh[mt][2], afh[mt][3],
                                 bfl[nt][0], bfl[nt][1]);
                    if (TERMS == 3)
                        mma_tf32(a[0], a[1], a[2], a[3],
                                 afl[mt][0], afl[mt][1], afl[mt][2], afl[mt][3],
                                 bfh[nt][0], bfh[nt][1]);
                }
        }
    }

#pragma unroll
    for (int mt = 0; mt < 4; mt++) {
#pragma unroll
        for (int nt = 0; nt < 4; nt++) {
            int row = m0 + wm * 64 + mt * 16 + g;
            int col = n0 + wn * 32 + nt * 8 + ct * 2;
            float v0 = acc[mt][nt][0], v1 = acc[mt][nt][1];
            float v2 = acc[mt][nt][2], v3 = acc[mt][nt][3];
            if (bias) {
                float b0 = bias[col], b1 = bias[col + 1];
                v0 += b0; v1 += b1; v2 += b0; v3 += b1;
            }
            if (do_clip) {
                v0 = fminf(fmaxf(v0, -10.f), 10.f);
                v1 = fminf(fmaxf(v1, -10.f), 10.f);
                v2 = fminf(fmaxf(v2, -10.f), 10.f);
                v3 = fminf(fmaxf(v3, -10.f), 10.f);
            }
            float2 lo2; lo2.x = v0; lo2.y = v1;
            float2 hi2; hi2.x = v2; hi2.y = v3;
            *(float2*)(C + (size_t)row * ldc + col) = lo2;
            *(float2*)(C + (size_t)(row + 8) * ldc + col) = hi2;
        }
    }
}

// qkv in one launch: first 6 column-blocks (q) 3-term, rest (k,v) 1-term
__global__ __launch_bounds__(256, 2) void qkv_gemm(
    const float* __restrict__ xhi, const float* __restrict__ xlo,
    const float* __restrict__ wTh, const float* __restrict__ wTl,
    float* __restrict__ C)
{
    extern __shared__ float sm[];
    if (blockIdx.x * 128 < CDIM)
        gemm_body<3, 16>(xhi, xlo, wTh, wTl, C, CDIM, C3, nullptr, 0, sm);
    else
        gemm_body<1, 32>(xhi, nullptr, wTh, nullptr, C, CDIM, C3, nullptr, 0, sm);
}

__global__ __launch_bounds__(256, 2) void proj_gemm(
    const float* __restrict__ A, const float* __restrict__ Bh,
    const float* __restrict__ Bl, const float* __restrict__ bias,
    float* __restrict__ C)
{
    extern __shared__ float sm[];
    gemm_body<2, 16>(A, nullptr, Bh, Bl, C, CDIM, CDIM, bias, 1, sm);
}

// ============================================================================
// x -> (hi, lo) tf32 split
// ============================================================================
__global__ void xsplit_kernel(const float* __restrict__ x, float* __restrict__ hi,
                              float* __restrict__ lo, int n4)
{
    int i = blockIdx.x * blockDim.x + threadIdx.x;
    if (i >= n4) return;
    float4 v = ((const float4*)x)[i];
    float4 h, l;
    h.x = tf32_rna(v.x); l.x = tf32_rna(v.x - h.x);
    h.y = tf32_rna(v.y); l.y = tf32_rna(v.y - h.y);
    h.z = tf32_rna(v.z); l.z = tf32_rna(v.z - h.z);
    h.w = tf32_rna(v.w); l.w = tf32_rna(v.w - h.w);
    ((float4*)hi)[i] = h;
    ((float4*)lo)[i] = l;
}

// ============================================================================
// weight transpose + tf32 split: in[K,N] -> ohi[N,K] + olo[N,K]
// ============================================================================
__global__ void wsplit_kernel(const float* __restrict__ in, float* __restrict__ ohi,
                              float* __restrict__ olo, int K, int N)
{
    __shared__ float t[32][33];
    const int n0 = blockIdx.x * 32, k0 = blockIdx.y * 32;
    const int tx = threadIdx.x, ty = threadIdx.y;
#pragma unroll
    for (int i = 0; i < 4; i++)
        t[ty + i * 8][tx] = in[(size_t)(k0 + ty + i * 8) * N + n0 + tx];
    __syncthreads();
#pragma unroll
    for (int i = 0; i < 4; i++) {
        float v = t[tx][ty + i * 8];
        float h = tf32_rna(v);
        ohi[(size_t)(n0 + ty + i * 8) * K + k0 + tx] = h;
        olo[(size_t)(n0 + ty + i * 8) * K + k0 + tx] = tf32_rna(v - h);
    }
}

// ============================================================================
// scores[bh][n] = sum_d q^2
// ============================================================================
__global__ void scores_kernel(const float* __restrict__ qkv, float* __restrict__ scores)
{
    int idx = blockIdx.x * blockDim.x + threadIdx.x;
    if (idx >= NBH * NTOK) return;
    int n  = idx & (NTOK - 1);
    int bh = idx >> 11;
    int h = bh % NH, b = bh / NH;
    const float4* q = (const float4*)(qkv + (size_t)(b * NTOK + n) * C3 + h * HD);
    float s = 0.f;
#pragma unroll
    for (int i = 0; i < 16; i++) {
        float4 v = q[i];
        s += v.x * v.x + v.y * v.y + v.z * v.z + v.w * v.w;
    }
    scores[idx] = s;
}

// ============================================================================
// Per-(b,h) top-KEEP via bitonic sort of packed u64 keys (set semantics).
// ============================================================================
__global__ __launch_bounds__(1024) void topk_kernel(
    const float* __restrict__ scores, int* __restrict__ keep)
{
    __shared__ unsigned long long keys[NTOK];
    const int bh = blockIdx.x, t = threadIdx.x;
    for (int i = t; i < NTOK; i += 1024) {
        unsigned sb = __float_as_uint(scores[bh * NTOK + i]);
        keys[i] = ((unsigned long long)sb << 32) | (unsigned)(NTOK - 1 - i);
    }
    for (int k = 2; k <= NTOK; k <<= 1) {
        for (int j = k >> 1; j > 0; j >>= 1) {
            __syncthreads();
            for (int i = t; i < NTOK; i += 1024) {
                int ixj = i ^ j;
                if (ixj > i) {
                    unsigned long long a = keys[i], c = keys[ixj];
                    bool asc = ((i & k) == 0);
                    if ((a > c) == asc) { keys[i] = c; keys[ixj] = a; }
                }
            }
        }
    }
    __syncthreads();
    if (t < KEEP) {
        keep[bh * KEEP + t] = (NTOK - 1) - (int)(keys[NTOK - KEEP + t] & 0xffffffffu);
    }
}

// ============================================================================
// Gather: K row-major [bh][j][d] (tf32-rounded).
// V transposed [bh][d][slot], slot order per 8-group = [0,2,4,6,1,3,5,7] so
// the S-mma C fragment feeds the PV-mma A operand directly.
// ============================================================================
__global__ __launch_bounds__(256) void gather_kernel(
    const float* __restrict__ qkv, const int* __restrict__ keep,
    float* __restrict__ ksel, float* __restrict__ vselT)
{
    __shared__ float tile[HD][65];
    const int bh = blockIdx.y, jc = blockIdx.x;
    const int b = bh / NH, h = bh % NH;
    const int t = threadIdx.x;

#pragma unroll
    for (int r = 0; r < 4; r++) {
        int idx = t + r * 256;
        int row = idx >> 4, f4 = (idx & 15) * 4;
        int kidx = keep[bh * KEEP + jc * 64 + row];
        const float* base = qkv + (size_t)(b * NTOK + kidx) * C3 + h * HD;
        float4 kv = *(const float4*)(base + CDIM + f4);
        kv.x = tf32_rna(kv.x); kv.y = tf32_rna(kv.y);
        kv.z = tf32_rna(kv.z); kv.w = tf32_rna(kv.w);
        *(float4*)(ksel + ((size_t)bh * KEEP + jc * 64 + row) * HD + f4) = kv;
        float4 vv = *(const float4*)(base + 2 * CDIM + f4);
        tile[f4 + 0][row] = tf32_rna(vv.x); tile[f4 + 1][row] = tf32_rna(vv.y);
        tile[f4 + 2][row] = tf32_rna(vv.z); tile[f4 + 3][row] = tf32_rna(vv.w);
    }
    __syncthreads();
#pragma unroll
    for (int r = 0; r < 4; r++) {
        int idx = t + r * 256;
        int d = idx >> 4, jf = (idx & 15) * 4;
        int jgrp = jf & ~7;
        int o = (jf & 4) ? 1 : 0;
        float4 v;
        v.x = tile[d][jgrp + 0 + o]; v.y = tile[d][jgrp + 2 + o];
        v.z = tile[d][jgrp + 4 + o]; v.w = tile[d][jgrp + 6 + o];
        *(float4*)(vselT + ((size_t)bh * HD + d) * KEEP + jc * 64 + jf) = v;
    }
}

// ============================================================================
// mma.sync attention, warp-row-split, ldmatrix feeds: 8 warps x 16 query rows;
// P stays in registers and feeds the PV mma directly (V pre-permuted).
// smem 96KB: Qs[128][64] | Ks[128][64] | Vs[64][128], all xor-swizzled.
// ============================================================================
__global__ __launch_bounds__(256, 2) void attn_mma(
    const float* __restrict__ qkv, const float* __restrict__ ksel,
    const float* __restrict__ vselT, float* __restrict__ out)
{
    extern __shared__ float sm[];
    float* Qs = sm;            // [128][64]
    float* Ks = sm + 8192;     // [128][64]
    float* Vs = sm + 16384;    // [64][128]

    const int tid = threadIdx.x, lane = tid & 31, wid = tid >> 5;
    const int g = lane >> 2, ct = lane & 3;
    const int bh = blockIdx.y, b = bh / NH, h = bh % NH;
    const int qbase = blockIdx.x * 128;

    // ldmatrix lane geometry
    const int ao = ((lane >> 3) & 1) * 8 + (lane & 7);
    const int ak = lane >> 4;
    const int bo = (lane >> 4) * 8 + (lane & 7);
    const int bk = (lane >> 3) & 1;
    const int swzq = ao & 7;
    const int swzb = bo & 7;

    {
        int j = tid & 127, half = tid >> 7;
        const float* qrow = qkv + (size_t)(b * NTOK + qbase + j) * C3 + h * HD + half * 32;
        const float QSC = 0.125f * 1.44269504f;
#pragma unroll
        for (int i = 0; i < 8; i++) {
            float4 v = *(const float4*)(qrow + i * 4);
            v.x = tf32_rna(v.x * QSC); v.y = tf32_rna(v.y * QSC);
            v.z = tf32_rna(v.z * QSC); v.w = tf32_rna(v.w * QSC);
            int c = half * 32 + i * 4;
            *(float4*)&Qs[j * 64 + (c ^ ((j & 7) << 2))] = v;
        }
    }

    // loop-invariant ldmatrix row bases
    const uint32_t qa_base = smem_u32(Qs) + (uint32_t)((wid * 16 + ao) * 64 * 4);
    uint32_t kb_base[8], vb_base[4];
#pragma unroll
    for (int ntp = 0; ntp < 8; ntp++)
        kb_base[ntp] = smem_u32(Ks) + (uint32_t)((ntp * 16 + bo) * 64 * 4);
#pragma unroll
    for (int dtp = 0; dtp < 4; dtp++)
        vb_base[dtp] = smem_u32(Vs) + (uint32_t)((dtp * 16 + bo) * 128 * 4);

    float P[16][4];
    float O[8][4];
    float lp0 = 0.f, lp1 = 0.f;
#pragma unroll
    for (int dt = 0; dt < 8; dt++)
#pragma unroll
        for (int i = 0; i < 4; i++) O[dt][i] = 0.f;

    const float* kbase = ksel  + (size_t)bh * KEEP * HD;
    const float* vbase = vselT + (size_t)bh * HD * KEEP;

    for (int kc = 0; kc < KEEP / 128; kc++) {
        {
            int j = tid & 127, half = tid >> 7;
            const float* kr = kbase + (size_t)(kc * 128 + j) * HD + half * 32;
#pragma unroll
            for (int i = 0; i < 8; i++) {
                float4 v = *(const float4*)(kr + i * 4);
                int c = half * 32 + i * 4;
                *(float4*)&Ks[j * 64 + (c ^ ((j & 7) << 2))] = v;
            }
            int d = tid & 63, part = tid >> 6;
            const float* vr = vbase + (size_t)d * KEEP + kc * 128 + part * 32;
#pragma unroll
            for (int i = 0; i < 8; i++) {
                float4 v = *(const float4*)(vr + i * 4);
                int c = part * 32 + i * 4;
                *(float4*)&Vs[d * 128 + (c ^ ((d & 7) << 2))] = v;
            }
        }
        __syncthreads();

        // ---- S = (Q*scale) @ K^T
#pragma unroll
        for (int nt = 0; nt < 16; nt++)
#pragma unroll
            for (int i = 0; i < 4; i++) P[nt][i] = 0.f;

#pragma unroll
        for (int ks = 0; ks < 8; ks++) {
            const uint32_t offq = (uint32_t)(((2 * ks + ak) ^ swzq) << 4);
            const uint32_t offb = (uint32_t)(((2 * ks + bk) ^ swzb) << 4);
            uint32_t qa0, qa1, qa2, qa3;
            LDSM4(qa0, qa1, qa2, qa3, qa_base + offq);
#pragma unroll
            for (int ntp = 0; ntp < 8; ntp++) {
                uint32_t k00, k01, k10, k11;
                LDSM4(k00, k01, k10, k11, kb_base[ntp] + offb);
                mma_tf32(P[2 * ntp][0], P[2 * ntp][1], P[2 * ntp][2], P[2 * ntp][3],
                         qa0, qa1, qa2, qa3, k00, k01);
                mma_tf32(P[2 * ntp + 1][0], P[2 * ntp + 1][1], P[2 * ntp + 1][2], P[2 * ntp + 1][3],
                         qa0, qa1, qa2, qa3, k10, k11);
            }
        }

        // ---- p = exp2(clip(s)); accumulate row sums
#pragma unroll
        for (int nt = 0; nt < 16; nt++) {
            float p0 = pexp(P[nt][0]);
            float p1 = pexp(P[nt][1]);
            float p2 = pexp(P[nt][2]);
            float p3 = pexp(P[nt][3]);
            lp0 += p0 + p1;
            lp1 += p2 + p3;
            P[nt][0] = p0; P[nt][1] = p1; P[nt][2] = p2; P[nt][3] = p3;
        }

        // ---- O += P @ V  (P registers as A; V slot-permuted to match C layout)
#pragma unroll
        for (int ks = 0; ks < 16; ks++) {
            const uint32_t offv = (uint32_t)(((2 * ks + bk) ^ swzb) << 4);
            uint32_t a0 = __float_as_uint(P[ks][0]);
            uint32_t a1 = __float_as_uint(P[ks][2]);
            uint32_t a2 = __float_as_uint(P[ks][1]);
            uint32_t a3 = __float_as_uint(P[ks][3]);
#pragma unroll
            for (int dtp = 0; dtp < 4; dtp++) {
                uint32_t v00, v01, v10, v11;
                LDSM4(v00, v01, v10, v11, vb_base[dtp] + offv);
                mma_tf32(O[2 * dtp][0], O[2 * dtp][1], O[2 * dtp][2], O[2 * dtp][3],
                         a0, a1, a2, a3, v00, v01);
                mma_tf32(O[2 * dtp + 1][0], O[2 * dtp + 1][1], O[2 * dtp + 1][2], O[2 * dtp + 1][3],
                         a0, a1, a2, a3, v10, v11);
            }
        }
        __syncthreads();
    }

    lp0 += __shfl_xor_sync(0xffffffffu, lp0, 1);
    lp0 += __shfl_xor_sync(0xffffffffu, lp0, 2);
    lp1 += __shfl_xor_sync(0xffffffffu, lp1, 1);
    lp1 += __shfl_xor_sync(0xffffffffu, lp1, 2);
    const float li0 = 1.f / lp0, li1 = 1.f / lp1;

    const int row0 = qbase + wid * 16 + g;
#pragma unroll
    for (int dt = 0; dt < 8; dt++) {
        int d0 = dt * 8 + 2 * ct;
        float2 a;
        a.x = tf32_rna(O[dt][0] * li0);
        a.y = tf32_rna(O[dt][1] * li0);
        *(float2*)&out[(size_t)(b * NTOK + row0) * CDIM + h * HD + d0] = a;
        float2 c;
        c.x = tf32_rna(O[dt][2] * li1);
        c.y = tf32_rna(O[dt][3] * li1);
        *(float2*)&out[(size_t)(b * NTOK + row0 + 8) * CDIM + h * HD + d0] = c;
    }
}

// ============================================================================
// launch
// ============================================================================
extern "C" void kernel_launch(void* const* d_in, const int* in_sizes, int n_in,
                              void* d_out, int out_size)
{
    (void)in_sizes; (void)n_in; (void)out_size;
    const float* x      = (const float*)d_in[0];
    const float* w_qkv  = (const float*)d_in[1];
    const float* w_proj = (const float*)d_in[2];
    const float* b_proj = (const float*)d_in[3];
    float* out = (float*)d_out;

    float *qkv_p, *sc_p, *ks_p, *vT_p, *ao_p, *xhi_p, *xlo_p;
    float *wqh_p, *wql_p, *wph_p, *wpl_p;
    int* keep_p;
    cudaGetSymbolAddress((void**)&qkv_p,  g_qkv);
    cudaGetSymbolAddress((void**)&sc_p,   g_scores);
    cudaGetSymbolAddress((void**)&keep_p, g_keep);
    cudaGetSymbolAddress((void**)&ks_p,   g_ksel);
    cudaGetSymbolAddress((void**)&vT_p,   g_vselT);
    cudaGetSymbolAddress((void**)&ao_p,   g_attnout);
    cudaGetSymbolAddress((void**)&xhi_p,  g_xhi);
    cudaGetSymbolAddress((void**)&xlo_p,  g_xlo);
    cudaGetSymbolAddress((void**)&wqh_p,  g_wqT_hi);
    cudaGetSymbolAddress((void**)&wql_p,  g_wqT_lo);
    cudaGetSymbolAddress((void**)&wph_p,  g_wpT_hi);
    cudaGetSymbolAddress((void**)&wpl_p,  g_wpT_lo);

    const int smem_qkv  = 3 * 8192 * (int)sizeof(float);   // 98304
    const int smem_proj = 3 * 6144 * (int)sizeof(float);   // 73728
    cudaFuncSetAttribute(qkv_gemm,  cudaFuncAttributeMaxDynamicSharedMemorySize, smem_qkv);
    cudaFuncSetAttribute(proj_gemm, cudaFuncAttributeMaxDynamicSharedMemorySize, smem_proj);
    const int attn_smem = 3 * 8192 * (int)sizeof(float);   // 98304
    cudaFuncSetAttribute(attn_mma, cudaFuncAttributeMaxDynamicSharedMemorySize, attn_smem);

    // 0) tf32 splits
    xsplit_kernel<<<(ROWS * CDIM / 4 + 255) / 256, 256>>>(x, xhi_p, xlo_p, ROWS * CDIM / 4);
    wsplit_kernel<<<dim3(C3 / 32, CDIM / 32), dim3(32, 8)>>>(w_qkv, wqh_p, wql_p, CDIM, C3);
    wsplit_kernel<<<dim3(CDIM / 32, CDIM / 32), dim3(32, 8)>>>(w_proj, wph_p, wpl_p, CDIM, CDIM);

    // 1) qkv = x @ w_qkv  (q 3-term, k/v 1-term, 3-stage cp.async, ldmatrix)
    qkv_gemm<<<dim3(C3 / 128, ROWS / 128), 256, smem_qkv>>>(
        xhi_p, xlo_p, wqh_p, wql_p, qkv_p);

    // 2) scores, 3) top-k, 4) gather (V slot-permuted)
    scores_kernel<<<(NBH * NTOK + 255) / 256, 256>>>(qkv_p, sc_p);
    topk_kernel<<<NBH, 1024>>>(sc_p, keep_p);
    gather_kernel<<<dim3(KEEP / 64, NBH), 256>>>(qkv_p, keep_p, ks_p, vT_p);

    // 5) attention on tensor cores (P in registers, ldmatrix feeds)
    attn_mma<<<dim3(NTOK / 128, NBH), 256, attn_smem>>>(qkv_p, ks_p, vT_p, ao_p);

    // 6) out = clip(attnout @ w_proj + b_proj, -10, 10)  (2-term tf32)
    proj_gemm<<<dim3(CDIM / 128, ROWS / 128), 256, smem_proj>>>(
        ao_p, wph_p, wpl_p, b_proj, out);
}

// round 10
// speedup vs baseline: 3.3617x; 1.1943x over previous
#include <cuda_runtime.h>
#include <math.h>
#include <cstdint>

#define NH    12
#define NTOK  2048
#define BATCH 4
#define CDIM  768
#define HD    64
#define KEEP  1024
#define ROWS  (BATCH*NTOK)   /* 8192 */
#define C3    (3*CDIM)       /* 2304 */
#define NBH   (BATCH*NH)     /* 48 */
#define CLIPV 72.134689f     /* 50 * log2(e) */

// ---- scratch (static device globals; no runtime allocation) ----
__device__ float g_qkv[(size_t)ROWS * C3];
__device__ int   g_keep[NBH * KEEP];
__device__ float g_ksel [(size_t)NBH * KEEP * HD];  // [bh][j][d] row-major, tf32
__device__ float g_vselT[(size_t)NBH * HD * KEEP];  // [bh][d][slot] transposed+slot-permuted
__device__ float g_attnout[(size_t)ROWS * CDIM];
__device__ float g_xhi[(size_t)ROWS * CDIM];
__device__ float g_xlo[(size_t)ROWS * CDIM];
__device__ float g_wqT_hi[(size_t)C3 * CDIM];   // w_qkv^T [2304][768]
__device__ float g_wqT_lo[(size_t)C3 * CDIM];
__device__ float g_wpT_hi[(size_t)CDIM * CDIM]; // w_proj^T [768][768]
__device__ float g_wpT_lo[(size_t)CDIM * CDIM];

__device__ __forceinline__ float tf32_rna(float a) {
    float r; asm("cvt.rna.tf32.f32 %0, %1;" : "=f"(r) : "f"(a)); return r;
}
__device__ __forceinline__ float pexp(float s) {
    s = fminf(fmaxf(s, -CLIPV), CLIPV);
    float r; asm("ex2.approx.ftz.f32 %0, %1;" : "=f"(r) : "f"(s)); return r;
}
__device__ __forceinline__ uint32_t smem_u32(const void* p) {
    uint32_t a;
    asm("{ .reg .u64 t; cvta.to.shared.u64 t, %1; cvt.u32.u64 %0, t; }" : "=r"(a) : "l"(p));
    return a;
}
__device__ __forceinline__ void cp16(uint32_t dst, const float* src) {
    size_t ga = __cvta_generic_to_global(src);
    asm volatile("cp.async.cg.shared.global [%0], [%1], 16;" :: "r"(dst), "l"(ga));
}
__device__ __forceinline__ void mma_tf32(float& c0, float& c1, float& c2, float& c3,
                                         uint32_t a0, uint32_t a1, uint32_t a2, uint32_t a3,
                                         uint32_t b0, uint32_t b1) {
    asm volatile("mma.sync.aligned.m16n8k8.row.col.f32.tf32.tf32.f32 "
        "{%0,%1,%2,%3}, {%4,%5,%6,%7}, {%8,%9}, {%0,%1,%2,%3};"
        : "+f"(c0), "+f"(c1), "+f"(c2), "+f"(c3)
        : "r"(a0), "r"(a1), "r"(a2), "r"(a3), "r"(b0), "r"(b1));
}
// ldmatrix x4 on 16B rows of fp32 data (b16 view): lane l <- elem l%4 of row l/4
#define LDSM4(r0_, r1_, r2_, r3_, addr_) \
    asm volatile("ldmatrix.sync.aligned.m8n8.x4.shared.b16 {%0,%1,%2,%3}, [%4];" \
        : "=r"(r0_), "=r"(r1_), "=r"(r2_), "=r"(r3_) : "r"(addr_))

// ============================================================================
// 3-stage cp.async mma.sync tf32 GEMM body, xor-swizzled smem, ldmatrix feeds.
// C[M,N] = A[M,K] @ BT[N,K]^T, CTA tile 128x128, 8 warps (2m x 4n).
// TERMS=3: Ah*Bh + Ah*Bl + Al*Bh;  TERMS=2: Ah*(Bh+Bl);  TERMS=1: Ah*Bh.
// ============================================================================
template<int TERMS, int CH>
__device__ __forceinline__ void gemm_body(
    const float* __restrict__ Ahi, const float* __restrict__ Alo,
    const float* __restrict__ Bhi, const float* __restrict__ Blo,
    float* __restrict__ C, int K, int ldc,
    const float* __restrict__ bias, int do_clip, float* sm)
{
    constexpr int STAGES = 3;
    constexpr int T  = 128 * CH;
    constexpr int NT = (TERMS == 3) ? 4 : (TERMS + 1);
    constexpr int SS = NT * T;
    constexpr int GPR = CH / 4;
    constexpr int GPT = 128 * GPR / 256;

    const int tid = threadIdx.x, lane = tid & 31, wid = tid >> 5;
    const int g = lane >> 2, ct = lane & 3;
    const int wm = wid & 1, wn = wid >> 1;
    const int m0 = blockIdx.y * 128, n0 = blockIdx.x * 128;

    const int ao = ((lane >> 3) & 1) * 8 + (lane & 7);
    const int ak = lane >> 4;
    const int bo = (lane >> 4) * 8 + (lane & 7);
    const int bk = (lane >> 3) & 1;
    const int swzA = (CH == 16) ? ((ao >> 1) & 3) : (ao & 7);
    const int swzB = (CH == 16) ? ((bo >> 1) & 3) : (bo & 7);

    float acc[4][4][4];
#pragma unroll
    for (int mt = 0; mt < 4; mt++)
#pragma unroll
        for (int nt = 0; nt < 4; nt++)
#pragma unroll
            for (int i = 0; i < 4; i++) acc[mt][nt][i] = 0.f;

    const uint32_t smb = smem_u32(sm);
    const int NC = K / CH;

    auto issue = [&](int c) {
        const uint32_t sb = smb + (uint32_t)((c % STAGES) * SS * 4);
        const int k0 = c * CH;
#pragma unroll
        for (int j = 0; j < GPT; j++) {
            int gidx = tid + j * 256;
            int row = gidx / GPR, gg = gidx & (GPR - 1);
            int swz = (CH == 16) ? ((row >> 1) & 3) : (row & 7);
            uint32_t off = (uint32_t)((row * CH + ((gg ^ swz) << 2)) * 4);
            int gk = k0 + gg * 4;
            cp16(sb + off,                   Ahi + (size_t)(m0 + row) * K + gk);
            cp16(sb + (uint32_t)T * 4 + off, Bhi + (size_t)(n0 + row) * K + gk);
            if (TERMS >= 2)
                cp16(sb + 2u * T * 4 + off, Blo + (size_t)(n0 + row) * K + gk);
            if (TERMS == 3)
                cp16(sb + 3u * T * 4 + off, Alo + (size_t)(m0 + row) * K + gk);
        }
        asm volatile("cp.async.commit_group;" ::: "memory");
    };

    issue(0);
    issue(1);

    for (int c = 0; c < NC; c++) {
        asm volatile("cp.async.wait_group %0;" :: "n"(STAGES - 2));
        __syncthreads();
        if (c + STAGES - 1 < NC) issue(c + STAGES - 1);

        const uint32_t stb = smb + (uint32_t)((c % STAGES) * SS * 4);
        uint32_t aAh[4], aAl[4], aBh[2], aBl[2];
#pragma unroll
        for (int mt = 0; mt < 4; mt++) {
            int row = wm * 64 + mt * 16 + ao;
            aAh[mt] = stb + (uint32_t)(row * CH * 4);
            if (TERMS == 3) aAl[mt] = aAh[mt] + 3u * T * 4;
        }
#pragma unroll
        for (int ntp = 0; ntp < 2; ntp++) {
            int row = wn * 32 + ntp * 16 + bo;
            aBh[ntp] = stb + (uint32_t)(T * 4 + row * CH * 4);
            if (TERMS >= 2) aBl[ntp] = aBh[ntp] + (uint32_t)(T * 4);
        }

#pragma unroll
        for (int ks = 0; ks < CH / 8; ks++) {
            const uint32_t offA = (uint32_t)(((2 * ks + ak) ^ swzA) << 4);
            const uint32_t offB = (uint32_t)(((2 * ks + bk) ^ swzB) << 4);
            uint32_t afh[4][4], afl[4][4], bfh[4][2], bfl[4][2];
#pragma unroll
            for (int mt = 0; mt < 4; mt++) {
                LDSM4(afh[mt][0], afh[mt][1], afh[mt][2], afh[mt][3], aAh[mt] + offA);
                if (TERMS == 3)
                    LDSM4(afl[mt][0], afl[mt][1], afl[mt][2], afl[mt][3], aAl[mt] + offA);
            }
            LDSM4(bfh[0][0], bfh[0][1], bfh[1][0], bfh[1][1], aBh[0] + offB);
            LDSM4(bfh[2][0], bfh[2][1], bfh[3][0], bfh[3][1], aBh[1] + offB);
            if (TERMS >= 2) {
                LDSM4(bfl[0][0], bfl[0][1], bfl[1][0], bfl[1][1], aBl[0] + offB);
                LDSM4(bfl[2][0], bfl[2][1], bfl[3][0], bfl[3][1], aBl[1] + offB);
            }
#pragma unroll
            for (int mt = 0; mt < 4; mt++)
#pragma unroll
                for (int nt = 0; nt < 4; nt++) {
                    float* a = acc[mt][nt];
                    mma_tf32(a[0], a[1], a[2], a[3],
                             afh[mt][0], afh[mt][1], afh[mt][2], afh[mt][3],
                             bfh[nt][0], bfh[nt][1]);
                    if (TERMS >= 2)
                        mma_tf32(a[0], a[1], a[2], a[3],
                                 afh[mt][0], afh[mt][1], afh[mt][2], afh[mt][3],
                                 bfl[nt][0], bfl[nt][1]);
                    if (TERMS == 3)
                        mma_tf32(a[0], a[1], a[2], a[3],
                                 afl[mt][0], afl[mt][1], afl[mt][2], afl[mt][3],
                                 bfh[nt][0], bfh[nt][1]);
                }
        }
    }

#pragma unroll
    for (int mt = 0; mt < 4; mt++) {
#pragma unroll
        for (int nt = 0; nt < 4; nt++) {
            int row = m0 + wm * 64 + mt * 16 + g;
            int col = n0 + wn * 32 + nt * 8 + ct * 2;
            float v0 = acc[mt][nt][0], v1 = acc[mt][nt][1];
            float v2 = acc[mt][nt][2], v3 = acc[mt][nt][3];
            if (bias) {
                float b0 = bias[col], b1 = bias[col + 1];
                v0 += b0; v1 += b1; v2 += b0; v3 += b1;
            }
            if (do_clip) {
                v0 = fminf(fmaxf(v0, -10.f), 10.f);
                v1 = fminf(fmaxf(v1, -10.f), 10.f);
                v2 = fminf(fmaxf(v2, -10.f), 10.f);
                v3 = fminf(fmaxf(v3, -10.f), 10.f);
            }
            float2 lo2; lo2.x = v0; lo2.y = v1;
            float2 hi2; hi2.x = v2; hi2.y = v3;
            *(float2*)(C + (size_t)row * ldc + col) = lo2;
            *(float2*)(C + (size_t)(row + 8) * ldc + col) = hi2;
        }
    }
}

// qkv in one launch: first 6 column-blocks (q) 3-term, rest (k,v) 1-term
__global__ __launch_bounds__(256, 2) void qkv_gemm(
    const float* __restrict__ xhi, const float* __restrict__ xlo,
    const float* __restrict__ wTh, const float* __restrict__ wTl,
    float* __restrict__ C)
{
    extern __shared__ float sm[];
    if (blockIdx.x * 128 < CDIM)
        gemm_body<3, 16>(xhi, xlo, wTh, wTl, C, CDIM, C3, nullptr, 0, sm);
    else
        gemm_body<1, 32>(xhi, nullptr, wTh, nullptr, C, CDIM, C3, nullptr, 0, sm);
}

__global__ __launch_bounds__(256, 2) void proj_gemm(
    const float* __restrict__ A, const float* __restrict__ Bh,
    const float* __restrict__ Bl, const float* __restrict__ bias,
    float* __restrict__ C)
{
    extern __shared__ float sm[];
    gemm_body<2, 16>(A, nullptr, Bh, Bl, C, CDIM, CDIM, bias, 1, sm);
}

// ============================================================================
// x -> (hi, lo) tf32 split
// ============================================================================
__global__ void xsplit_kernel(const float* __restrict__ x, float* __restrict__ hi,
                              float* __restrict__ lo, int n4)
{
    int i = blockIdx.x * blockDim.x + threadIdx.x;
    if (i >= n4) return;
    float4 v = ((const float4*)x)[i];
    float4 h, l;
    h.x = tf32_rna(v.x); l.x = tf32_rna(v.x - h.x);
    h.y = tf32_rna(v.y); l.y = tf32_rna(v.y - h.y);
    h.z = tf32_rna(v.z); l.z = tf32_rna(v.z - h.z);
    h.w = tf32_rna(v.w); l.w = tf32_rna(v.w - h.w);
    ((float4*)hi)[i] = h;
    ((float4*)lo)[i] = l;
}

// ============================================================================
// weight transpose + tf32 split: in[K,N] -> ohi[N,K] + olo[N,K]
// ============================================================================
__global__ void wsplit_kernel(const float* __restrict__ in, float* __restrict__ ohi,
                              float* __restrict__ olo, int K, int N)
{
    __shared__ float t[32][33];
    const int n0 = blockIdx.x * 32, k0 = blockIdx.y * 32;
    const int tx = threadIdx.x, ty = threadIdx.y;
#pragma unroll
    for (int i = 0; i < 4; i++)
        t[ty + i * 8][tx] = in[(size_t)(k0 + ty + i * 8) * N + n0 + tx];
    __syncthreads();
#pragma unroll
    for (int i = 0; i < 4; i++) {
        float v = t[tx][ty + i * 8];
        float h = tf32_rna(v);
        ohi[(size_t)(n0 + ty + i * 8) * K + k0 + tx] = h;
        olo[(size_t)(n0 + ty + i * 8) * K + k0 + tx] = tf32_rna(v - h);
    }
}

// ============================================================================
// Per-(b,h) top-KEEP: scores computed inline (sum_d q^2), then bitonic sort
// of packed u64 keys (set semantics — attention is permutation-invariant).
// ============================================================================
__global__ __launch_bounds__(1024) void topk_kernel(
    const float* __restrict__ qkv, int* __restrict__ keep)
{
    __shared__ unsigned long long keys[NTOK];
    const int bh = blockIdx.x, t = threadIdx.x;
    const int h = bh % NH, b = bh / NH;
    for (int i = t; i < NTOK; i += 1024) {
        const float4* q = (const float4*)(qkv + (size_t)(b * NTOK + i) * C3 + h * HD);
        float s = 0.f;
#pragma unroll
        for (int u = 0; u < 16; u++) {
            float4 v = q[u];
            s += v.x * v.x + v.y * v.y + v.z * v.z + v.w * v.w;
        }
        keys[i] = ((unsigned long long)__float_as_uint(s) << 32) | (unsigned)(NTOK - 1 - i);
    }
    for (int k = 2; k <= NTOK; k <<= 1) {
        for (int j = k >> 1; j > 0; j >>= 1) {
            __syncthreads();
            for (int i = t; i < NTOK; i += 1024) {
                int ixj = i ^ j;
                if (ixj > i) {
                    unsigned long long a = keys[i], c = keys[ixj];
                    bool asc = ((i & k) == 0);
                    if ((a > c) == asc) { keys[i] = c; keys[ixj] = a; }
                }
            }
        }
    }
    __syncthreads();
    if (t < KEEP) {
        keep[bh * KEEP + t] = (NTOK - 1) - (int)(keys[NTOK - KEEP + t] & 0xffffffffu);
    }
}

// ============================================================================
// Gather: K row-major [bh][j][d] (tf32-rounded).
// V transposed [bh][d][slot], slot order per 8-group = [0,2,4,6,1,3,5,7] so
// the S-mma C fragment feeds the PV-mma A operand directly.
// ============================================================================
__global__ __launch_bounds__(256) void gather_kernel(
    const float* __restrict__ qkv, const int* __restrict__ keep,
    float* __restrict__ ksel, float* __restrict__ vselT)
{
    __shared__ float tile[HD][65];
    const int bh = blockIdx.y, jc = blockIdx.x;
    const int b = bh / NH, h = bh % NH;
    const int t = threadIdx.x;

#pragma unroll
    for (int r = 0; r < 4; r++) {
        int idx = t + r * 256;
        int row = idx >> 4, f4 = (idx & 15) * 4;
        int kidx = keep[bh * KEEP + jc * 64 + row];
        const float* base = qkv + (size_t)(b * NTOK + kidx) * C3 + h * HD;
        float4 kv = *(const float4*)(base + CDIM + f4);
        kv.x = tf32_rna(kv.x); kv.y = tf32_rna(kv.y);
        kv.z = tf32_rna(kv.z); kv.w = tf32_rna(kv.w);
        *(float4*)(ksel + ((size_t)bh * KEEP + jc * 64 + row) * HD + f4) = kv;
        float4 vv = *(const float4*)(base + 2 * CDIM + f4);
        tile[f4 + 0][row] = tf32_rna(vv.x); tile[f4 + 1][row] = tf32_rna(vv.y);
        tile[f4 + 2][row] = tf32_rna(vv.z); tile[f4 + 3][row] = tf32_rna(vv.w);
    }
    __syncthreads();
#pragma unroll
    for (int r = 0; r < 4; r++) {
        int idx = t + r * 256;
        int d = idx >> 4, jf = (idx & 15) * 4;
        int jgrp = jf & ~7;
        int o = (jf & 4) ? 1 : 0;
        float4 v;
        v.x = tile[d][jgrp + 0 + o]; v.y = tile[d][jgrp + 2 + o];
        v.z = tile[d][jgrp + 4 + o]; v.w = tile[d][jgrp + 6 + o];
        *(float4*)(vselT + ((size_t)bh * HD + d) * KEEP + jc * 64 + jf) = v;
    }
}

// ============================================================================
// mma.sync attention, warp-row-split + 2-stage cp.async K/V pipeline.
// 8 warps x 16 query rows; key chunks of 64; P stays in registers and feeds
// the PV mma directly (V pre-permuted per 8-group).
// smem 96KB: Qs[128][64] (32K) | 2 stages x { K[64][64] 16K + V[64][64] 16K }.
// ============================================================================
__global__ __launch_bounds__(256, 2) void attn_mma(
    const float* __restrict__ qkv, const float* __restrict__ ksel,
    const float* __restrict__ vselT, float* __restrict__ out)
{
    extern __shared__ float sm[];
    float* Qs = sm;                       // [128][64]
    const uint32_t smb   = smem_u32(sm);
    const uint32_t stage0 = smb + 8192u * 4;   // stage s at stage0 + s*32KB; V at +16KB

    const int tid = threadIdx.x, lane = tid & 31, wid = tid >> 5;
    const int g = lane >> 2, ct = lane & 3;
    const int bh = blockIdx.y, b = bh / NH, h = bh % NH;
    const int qbase = blockIdx.x * 128;

    // ldmatrix lane geometry
    const int ao = ((lane >> 3) & 1) * 8 + (lane & 7);
    const int ak = lane >> 4;
    const int bo = (lane >> 4) * 8 + (lane & 7);
    const int bk = (lane >> 3) & 1;
    const int swzq = ao & 7;
    const int swzb = bo & 7;

    // load Q scaled by 0.125*log2(e), tf32-rounded, swizzled
    {
        int j = tid & 127, half = tid >> 7;
        const float* qrow = qkv + (size_t)(b * NTOK + qbase + j) * C3 + h * HD + half * 32;
        const float QSC = 0.125f * 1.44269504f;
#pragma unroll
        for (int i = 0; i < 8; i++) {
            float4 v = *(const float4*)(qrow + i * 4);
            v.x = tf32_rna(v.x * QSC); v.y = tf32_rna(v.y * QSC);
            v.z = tf32_rna(v.z * QSC); v.w = tf32_rna(v.w * QSC);
            int c = half * 32 + i * 4;
            *(float4*)&Qs[j * 64 + (c ^ ((j & 7) << 2))] = v;
        }
    }

    const float* kbase = ksel  + (size_t)bh * KEEP * HD;
    const float* vbase = vselT + (size_t)bh * HD * KEEP;

    // cp.async loader: K[64 rows][16 groups] + V[64 d-rows][16 groups] per chunk
    auto issue = [&](int kc) {
        const uint32_t sb = stage0 + (uint32_t)((kc & 1) * 8192 * 4);
#pragma unroll
        for (int j = 0; j < 4; j++) {
            int gidx = tid + j * 256;
            int row = gidx >> 4, gg = gidx & 15;
            uint32_t off = (uint32_t)((row * 64 + ((gg ^ (row & 7)) << 2)) * 4);
            cp16(sb + off, kbase + (size_t)(kc * 64 + row) * HD + gg * 4);
            cp16(sb + 4096u * 4 + off, vbase + (size_t)row * KEEP + kc * 64 + gg * 4);
        }
        asm volatile("cp.async.commit_group;" ::: "memory");
    };

    const uint32_t qa_base = smb + (uint32_t)((wid * 16 + ao) * 64 * 4);

    float P[8][4];
    float O[8][4];
    float lp0 = 0.f, lp1 = 0.f;
#pragma unroll
    for (int dt = 0; dt < 8; dt++)
#pragma unroll
        for (int i = 0; i < 4; i++) O[dt][i] = 0.f;

    issue(0);

    for (int kc = 0; kc < KEEP / 64; kc++) {
        if (kc + 1 < KEEP / 64) {
            issue(kc + 1);
            asm volatile("cp.async.wait_group 1;" ::: "memory");
        } else {
            asm volatile("cp.async.wait_group 0;" ::: "memory");
        }
        __syncthreads();

        const uint32_t kst = stage0 + (uint32_t)((kc & 1) * 8192 * 4);
        const uint32_t vst = kst + 4096u * 4;

        // ---- S = (Q*scale) @ K^T : 16 rows x 64 keys
#pragma unroll
        for (int nt = 0; nt < 8; nt++)
#pragma unroll
            for (int i = 0; i < 4; i++) P[nt][i] = 0.f;

#pragma unroll
        for (int ks = 0; ks < 8; ks++) {
            const uint32_t offq = (uint32_t)(((2 * ks + ak) ^ swzq) << 4);
            const uint32_t offb = (uint32_t)(((2 * ks + bk) ^ swzb) << 4);
            uint32_t qa0, qa1, qa2, qa3;
            LDSM4(qa0, qa1, qa2, qa3, qa_base + offq);
#pragma unroll
            for (int ntp = 0; ntp < 4; ntp++) {
                uint32_t k00, k01, k10, k11;
                LDSM4(k00, k01, k10, k11, kst + (uint32_t)((ntp * 16 + bo) * 64 * 4) + offb);
                mma_tf32(P[2 * ntp][0], P[2 * ntp][1], P[2 * ntp][2], P[2 * ntp][3],
                         qa0, qa1, qa2, qa3, k00, k01);
                mma_tf32(P[2 * ntp + 1][0], P[2 * ntp + 1][1], P[2 * ntp + 1][2], P[2 * ntp + 1][3],
                         qa0, qa1, qa2, qa3, k10, k11);
            }
        }

        // ---- p = exp2(clip(s)); accumulate row sums
#pragma unroll
        for (int nt = 0; nt < 8; nt++) {
            float p0 = pexp(P[nt][0]);
            float p1 = pexp(P[nt][1]);
            float p2 = pexp(P[nt][2]);
            float p3 = pexp(P[nt][3]);
            lp0 += p0 + p1;
            lp1 += p2 + p3;
            P[nt][0] = p0; P[nt][1] = p1; P[nt][2] = p2; P[nt][3] = p3;
        }

        // ---- O += P @ V  (P registers as A; V slot-permuted to match C layout)
#pragma unroll
        for (int ks = 0; ks < 8; ks++) {
            const uint32_t offv = (uint32_t)(((2 * ks + bk) ^ swzb) << 4);
            uint32_t a0 = __float_as_uint(P[ks][0]);
            uint32_t a1 = __float_as_uint(P[ks][2]);
            uint32_t a2 = __float_as_uint(P[ks][1]);
            uint32_t a3 = __float_as_uint(P[ks][3]);
#pragma unroll
            for (int dtp = 0; dtp < 4; dtp++) {
                uint32_t v00, v01, v10, v11;
                LDSM4(v00, v01, v10, v11, vst + (uint32_t)((dtp * 16 + bo) * 64 * 4) + offv);
                mma_tf32(O[2 * dtp][0], O[2 * dtp][1], O[2 * dtp][2], O[2 * dtp][3],
                         a0, a1, a2, a3, v00, v01);
                mma_tf32(O[2 * dtp + 1][0], O[2 * dtp + 1][1], O[2 * dtp + 1][2], O[2 * dtp + 1][3],
                         a0, a1, a2, a3, v10, v11);
            }
        }
        __syncthreads();   // all reads of stage kc done before issue(kc+2) overwrites it
    }

    lp0 += __shfl_xor_sync(0xffffffffu, lp0, 1);
    lp0 += __shfl_xor_sync(0xffffffffu, lp0, 2);
    lp1 += __shfl_xor_sync(0xffffffffu, lp1, 1);
    lp1 += __shfl_xor_sync(0xffffffffu, lp1, 2);
    const float li0 = 1.f / lp0, li1 = 1.f / lp1;

    const int row0 = qbase + wid * 16 + g;
#pragma unroll
    for (int dt = 0; dt < 8; dt++) {
        int d0 = dt * 8 + 2 * ct;
        float2 a;
        a.x = tf32_rna(O[dt][0] * li0);
        a.y = tf32_rna(O[dt][1] * li0);
        *(float2*)&out[(size_t)(b * NTOK + row0) * CDIM + h * HD + d0] = a;
        float2 c;
        c.x = tf32_rna(O[dt][2] * li1);
        c.y = tf32_rna(O[dt][3] * li1);
        *(float2*)&out[(size_t)(b * NTOK + row0 + 8) * CDIM + h * HD + d0] = c;
    }
}

// ============================================================================
// launch
// ============================================================================
extern "C" void kernel_launch(void* const* d_in, const int* in_sizes, int n_in,
                              void* d_out, int out_size)
{
    (void)in_sizes; (void)n_in; (void)out_size;
    const float* x      = (const float*)d_in[0];
    const float* w_qkv  = (const float*)d_in[1];
    const float* w_proj = (const float*)d_in[2];
    const float* b_proj = (const float*)d_in[3];
    float* out = (float*)d_out;

    float *qkv_p, *ks_p, *vT_p, *ao_p, *xhi_p, *xlo_p;
    float *wqh_p, *wql_p, *wph_p, *wpl_p;
    int* keep_p;
    cudaGetSymbolAddress((void**)&qkv_p,  g_qkv);
    cudaGetSymbolAddress((void**)&keep_p, g_keep);
    cudaGetSymbolAddress((void**)&ks_p,   g_ksel);
    cudaGetSymbolAddress((void**)&vT_p,   g_vselT);
    cudaGetSymbolAddress((void**)&ao_p,   g_attnout);
    cudaGetSymbolAddress((void**)&xhi_p,  g_xhi);
    cudaGetSymbolAddress((void**)&xlo_p,  g_xlo);
    cudaGetSymbolAddress((void**)&wqh_p,  g_wqT_hi);
    cudaGetSymbolAddress((void**)&wql_p,  g_wqT_lo);
    cudaGetSymbolAddress((void**)&wph_p,  g_wpT_hi);
    cudaGetSymbolAddress((void**)&wpl_p,  g_wpT_lo);

    const int smem_qkv  = 3 * 8192 * (int)sizeof(float);   // 98304
    const int smem_proj = 3 * 6144 * (int)sizeof(float);   // 73728
    cudaFuncSetAttribute(qkv_gemm,  cudaFuncAttributeMaxDynamicSharedMemorySize, smem_qkv);
    cudaFuncSetAttribute(proj_gemm, cudaFuncAttributeMaxDynamicSharedMemorySize, smem_proj);
    const int attn_smem = 3 * 8192 * (int)sizeof(float);   // 98304 (Q 32K + 2x32K stages)
    cudaFuncSetAttribute(attn_mma, cudaFuncAttributeMaxDynamicSharedMemorySize, attn_smem);

    // 0) tf32 splits
    xsplit_kernel<<<(ROWS * CDIM / 4 + 255) / 256, 256>>>(x, xhi_p, xlo_p, ROWS * CDIM / 4);
    wsplit_kernel<<<dim3(C3 / 32, CDIM / 32), dim3(32, 8)>>>(w_qkv, wqh_p, wql_p, CDIM, C3);
    wsplit_kernel<<<dim3(CDIM / 32, CDIM / 32), dim3(32, 8)>>>(w_proj, wph_p, wpl_p, CDIM, CDIM);

    // 1) qkv = x @ w_qkv  (q 3-term, k/v 1-term, 3-stage cp.async, ldmatrix)
    qkv_gemm<<<dim3(C3 / 128, ROWS / 128), 256, smem_qkv>>>(
        xhi_p, xlo_p, wqh_p, wql_p, qkv_p);

    // 2) top-k (scores fused), 3) gather (V slot-permuted)
    topk_kernel<<<NBH, 1024>>>(qkv_p, keep_p);
    gather_kernel<<<dim3(KEEP / 64, NBH), 256>>>(qkv_p, keep_p, ks_p, vT_p);

    // 4) attention on tensor cores (P in registers, 2-stage cp.async K/V)
    attn_mma<<<dim3(NTOK / 128, NBH), 256, attn_smem>>>(qkv_p, ks_p, vT_p, ao_p);

    // 5) out = clip(attnout @ w_proj + b_proj, -10, 10)  (2-term tf32)
    proj_gemm<<<dim3(CDIM / 128, ROWS / 128), 256, smem_proj>>>(
        ao_p, wph_p, wpl_p, b_proj, out);
}

// round 11
// speedup vs baseline: 3.7360x; 1.1113x over previous
#include <cuda_runtime.h>
#include <math.h>
#include <cstdint>

#define NH    12
#define NTOK  2048
#define BATCH 4
#define CDIM  768
#define HD    64
#define KEEP  1024
#define ROWS  (BATCH*NTOK)   /* 8192 */
#define C3    (3*CDIM)       /* 2304 */
#define NBH   (BATCH*NH)     /* 48 */
#define CLIPV 72.134689f     /* 50 * log2(e) */

// ---- scratch (static device globals; no runtime allocation) ----
__device__ float g_q[(size_t)ROWS * CDIM];          // q only, [row][768]
__device__ int   g_keep[NBH * KEEP];
__device__ float g_ksel [(size_t)NBH * KEEP * HD];  // [bh][j][d] row-major, tf32
__device__ float g_vselT[(size_t)NBH * HD * KEEP];  // [bh][d][slot] transposed+permuted
__device__ float g_attnout[(size_t)ROWS * CDIM];
__device__ float g_xhi[(size_t)ROWS * CDIM];
__device__ float g_xlo[(size_t)ROWS * CDIM];
__device__ float g_wqT_hi[(size_t)C3 * CDIM];       // w_qkv^T [2304][768]
__device__ float g_wqT_lo[(size_t)C3 * CDIM];
__device__ float g_wpT_hi[(size_t)CDIM * CDIM];
__device__ float g_wpT_lo[(size_t)CDIM * CDIM];

__device__ __forceinline__ float tf32_rna(float a) {
    float r; asm("cvt.rna.tf32.f32 %0, %1;" : "=f"(r) : "f"(a)); return r;
}
__device__ __forceinline__ float pexp(float s) {
    s = fminf(fmaxf(s, -CLIPV), CLIPV);
    float r; asm("ex2.approx.ftz.f32 %0, %1;" : "=f"(r) : "f"(s)); return r;
}
__device__ __forceinline__ uint32_t smem_u32(const void* p) {
    uint32_t a;
    asm("{ .reg .u64 t; cvta.to.shared.u64 t, %1; cvt.u32.u64 %0, t; }" : "=r"(a) : "l"(p));
    return a;
}
__device__ __forceinline__ void cp16(uint32_t dst, const float* src) {
    size_t ga = __cvta_generic_to_global(src);
    asm volatile("cp.async.cg.shared.global [%0], [%1], 16;" :: "r"(dst), "l"(ga));
}
__device__ __forceinline__ void mma_tf32(float& c0, float& c1, float& c2, float& c3,
                                         uint32_t a0, uint32_t a1, uint32_t a2, uint32_t a3,
                                         uint32_t b0, uint32_t b1) {
    asm volatile("mma.sync.aligned.m16n8k8.row.col.f32.tf32.tf32.f32 "
        "{%0,%1,%2,%3}, {%4,%5,%6,%7}, {%8,%9}, {%0,%1,%2,%3};"
        : "+f"(c0), "+f"(c1), "+f"(c2), "+f"(c3)
        : "r"(a0), "r"(a1), "r"(a2), "r"(a3), "r"(b0), "r"(b1));
}
#define LDSM4(r0_, r1_, r2_, r3_, addr_) \
    asm volatile("ldmatrix.sync.aligned.m8n8.x4.shared.b16 {%0,%1,%2,%3}, [%4];" \
        : "=r"(r0_), "=r"(r1_), "=r"(r2_), "=r"(r3_) : "r"(addr_))

// ============================================================================
// 3-stage cp.async mma.sync tf32 GEMM body (dense), ldmatrix feeds.
// C[M,N] = A[M,K] @ BT[N,K]^T, CTA tile 128x128, 8 warps (2m x 4n).
// TERMS=3: Ah*Bh + Ah*Bl + Al*Bh;  TERMS=2: Ah*(Bh+Bl).
// ============================================================================
template<int TERMS, int CH>
__device__ __forceinline__ void gemm_body(
    const float* __restrict__ Ahi, const float* __restrict__ Alo,
    const float* __restrict__ Bhi, const float* __restrict__ Blo,
    float* __restrict__ C, int K, int ldc,
    const float* __restrict__ bias, int do_clip, float* sm)
{
    constexpr int STAGES = 3;
    constexpr int T  = 128 * CH;
    constexpr int NT = (TERMS == 3) ? 4 : (TERMS + 1);
    constexpr int SS = NT * T;
    constexpr int GPR = CH / 4;
    constexpr int GPT = 128 * GPR / 256;

    const int tid = threadIdx.x, lane = tid & 31, wid = tid >> 5;
    const int g = lane >> 2, ct = lane & 3;
    const int wm = wid & 1, wn = wid >> 1;
    const int m0 = blockIdx.y * 128, n0 = blockIdx.x * 128;

    const int ao = ((lane >> 3) & 1) * 8 + (lane & 7);
    const int ak = lane >> 4;
    const int bo = (lane >> 4) * 8 + (lane & 7);
    const int bk = (lane >> 3) & 1;
    const int swzA = (CH == 16) ? ((ao >> 1) & 3) : (ao & 7);
    const int swzB = (CH == 16) ? ((bo >> 1) & 3) : (bo & 7);

    float acc[4][4][4];
#pragma unroll
    for (int mt = 0; mt < 4; mt++)
#pragma unroll
        for (int nt = 0; nt < 4; nt++)
#pragma unroll
            for (int i = 0; i < 4; i++) acc[mt][nt][i] = 0.f;

    const uint32_t smb = smem_u32(sm);
    const int NC = K / CH;

    auto issue = [&](int c) {
        const uint32_t sb = smb + (uint32_t)((c % STAGES) * SS * 4);
        const int k0 = c * CH;
#pragma unroll
        for (int j = 0; j < GPT; j++) {
            int gidx = tid + j * 256;
            int row = gidx / GPR, gg = gidx & (GPR - 1);
            int swz = (CH == 16) ? ((row >> 1) & 3) : (row & 7);
            uint32_t off = (uint32_t)((row * CH + ((gg ^ swz) << 2)) * 4);
            int gk = k0 + gg * 4;
            cp16(sb + off,                   Ahi + (size_t)(m0 + row) * K + gk);
            cp16(sb + (uint32_t)T * 4 + off, Bhi + (size_t)(n0 + row) * K + gk);
            if (TERMS >= 2)
                cp16(sb + 2u * T * 4 + off, Blo + (size_t)(n0 + row) * K + gk);
            if (TERMS == 3)
                cp16(sb + 3u * T * 4 + off, Alo + (size_t)(m0 + row) * K + gk);
        }
        asm volatile("cp.async.commit_group;" ::: "memory");
    };

    issue(0);
    issue(1);

    for (int c = 0; c < NC; c++) {
        asm volatile("cp.async.wait_group %0;" :: "n"(STAGES - 2));
        __syncthreads();
        if (c + STAGES - 1 < NC) issue(c + STAGES - 1);

        const uint32_t stb = smb + (uint32_t)((c % STAGES) * SS * 4);
        uint32_t aAh[4], aAl[4], aBh[2], aBl[2];
#pragma unroll
        for (int mt = 0; mt < 4; mt++) {
            int row = wm * 64 + mt * 16 + ao;
            aAh[mt] = stb + (uint32_t)(row * CH * 4);
            if (TERMS == 3) aAl[mt] = aAh[mt] + 3u * T * 4;
        }
#pragma unroll
        for (int ntp = 0; ntp < 2; ntp++) {
            int row = wn * 32 + ntp * 16 + bo;
            aBh[ntp] = stb + (uint32_t)(T * 4 + row * CH * 4);
            if (TERMS >= 2) aBl[ntp] = aBh[ntp] + (uint32_t)(T * 4);
        }

#pragma unroll
        for (int ks = 0; ks < CH / 8; ks++) {
            const uint32_t offA = (uint32_t)(((2 * ks + ak) ^ swzA) << 4);
            const uint32_t offB = (uint32_t)(((2 * ks + bk) ^ swzB) << 4);
            uint32_t afh[4][4], afl[4][4], bfh[4][2], bfl[4][2];
#pragma unroll
            for (int mt = 0; mt < 4; mt++) {
                LDSM4(afh[mt][0], afh[mt][1], afh[mt][2], afh[mt][3], aAh[mt] + offA);
                if (TERMS == 3)
                    LDSM4(afl[mt][0], afl[mt][1], afl[mt][2], afl[mt][3], aAl[mt] + offA);
            }
            LDSM4(bfh[0][0], bfh[0][1], bfh[1][0], bfh[1][1], aBh[0] + offB);
            LDSM4(bfh[2][0], bfh[2][1], bfh[3][0], bfh[3][1], aBh[1] + offB);
            if (TERMS >= 2) {
                LDSM4(bfl[0][0], bfl[0][1], bfl[1][0], bfl[1][1], aBl[0] + offB);
                LDSM4(bfl[2][0], bfl[2][1], bfl[3][0], bfl[3][1], aBl[1] + offB);
            }
#pragma unroll
            for (int mt = 0; mt < 4; mt++)
#pragma unroll
                for (int nt = 0; nt < 4; nt++) {
                    float* a = acc[mt][nt];
                    mma_tf32(a[0], a[1], a[2], a[3],
                             afh[mt][0], afh[mt][1], afh[mt][2], afh[mt][3],
                             bfh[nt][0], bfh[nt][1]);
                    if (TERMS >= 2)
                        mma_tf32(a[0], a[1], a[2], a[3],
                                 afh[mt][0], afh[mt][1], afh[mt][2], afh[mt][3],
                                 bfl[nt][0], bfl[nt][1]);
                    if (TERMS == 3)
                        mma_tf32(a[0], a[1], a[2], a[3],
                                 afl[mt][0], afl[mt][1], afl[mt][2], afl[mt][3],
                                 bfh[nt][0], bfh[nt][1]);
                }
        }
    }

#pragma unroll
    for (int mt = 0; mt < 4; mt++) {
#pragma unroll
        for (int nt = 0; nt < 4; nt++) {
            int row = m0 + wm * 64 + mt * 16 + g;
            int col = n0 + wn * 32 + nt * 8 + ct * 2;
            float v0 = acc[mt][nt][0], v1 = acc[mt][nt][1];
            float v2 = acc[mt][nt][2], v3 = acc[mt][nt][3];
            if (bias) {
                float b0 = bias[col], b1 = bias[col + 1];
                v0 += b0; v1 += b1; v2 += b0; v3 += b1;
            }
            if (do_clip) {
                v0 = fminf(fmaxf(v0, -10.f), 10.f);
                v1 = fminf(fmaxf(v1, -10.f), 10.f);
                v2 = fminf(fmaxf(v2, -10.f), 10.f);
                v3 = fminf(fmaxf(v3, -10.f), 10.f);
            }
            float2 lo2; lo2.x = v0; lo2.y = v1;
            float2 hi2; hi2.x = v2; hi2.y = v3;
            *(float2*)(C + (size_t)row * ldc + col) = lo2;
            *(float2*)(C + (size_t)(row + 8) * ldc + col) = hi2;
        }
    }
}

// q only: [8192 x 768] = [8192 x 768] @ w_q^T, 3-term tf32 (top-k safe)
__global__ __launch_bounds__(256, 2) void q_gemm(
    const float* __restrict__ xhi, const float* __restrict__ xlo,
    const float* __restrict__ wTh, const float* __restrict__ wTl,
    float* __restrict__ C)
{
    extern __shared__ float sm[];
    gemm_body<3, 16>(xhi, xlo, wTh, wTl, C, CDIM, CDIM, nullptr, 0, sm);
}

__global__ __launch_bounds__(256, 2) void proj_gemm(
    const float* __restrict__ A, const float* __restrict__ Bh,
    const float* __restrict__ Bl, const float* __restrict__ bias,
    float* __restrict__ C)
{
    extern __shared__ float sm[];
    gemm_body<2, 16>(A, nullptr, Bh, Bl, C, CDIM, CDIM, bias, 1, sm);
}

// ============================================================================
// Gather-GEMM: per (b,h) compute Ksel = x[keep]·w_k[h], Vsel = x[keep]·w_v[h].
// Tile M=128 gathered tokens x N=128 (cols 0-63 = k dims, 64-127 = v dims),
// K=768, 1-term tf32, CH=32, 3-stage cp.async, ldmatrix. Epilogue writes
// Ksel row-major (tf32-rounded) and Vsel^T slot-permuted via smem transpose.
// ============================================================================
__global__ __launch_bounds__(256, 2) void kvg_gemm(
    const float* __restrict__ xhi, const float* __restrict__ wTh,
    const int* __restrict__ keep,
    float* __restrict__ ksel, float* __restrict__ vselT)
{
    extern __shared__ float sm[];
    constexpr int CH = 32, STAGES = 3;
    constexpr int T  = 128 * CH;   // 4096 floats
    constexpr int SS = 2 * T;      // 8192 floats per stage

    const int tid = threadIdx.x, lane = tid & 31, wid = tid >> 5;
    const int g = lane >> 2, ct = lane & 3;
    const int wm = wid & 1, wn = wid >> 1;
    const int m0 = blockIdx.x * 128;
    const int bh = blockIdx.y, b = bh / NH, h = bh % NH;

    const int ao = ((lane >> 3) & 1) * 8 + (lane & 7);
    const int ak = lane >> 4;
    const int bo = (lane >> 4) * 8 + (lane & 7);
    const int bk = (lane >> 3) & 1;
    const int swzA = ao & 7;
    const int swzB = bo & 7;

    // loader: row = tid/8 + 32j, group gg = tid%8; pointers loop-invariant
    const int lrow = tid >> 3, lgg = tid & 7;
    const float* aptr[4];
    const float* bptr[4];
    uint32_t soff[4];
#pragma unroll
    for (int j = 0; j < 4; j++) {
        int row = lrow + 32 * j;
        int tok = keep[bh * KEEP + m0 + row];
        aptr[j] = xhi + (size_t)(b * NTOK + tok) * CDIM + lgg * 4;
        int wrow = (row < 64) ? (CDIM + h * HD + row) : (2 * CDIM + h * HD + row - 64);
        bptr[j] = wTh + (size_t)wrow * CDIM + lgg * 4;
        soff[j] = (uint32_t)((row * CH + ((lgg ^ (row & 7)) << 2)) * 4);
    }

    float acc[4][4][4];
#pragma unroll
    for (int mt = 0; mt < 4; mt++)
#pragma unroll
        for (int nt = 0; nt < 4; nt++)
#pragma unroll
            for (int i = 0; i < 4; i++) acc[mt][nt][i] = 0.f;

    const uint32_t smb = smem_u32(sm);
    const int NC = CDIM / CH;   // 24

    auto issue = [&](int c) {
        const uint32_t sb = smb + (uint32_t)((c % STAGES) * SS * 4);
        const int k0 = c * CH;
#pragma unroll
        for (int j = 0; j < 4; j++) {
            cp16(sb + soff[j],                   aptr[j] + k0);
            cp16(sb + (uint32_t)T * 4 + soff[j], bptr[j] + k0);
        }
        asm volatile("cp.async.commit_group;" ::: "memory");
    };

    issue(0);
    issue(1);

    for (int c = 0; c < NC; c++) {
        asm volatile("cp.async.wait_group %0;" :: "n"(STAGES - 2));
        __syncthreads();
        if (c + STAGES - 1 < NC) issue(c + STAGES - 1);

        const uint32_t stb = smb + (uint32_t)((c % STAGES) * SS * 4);
        uint32_t aA[4], aB[2];
#pragma unroll
        for (int mt = 0; mt < 4; mt++)
            aA[mt] = stb + (uint32_t)((wm * 64 + mt * 16 + ao) * CH * 4);
#pragma unroll
        for (int ntp = 0; ntp < 2; ntp++)
            aB[ntp] = stb + (uint32_t)(T * 4 + (wn * 32 + ntp * 16 + bo) * CH * 4);

#pragma unroll
        for (int ks = 0; ks < CH / 8; ks++) {
            const uint32_t offA = (uint32_t)(((2 * ks + ak) ^ swzA) << 4);
            const uint32_t offB = (uint32_t)(((2 * ks + bk) ^ swzB) << 4);
            uint32_t af[4][4], bf[4][2];
#pragma unroll
            for (int mt = 0; mt < 4; mt++)
                LDSM4(af[mt][0], af[mt][1], af[mt][2], af[mt][3], aA[mt] + offA);
            LDSM4(bf[0][0], bf[0][1], bf[1][0], bf[1][1], aB[0] + offB);
            LDSM4(bf[2][0], bf[2][1], bf[3][0], bf[3][1], aB[1] + offB);
#pragma unroll
            for (int mt = 0; mt < 4; mt++)
#pragma unroll
                for (int nt = 0; nt < 4; nt++)
                    mma_tf32(acc[mt][nt][0], acc[mt][nt][1], acc[mt][nt][2], acc[mt][nt][3],
                             af[mt][0], af[mt][1], af[mt][2], af[mt][3],
                             bf[nt][0], bf[nt][1]);
        }
    }

    __syncthreads();   // all smem stage reads done; safe to reuse sm for vstage

    // ---- k-half epilogue (warps wn 0,1): cols 0-63 -> ksel[bh][m0+j][d]
    if (wn < 2) {
#pragma unroll
        for (int mt = 0; mt < 4; mt++) {
#pragma unroll
            for (int nt = 0; nt < 4; nt++) {
                int j0 = wm * 64 + mt * 16 + g;
                int d  = wn * 32 + nt * 8 + ct * 2;
                float2 a;
                a.x = tf32_rna(acc[mt][nt][0]); a.y = tf32_rna(acc[mt][nt][1]);
                *(float2*)(ksel + ((size_t)bh * KEEP + m0 + j0) * HD + d) = a;
                float2 c2;
                c2.x = tf32_rna(acc[mt][nt][2]); c2.y = tf32_rna(acc[mt][nt][3]);
                *(float2*)(ksel + ((size_t)bh * KEEP + m0 + j0 + 8) * HD + d) = c2;
            }
        }
    } else {
        // ---- v-half: cols 64-127 -> vstage[d][slot(j)], tf32-rounded
        float* vst = sm;   // [64][132]
#pragma unroll
        for (int mt = 0; mt < 4; mt++) {
#pragma unroll
            for (int nt = 0; nt < 4; nt++) {
                int j0 = wm * 64 + mt * 16 + g;
                int j1 = j0 + 8;
                int d  = (wn - 2) * 32 + nt * 8 + ct * 2;
                int s0 = (j0 & ~7) | ((j0 & 1) << 2) | ((j0 & 7) >> 1);
                int s1 = (j1 & ~7) | ((j1 & 1) << 2) | ((j1 & 7) >> 1);
                vst[d * 132 + s0]       = tf32_rna(acc[mt][nt][0]);
                vst[(d + 1) * 132 + s0] = tf32_rna(acc[mt][nt][1]);
                vst[d * 132 + s1]       = tf32_rna(acc[mt][nt][2]);
                vst[(d + 1) * 132 + s1] = tf32_rna(acc[mt][nt][3]);
            }
        }
    }
    __syncthreads();

    // cooperative coalesced write of Vsel^T
    for (int i = tid; i < 64 * 32; i += 256) {
        int d = i >> 5, f = (i & 31) * 4;
        float4 v;
        v.x = sm[d * 132 + f];     v.y = sm[d * 132 + f + 1];
        v.z = sm[d * 132 + f + 2]; v.w = sm[d * 132 + f + 3];
        *(float4*)(vselT + ((size_t)bh * HD + d) * KEEP + m0 + f) = v;
    }
}

// ============================================================================
// x -> (hi, lo) tf32 split
// ============================================================================
__global__ void xsplit_kernel(const float* __restrict__ x, float* __restrict__ hi,
                              float* __restrict__ lo, int n4)
{
    int i = blockIdx.x * blockDim.x + threadIdx.x;
    if (i >= n4) return;
    float4 v = ((const float4*)x)[i];
    float4 h, l;
    h.x = tf32_rna(v.x); l.x = tf32_rna(v.x - h.x);
    h.y = tf32_rna(v.y); l.y = tf32_rna(v.y - h.y);
    h.z = tf32_rna(v.z); l.z = tf32_rna(v.z - h.z);
    h.w = tf32_rna(v.w); l.w = tf32_rna(v.w - h.w);
    ((float4*)hi)[i] = h;
    ((float4*)lo)[i] = l;
}

// ============================================================================
// weight transpose + tf32 split: in[K,N] -> ohi[N,K] + olo[N,K]
// ============================================================================
__global__ void wsplit_kernel(const float* __restrict__ in, float* __restrict__ ohi,
                              float* __restrict__ olo, int K, int N)
{
    __shared__ float t[32][33];
    const int n0 = blockIdx.x * 32, k0 = blockIdx.y * 32;
    const int tx = threadIdx.x, ty = threadIdx.y;
#pragma unroll
    for (int i = 0; i < 4; i++)
        t[ty + i * 8][tx] = in[(size_t)(k0 + ty + i * 8) * N + n0 + tx];
    __syncthreads();
#pragma unroll
    for (int i = 0; i < 4; i++) {
        float v = t[tx][ty + i * 8];
        float h = tf32_rna(v);
        ohi[(size_t)(n0 + ty + i * 8) * K + k0 + tx] = h;
        olo[(size_t)(n0 + ty + i * 8) * K + k0 + tx] = tf32_rna(v - h);
    }
}

// ============================================================================
// Per-(b,h) top-KEEP: scores inline (sum_d q^2), bitonic sort (set semantics).
// ============================================================================
__global__ __launch_bounds__(1024) void topk_kernel(
    const float* __restrict__ q, int* __restrict__ keep)
{
    __shared__ unsigned long long keys[NTOK];
    const int bh = blockIdx.x, t = threadIdx.x;
    const int h = bh % NH, b = bh / NH;
    for (int i = t; i < NTOK; i += 1024) {
        const float4* qp = (const float4*)(q + (size_t)(b * NTOK + i) * CDIM + h * HD);
        float s = 0.f;
#pragma unroll
        for (int u = 0; u < 16; u++) {
            float4 v = qp[u];
            s += v.x * v.x + v.y * v.y + v.z * v.z + v.w * v.w;
        }
        keys[i] = ((unsigned long long)__float_as_uint(s) << 32) | (unsigned)(NTOK - 1 - i);
    }
    for (int k = 2; k <= NTOK; k <<= 1) {
        for (int j = k >> 1; j > 0; j >>= 1) {
            __syncthreads();
            for (int i = t; i < NTOK; i += 1024) {
                int ixj = i ^ j;
                if (ixj > i) {
                    unsigned long long a = keys[i], c = keys[ixj];
                    bool asc = ((i & k) == 0);
                    if ((a > c) == asc) { keys[i] = c; keys[ixj] = a; }
                }
            }
        }
    }
    __syncthreads();
    if (t < KEEP) {
        keep[bh * KEEP + t] = (NTOK - 1) - (int)(keys[NTOK - KEEP + t] & 0xffffffffu);
    }
}

// ============================================================================
// mma.sync attention, warp-row-split + 2-stage cp.async K/V pipeline.
// 8 warps x 16 query rows; key chunks of 64; P stays in registers and feeds
// the PV mma directly (V pre-permuted per 8-group).
// smem 96KB: Qs[128][64] (32K) | 2 stages x { K 16K + V 16K }.
// ============================================================================
__global__ __launch_bounds__(256, 2) void attn_mma(
    const float* __restrict__ q, const float* __restrict__ ksel,
    const float* __restrict__ vselT, float* __restrict__ out)
{
    extern __shared__ float sm[];
    float* Qs = sm;
    const uint32_t smb    = smem_u32(sm);
    const uint32_t stage0 = smb + 8192u * 4;

    const int tid = threadIdx.x, lane = tid & 31, wid = tid >> 5;
    const int g = lane >> 2, ct = lane & 3;
    const int bh = blockIdx.y, b = bh / NH, h = bh % NH;
    const int qbase = blockIdx.x * 128;

    const int ao = ((lane >> 3) & 1) * 8 + (lane & 7);
    const int ak = lane >> 4;
    const int bo = (lane >> 4) * 8 + (lane & 7);
    const int bk = (lane >> 3) & 1;
    const int swzq = ao & 7;
    const int swzb = bo & 7;

    {
        int j = tid & 127, half = tid >> 7;
        const float* qrow = q + (size_t)(b * NTOK + qbase + j) * CDIM + h * HD + half * 32;
        const float QSC = 0.125f * 1.44269504f;
#pragma unroll
        for (int i = 0; i < 8; i++) {
            float4 v = *(const float4*)(qrow + i * 4);
            v.x = tf32_rna(v.x * QSC); v.y = tf32_rna(v.y * QSC);
            v.z = tf32_rna(v.z * QSC); v.w = tf32_rna(v.w * QSC);
            int c = half * 32 + i * 4;
            *(float4*)&Qs[j * 64 + (c ^ ((j & 7) << 2))] = v;
        }
    }

    const float* kbase = ksel  + (size_t)bh * KEEP * HD;
    const float* vbase = vselT + (size_t)bh * HD * KEEP;

    auto issue = [&](int kc) {
        const uint32_t sb = stage0 + (uint32_t)((kc & 1) * 8192 * 4);
#pragma unroll
        for (int j = 0; j < 4; j++) {
            int gidx = tid + j * 256;
            int row = gidx >> 4, gg = gidx & 15;
            uint32_t off = (uint32_t)((row * 64 + ((gg ^ (row & 7)) << 2)) * 4);
            cp16(sb + off, kbase + (size_t)(kc * 64 + row) * HD + gg * 4);
            cp16(sb + 4096u * 4 + off, vbase + (size_t)row * KEEP + kc * 64 + gg * 4);
        }
        asm volatile("cp.async.commit_group;" ::: "memory");
    };

    const uint32_t qa_base = smb + (uint32_t)((wid * 16 + ao) * 64 * 4);

    float P[8][4];
    float O[8][4];
    float lp0 = 0.f, lp1 = 0.f;
#pragma unroll
    for (int dt = 0; dt < 8; dt++)
#pragma unroll
        for (int i = 0; i < 4; i++) O[dt][i] = 0.f;

    issue(0);

    for (int kc = 0; kc < KEEP / 64; kc++) {
        if (kc + 1 < KEEP / 64) {
            issue(kc + 1);
            asm volatile("cp.async.wait_group 1;" ::: "memory");
        } else {
            asm volatile("cp.async.wait_group 0;" ::: "memory");
        }
        __syncthreads();

        const uint32_t kst = stage0 + (uint32_t)((kc & 1) * 8192 * 4);
        const uint32_t vst = kst + 4096u * 4;

#pragma unroll
        for (int nt = 0; nt < 8; nt++)
#pragma unroll
            for (int i = 0; i < 4; i++) P[nt][i] = 0.f;

#pragma unroll
        for (int ks = 0; ks < 8; ks++) {
            const uint32_t offq = (uint32_t)(((2 * ks + ak) ^ swzq) << 4);
            const uint32_t offb = (uint32_t)(((2 * ks + bk) ^ swzb) << 4);
            uint32_t qa0, qa1, qa2, qa3;
            LDSM4(qa0, qa1, qa2, qa3, qa_base + offq);
#pragma unroll
            for (int ntp = 0; ntp < 4; ntp++) {
                uint32_t k00, k01, k10, k11;
                LDSM4(k00, k01, k10, k11, kst + (uint32_t)((ntp * 16 + bo) * 64 * 4) + offb);
                mma_tf32(P[2 * ntp][0], P[2 * ntp][1], P[2 * ntp][2], P[2 * ntp][3],
                         qa0, qa1, qa2, qa3, k00, k01);
                mma_tf32(P[2 * ntp + 1][0], P[2 * ntp + 1][1], P[2 * ntp + 1][2], P[2 * ntp + 1][3],
                         qa0, qa1, qa2, qa3, k10, k11);
            }
        }

#pragma unroll
        for (int nt = 0; nt < 8; nt++) {
            float p0 = pexp(P[nt][0]);
            float p1 = pexp(P[nt][1]);
            float p2 = pexp(P[nt][2]);
            float p3 = pexp(P[nt][3]);
            lp0 += p0 + p1;
            lp1 += p2 + p3;
            P[nt][0] = p0; P[nt][1] = p1; P[nt][2] = p2; P[nt][3] = p3;
        }

#pragma unroll
        for (int ks = 0; ks < 8; ks++) {
            const uint32_t offv = (uint32_t)(((2 * ks + bk) ^ swzb) << 4);
            uint32_t a0 = __float_as_uint(P[ks][0]);
            uint32_t a1 = __float_as_uint(P[ks][2]);
            uint32_t a2 = __float_as_uint(P[ks][1]);
            uint32_t a3 = __float_as_uint(P[ks][3]);
#pragma unroll
            for (int dtp = 0; dtp < 4; dtp++) {
                uint32_t v00, v01, v10, v11;
                LDSM4(v00, v01, v10, v11, vst + (uint32_t)((dtp * 16 + bo) * 64 * 4) + offv);
                mma_tf32(O[2 * dtp][0], O[2 * dtp][1], O[2 * dtp][2], O[2 * dtp][3],
                         a0, a1, a2, a3, v00, v01);
                mma_tf32(O[2 * dtp + 1][0], O[2 * dtp + 1][1], O[2 * dtp + 1][2], O[2 * dtp + 1][3],
                         a0, a1, a2, a3, v10, v11);
            }
        }
        __syncthreads();
    }

    lp0 += __shfl_xor_sync(0xffffffffu, lp0, 1);
    lp0 += __shfl_xor_sync(0xffffffffu, lp0, 2);
    lp1 += __shfl_xor_sync(0xffffffffu, lp1, 1);
    lp1 += __shfl_xor_sync(0xffffffffu, lp1, 2);
    const float li0 = 1.f / lp0, li1 = 1.f / lp1;

    const int row0 = qbase + wid * 16 + g;
#pragma unroll
    for (int dt = 0; dt < 8; dt++) {
        int d0 = dt * 8 + 2 * ct;
        float2 a;
        a.x = tf32_rna(O[dt][0] * li0);
        a.y = tf32_rna(O[dt][1] * li0);
        *(float2*)&out[(size_t)(b * NTOK + row0) * CDIM + h * HD + d0] = a;
        float2 c;
        c.x = tf32_rna(O[dt][2] * li1);
        c.y = tf32_rna(O[dt][3] * li1);
        *(float2*)&out[(size_t)(b * NTOK + row0 + 8) * CDIM + h * HD + d0] = c;
    }
}

// ============================================================================
// launch
// ============================================================================
extern "C" void kernel_launch(void* const* d_in, const int* in_sizes, int n_in,
                              void* d_out, int out_size)
{
    (void)in_sizes; (void)n_in; (void)out_size;
    const float* x      = (const float*)d_in[0];
    const float* w_qkv  = (const float*)d_in[1];
    const float* w_proj = (const float*)d_in[2];
    const float* b_proj = (const float*)d_in[3];
    float* out = (float*)d_out;

    float *q_p, *ks_p, *vT_p, *ao_p, *xhi_p, *xlo_p;
    float *wqh_p, *wql_p, *wph_p, *wpl_p;
    int* keep_p;
    cudaGetSymbolAddress((void**)&q_p,    g_q);
    cudaGetSymbolAddress((void**)&keep_p, g_keep);
    cudaGetSymbolAddress((void**)&ks_p,   g_ksel);
    cudaGetSymbolAddress((void**)&vT_p,   g_vselT);
    cudaGetSymbolAddress((void**)&ao_p,   g_attnout);
    cudaGetSymbolAddress((void**)&xhi_p,  g_xhi);
    cudaGetSymbolAddress((void**)&xlo_p,  g_xlo);
    cudaGetSymbolAddress((void**)&wqh_p,  g_wqT_hi);
    cudaGetSymbolAddress((void**)&wql_p,  g_wqT_lo);
    cudaGetSymbolAddress((void**)&wph_p,  g_wpT_hi);
    cudaGetSymbolAddress((void**)&wpl_p,  g_wpT_lo);

    const int smem_q    = 3 * 8192 * (int)sizeof(float);   // 98304
    const int smem_proj = 3 * 6144 * (int)sizeof(float);   // 73728
    const int smem_kvg  = 3 * 8192 * (int)sizeof(float);   // 98304
    cudaFuncSetAttribute(q_gemm,    cudaFuncAttributeMaxDynamicSharedMemorySize, smem_q);
    cudaFuncSetAttribute(proj_gemm, cudaFuncAttributeMaxDynamicSharedMemorySize, smem_proj);
    cudaFuncSetAttribute(kvg_gemm,  cudaFuncAttributeMaxDynamicSharedMemorySize, smem_kvg);
    const int attn_smem = 3 * 8192 * (int)sizeof(float);   // 98304
    cudaFuncSetAttribute(attn_mma, cudaFuncAttributeMaxDynamicSharedMemorySize, attn_smem);

    // 0) tf32 splits
    xsplit_kernel<<<(ROWS * CDIM / 4 + 255) / 256, 256>>>(x, xhi_p, xlo_p, ROWS * CDIM / 4);
    wsplit_kernel<<<dim3(C3 / 32, CDIM / 32), dim3(32, 8)>>>(w_qkv, wqh_p, wql_p, CDIM, C3);
    wsplit_kernel<<<dim3(CDIM / 32, CDIM / 32), dim3(32, 8)>>>(w_proj, wph_p, wpl_p, CDIM, CDIM);

    // 1) q = x @ w_q  (3-term tf32)
    q_gemm<<<dim3(CDIM / 128, ROWS / 128), 256, smem_q>>>(
        xhi_p, xlo_p, wqh_p, wql_p, q_p);

    // 2) top-k (scores fused)
    topk_kernel<<<NBH, 1024>>>(q_p, keep_p);

    // 3) gather-GEMM: Ksel / Vsel^T for selected tokens only (half the kv work)
    kvg_gemm<<<dim3(KEEP / 128, NBH), 256, smem_kvg>>>(
        xhi_p, wqh_p, keep_p, ks_p, vT_p);

    // 4) attention on tensor cores
    attn_mma<<<dim3(NTOK / 128, NBH), 256, attn_smem>>>(q_p, ks_p, vT_p, ao_p);

    // 5) out = clip(attnout @ w_proj + b_proj, -10, 10)
    proj_gemm<<<dim3(CDIM / 128, ROWS / 128), 256, smem_proj>>>(
        ao_p, wph_p, wpl_p, b_proj, out);
}